// round 12
// baseline (speedup 1.0000x reference)
#include <cuda_runtime.h>
#include <cuda_bf16.h>
#include <cuda_fp16.h>
#include <math.h>
#include <stdint.h>

// Problem dims
#define BB   2
#define SSQ  2048
#define DD   1024
#define HHD  16
#define DKK  64
#define MTOT (BB * SSQ)   // 4096

typedef __nv_bfloat16 bf16;
typedef __nv_bfloat162 bf162;

#define LOG2E 1.44269504f

// ---------------------------------------------------------------------------
// Scratch (__device__ globals; no allocation allowed)
// ---------------------------------------------------------------------------
__device__ bf16 g_qAh[MTOT * DD], g_qAl[MTOT * DD];
__device__ bf16 g_kAh[MTOT * DD], g_kAl[MTOT * DD];   // compacted k input
__device__ bf16 g_vAh[MTOT * DD], g_vAl[MTOT * DD];   // compacted v input
__device__ bf16 g_WqH[DD * DD], g_WqL[DD * DD];
__device__ bf16 g_WkH[DD * DD], g_WkL[DD * DD];
__device__ bf16 g_WvH[DD * DD], g_WvL[DD * DD];
__device__ bf16 g_WoH[DD * DD], g_WoL[DD * DD];
__device__ bf16 g_Qh[MTOT * DD], g_Ql[MTOT * DD];
__device__ bf16 g_Kh[MTOT * DD], g_Kl[MTOT * DD];     // compacted projected K
__device__ __half g_Vf[MTOT * DD];                    // compacted projected V (fp16)
__device__ bf16 g_Oh[MTOT * DD], g_Ol[MTOT * DD];
__device__ float g_cbias[MTOT];                       // compacted bias
__device__ int   g_idx[MTOT];                         // compaction permutation
__device__ int   g_nv[BB];                            // valid keys per batch

// ---------------------------------------------------------------------------
// PTX helpers
// ---------------------------------------------------------------------------
__device__ __forceinline__ uint32_t smem_u32(const void* p) {
    uint32_t a;
    asm("{ .reg .u64 t; cvta.to.shared.u64 t, %1; cvt.u32.u64 %0, t; }"
        : "=r"(a) : "l"(p));
    return a;
}
__device__ __forceinline__ void ldsm4(uint32_t r[4], uint32_t a) {
    asm volatile("ldmatrix.sync.aligned.m8n8.x4.shared.b16 {%0,%1,%2,%3}, [%4];"
                 : "=r"(r[0]), "=r"(r[1]), "=r"(r[2]), "=r"(r[3]) : "r"(a));
}
__device__ __forceinline__ void ldsm4t(uint32_t r[4], uint32_t a) {
    asm volatile("ldmatrix.sync.aligned.m8n8.x4.trans.shared.b16 {%0,%1,%2,%3}, [%4];"
                 : "=r"(r[0]), "=r"(r[1]), "=r"(r[2]), "=r"(r[3]) : "r"(a));
}
__device__ __forceinline__ void mma16816(float* c, const uint32_t* a,
                                         uint32_t b0, uint32_t b1) {
    asm("mma.sync.aligned.m16n8k16.row.col.f32.bf16.bf16.f32 "
        "{%0,%1,%2,%3}, {%4,%5,%6,%7}, {%8,%9}, {%0,%1,%2,%3};"
        : "+f"(c[0]), "+f"(c[1]), "+f"(c[2]), "+f"(c[3])
        : "r"(a[0]), "r"(a[1]), "r"(a[2]), "r"(a[3]), "r"(b0), "r"(b1));
}
// fp16 variant (f32 accumulate)
__device__ __forceinline__ void mma16816h(float* c, const uint32_t* a,
                                          uint32_t b0, uint32_t b1) {
    asm("mma.sync.aligned.m16n8k16.row.col.f32.f16.f16.f32 "
        "{%0,%1,%2,%3}, {%4,%5,%6,%7}, {%8,%9}, {%0,%1,%2,%3};"
        : "+f"(c[0]), "+f"(c[1]), "+f"(c[2]), "+f"(c[3])
        : "r"(a[0]), "r"(a[1]), "r"(a[2]), "r"(a[3]), "r"(b0), "r"(b1));
}
__device__ __forceinline__ uint32_t bits(bf162 h) {
    return *reinterpret_cast<uint32_t*>(&h);
}
__device__ __forceinline__ uint32_t bitsh(__half2 h) {
    return *reinterpret_cast<uint32_t*>(&h);
}
__device__ __forceinline__ float ex2f(float x) {
    float y;
    asm("ex2.approx.ftz.f32 %0, %1;" : "=f"(y) : "f"(x));
    return y;
}
#define CP16(dst, src) \
    asm volatile("cp.async.cg.shared.global [%0], [%1], 16;" \
                 :: "r"(dst), "l"(src) : "memory")
#define CPCOMMIT() asm volatile("cp.async.commit_group;" ::: "memory")
#define CPWAIT1()  asm volatile("cp.async.wait_group 1;" ::: "memory")
#define CPWAIT0()  asm volatile("cp.async.wait_group 0;" ::: "memory")

// defensive clamp for scratch-derived control values
__device__ __forceinline__ int clamp_nv(int x) {
    return x < 0 ? 0 : (x > SSQ ? SSQ : x);
}

// ---------------------------------------------------------------------------
// Mask compaction: deterministic (stable) prefix scan, one block per batch.
// ---------------------------------------------------------------------------
__global__ void scan_mask_k(const int* __restrict__ mask, int* __restrict__ idx,
                            int* __restrict__ nv, float* __restrict__ cbias)
{
    __shared__ int warp_sums[16];
    __shared__ int s_nv;
    const int b = blockIdx.x;
    const int tid = threadIdx.x;          // 512 threads, 4 keys each
    const int lane = tid & 31, wrp = tid >> 5;
    const int base = tid * 4;

    int m[4];
#pragma unroll
    for (int u = 0; u < 4; u++) m[u] = mask[b * SSQ + base + u] != 0;
    int local = m[0] + m[1] + m[2] + m[3];

    int pre = local;   // inclusive warp scan
#pragma unroll
    for (int d = 1; d < 32; d <<= 1) {
        int y = __shfl_up_sync(0xffffffffu, pre, d);
        if (lane >= d) pre += y;
    }
    if (lane == 31) warp_sums[wrp] = pre;
    __syncthreads();
    if (wrp == 0) {
        int ws = (lane < 16) ? warp_sums[lane] : 0;
#pragma unroll
        for (int d = 1; d < 16; d <<= 1) {
            int y = __shfl_up_sync(0xffffffffu, ws, d);
            if (lane >= d) ws += y;
        }
        if (lane < 16) warp_sums[lane] = ws;
        if (lane == 15) s_nv = ws;
    }
    __syncthreads();

    int offset = (pre - local) + (wrp > 0 ? warp_sums[wrp - 1] : 0);
#pragma unroll
    for (int u = 0; u < 4; u++) {
        if (m[u] && offset < SSQ) { idx[b * SSQ + offset] = base + u; offset++; }
    }
    const int total = s_nv;
    if (tid == 0) nv[b] = total;
#pragma unroll
    for (int u = 0; u < 4; u++) {
        int j = base + u;
        cbias[b * SSQ + j] = (j < total) ? 0.0f : -1e9f * LOG2E;
    }
}

// ---------------------------------------------------------------------------
// split helpers
// ---------------------------------------------------------------------------
__device__ __forceinline__ void split_store(float4 v, bf16* __restrict__ hi,
                                            bf16* __restrict__ lo, int i)
{
    bf16 h0 = __float2bfloat16_rn(v.x), h1 = __float2bfloat16_rn(v.y);
    bf16 h2 = __float2bfloat16_rn(v.z), h3 = __float2bfloat16_rn(v.w);
    bf16 l0 = __float2bfloat16_rn(v.x - __bfloat162float(h0));
    bf16 l1 = __float2bfloat16_rn(v.y - __bfloat162float(h1));
    bf16 l2 = __float2bfloat16_rn(v.z - __bfloat162float(h2));
    bf16 l3 = __float2bfloat16_rn(v.w - __bfloat162float(h3));
    ((bf162*)hi)[2 * i + 0] = bf162(h0, h1);
    ((bf162*)hi)[2 * i + 1] = bf162(h2, h3);
    ((bf162*)lo)[2 * i + 0] = bf162(l0, l1);
    ((bf162*)lo)[2 * i + 1] = bf162(l2, l3);
}

// All splits in one kernel:
//   [0, 1M)   : q full split
//   [1M, 3M)  : k,v gathered-compacted split (+ zero pad to rnd128)
//   [3M, 4M)  : 4 weight matrices (256K float4 each)
struct SplitArgs {
    const float *q, *k, *v;
    const float *wq, *wk, *wv, *wo;
    bf16 *qh, *ql, *kch, *kcl, *vch, *vcl;
    bf16 *wqh, *wql, *wkh, *wkl, *wvh, *wvl, *woh, *wol;
    const int *idx, *nv;
};

__global__ void split_all_k(SplitArgs a)
{
    const int n4q = MTOT * DD / 4;          // 1M
    const int n4kv = 2 * MTOT * DD / 4;     // 2M
    const int n4w = DD * DD / 4;            // 256K
    const int total = n4q + n4kv + 4 * n4w; // 4M
    int i = blockIdx.x * blockDim.x + threadIdx.x;
    int stride = gridDim.x * blockDim.x;
    for (; i < total; i += stride) {
        if (i < n4q) {
            split_store(((const float4*)a.q)[i], a.qh, a.ql, i);
            continue;
        }
        if (i < n4q + n4kv) {
            int r = i - n4q;                // [0, 2M)
            int tsel = r >> 20;             // 0=k, 1=v
            int rem = r & ((1 << 20) - 1);
            int b = rem >> 19;
            int loc = rem & ((1 << 19) - 1);
            int row = loc >> 8;             // 0..2047
            int c4 = loc & 255;
            int nvb = clamp_nv(a.nv[b]);
            int rnd = (nvb + 127) & ~127;
            if (row >= rnd) continue;
            bf16* hi = tsel ? a.vch : a.kch;
            bf16* lo = tsel ? a.vcl : a.kcl;
            int dsti = (b * SSQ + row) * 256 + c4;
            if (row < nvb) {
                const float* src = tsel ? a.v : a.k;
                int srow = a.idx[b * SSQ + row] & (SSQ - 1);
                split_store(((const float4*)src)[(b * SSQ + srow) * 256 + c4],
                            hi, lo, dsti);
            } else {
                split_store(make_float4(0.f, 0.f, 0.f, 0.f), hi, lo, dsti);
            }
            continue;
        }
        int r = i - n4q - n4kv;             // [0, 1M)
        int wsel = r / n4w;
        int wi = r - wsel * n4w;
        if (wsel == 0)      split_store(((const float4*)a.wq)[wi], a.wqh, a.wql, wi);
        else if (wsel == 1) split_store(((const float4*)a.wk)[wi], a.wkh, a.wkl, wi);
        else if (wsel == 2) split_store(((const float4*)a.wv)[wi], a.wvh, a.wvl, wi);
        else                split_store(((const float4*)a.wo)[wi], a.woh, a.wol, wi);
    }
}

// ---------------------------------------------------------------------------
// GEMM tiles: 128x128, BK=32, 8 warps (4m x 2n), warp 32x64, cp.async 2-stage
// ---------------------------------------------------------------------------
#define GS 40
#define GT_TILEB  (128 * GS * 2)
#define GT_STAGEB (4 * GT_TILEB)
#define GT_SMEM   (2 * GT_STAGEB)

__device__ __forceinline__ void gemm_stage_load(
    uint32_t sbase, const bf16* __restrict__ gAh, const bf16* __restrict__ gAl,
    const bf16* __restrict__ gBh, const bf16* __restrict__ gBl,
    int k0, int tid)
{
#pragma unroll
    for (int i = tid; i < 512; i += 256) {
        int r = i >> 2, c4 = i & 3;
        size_t go = (size_t)r * DD + k0 + c4 * 8;
        uint32_t so = (uint32_t)(r * GS + c4 * 8) * 2;
        CP16(sbase + so,                gAh + go);
        CP16(sbase + GT_TILEB + so,     gAl + go);
        CP16(sbase + 2 * GT_TILEB + so, gBh + go);
        CP16(sbase + 3 * GT_TILEB + so, gBl + go);
    }
}

__device__ __forceinline__ void gemm_mainloop(
    uint32_t sb, const bf16* gAh, const bf16* gAl,
    const bf16* gBh, const bf16* gBl,
    int tid, int lane, int wm, int wn, float acc[2][8][4])
{
    const int lrA = wm * 32 + (lane & 15);
    const int lcA = (lane >> 4) * 8;
    const int lrB = wn * 64 + ((lane >> 4) & 1) * 8 + (lane & 7);
    const int lcB = ((lane >> 3) & 1) * 8;

    gemm_stage_load(sb, gAh, gAl, gBh, gBl, 0, tid);
    CPCOMMIT();

    for (int t = 0; t < 32; ++t) {
        const int st = t & 1;
        if (t < 31) {
            gemm_stage_load(sb + (st ^ 1) * GT_STAGEB, gAh, gAl, gBh, gBl,
                            (t + 1) * 32, tid);
            CPCOMMIT();
            CPWAIT1();
        } else {
            CPWAIT0();
        }
        __syncthreads();

        const uint32_t bAh = sb + st * GT_STAGEB;
        const uint32_t bAl = bAh + GT_TILEB;
        const uint32_t bBh = bAh + 2 * GT_TILEB;
        const uint32_t bBl = bAh + 3 * GT_TILEB;

#pragma unroll
        for (int kb = 0; kb < 2; kb++) {
            uint32_t ah[2][4], al[2][4];
#pragma unroll
            for (int mi = 0; mi < 2; mi++) {
                uint32_t off = ((lrA + mi * 16) * GS + kb * 16 + lcA) * 2;
                ldsm4(ah[mi], bAh + off);
                ldsm4(al[mi], bAl + off);
            }
#pragma unroll
            for (int njp = 0; njp < 4; njp++) {
                uint32_t off = ((lrB + njp * 16) * GS + kb * 16 + lcB) * 2;
                uint32_t bh[4], bl[4];
                ldsm4(bh, bBh + off);
                ldsm4(bl, bBl + off);
                float* c00 = acc[0][njp * 2];
                float* c01 = acc[0][njp * 2 + 1];
                float* c10 = acc[1][njp * 2];
                float* c11 = acc[1][njp * 2 + 1];
                mma16816(c00, ah[0], bh[0], bh[1]);
                mma16816(c10, ah[1], bh[0], bh[1]);
                mma16816(c01, ah[0], bh[2], bh[3]);
                mma16816(c11, ah[1], bh[2], bh[3]);
                mma16816(c00, ah[0], bl[0], bl[1]);
                mma16816(c10, ah[1], bl[0], bl[1]);
                mma16816(c01, ah[0], bl[2], bl[3]);
                mma16816(c11, ah[1], bl[2], bl[3]);
                mma16816(c00, al[0], bh[0], bh[1]);
                mma16816(c10, al[1], bh[0], bh[1]);
                mma16816(c01, al[0], bh[2], bh[3]);
                mma16816(c11, al[1], bh[2], bh[3]);
            }
        }
        __syncthreads();
    }
}

// Fused QKV projections; K/V (z>0) skip CTAs above the valid compacted rows.
// z==2 (V) writes SINGLE fp16 output; z<2 write bf16 hi/lo.
struct G3Args {
    const bf16 *Ah[3], *Al[3], *Bh[3], *Bl[3];
    const float* bias[3];
    bf16 *Ch[3], *Cl[3];
    __half* Vf;
    const int* nv;
};

__global__ __launch_bounds__(256, 2) void gemm3_mma(G3Args p)
{
    extern __shared__ __align__(16) char dyn[];
    const uint32_t sb = smem_u32(dyn);
    const int z = blockIdx.z;
    const int bm = blockIdx.y * 128;
    const int bn = blockIdx.x * 128;

    if (z > 0) {   // K or V projection: skip masked-out row tiles
        int batch = bm >> 11;
        int local = bm & 2047;
        int rnd = (clamp_nv(p.nv[batch]) + 127) & ~127;
        if (local >= rnd) return;
    }

    const int tid  = threadIdx.x;
    const int lane = tid & 31;
    const int warp = tid >> 5;
    const int wm = warp & 3, wn = warp >> 2;

    float acc[2][8][4];
#pragma unroll
    for (int mi = 0; mi < 2; mi++)
#pragma unroll
        for (int nj = 0; nj < 8; nj++)
#pragma unroll
            for (int e = 0; e < 4; e++) acc[mi][nj][e] = 0.0f;

    gemm_mainloop(sb,
                  p.Ah[z] + (size_t)bm * DD, p.Al[z] + (size_t)bm * DD,
                  p.Bh[z] + (size_t)bn * DD, p.Bl[z] + (size_t)bn * DD,
                  tid, lane, wm, wn, acc);

    const float* bias = p.bias[z];
    const int g = lane >> 2, c = lane & 3;
    if (z == 2) {
        __half* Vf = p.Vf;
#pragma unroll
        for (int mi = 0; mi < 2; mi++) {
#pragma unroll
            for (int nj = 0; nj < 8; nj++) {
                int row = bm + wm * 32 + mi * 16 + g;
                int col = bn + wn * 64 + nj * 8 + c * 2;
                float b0 = bias[col], b1 = bias[col + 1];
                __half2 v01 = __float22half2_rn(
                    make_float2(acc[mi][nj][0] + b0, acc[mi][nj][1] + b1));
                __half2 v23 = __float22half2_rn(
                    make_float2(acc[mi][nj][2] + b0, acc[mi][nj][3] + b1));
                *(__half2*)&Vf[(size_t)row * DD + col] = v01;
                *(__half2*)&Vf[(size_t)(row + 8) * DD + col] = v23;
            }
        }
    } else {
        bf16* Chi = p.Ch[z];
        bf16* Clo = p.Cl[z];
#pragma unroll
        for (int mi = 0; mi < 2; mi++) {
#pragma unroll
            for (int nj = 0; nj < 8; nj++) {
                int row = bm + wm * 32 + mi * 16 + g;
                int col = bn + wn * 64 + nj * 8 + c * 2;
                float b0 = bias[col], b1 = bias[col + 1];
                float x0 = acc[mi][nj][0] + b0, x1 = acc[mi][nj][1] + b1;
                float x2 = acc[mi][nj][2] + b0, x3 = acc[mi][nj][3] + b1;
                bf162 h01 = __float22bfloat162_rn(make_float2(x0, x1));
                bf162 h23 = __float22bfloat162_rn(make_float2(x2, x3));
                bf162 l01 = __float22bfloat162_rn(make_float2(
                    x0 - __low2float(h01), x1 - __high2float(h01)));
                bf162 l23 = __float22bfloat162_rn(make_float2(
                    x2 - __low2float(h23), x3 - __high2float(h23)));
                *(bf162*)&Chi[(size_t)row * DD + col] = h01;
                *(bf162*)&Clo[(size_t)row * DD + col] = l01;
                *(bf162*)&Chi[(size_t)(row + 8) * DD + col] = h23;
                *(bf162*)&Clo[(size_t)(row + 8) * DD + col] = l23;
            }
        }
    }
}

// Output projection (fp32 result)
__global__ __launch_bounds__(256, 2) void gemm_out_mma(
    const bf16* __restrict__ Ah, const bf16* __restrict__ Al,
    const bf16* __restrict__ Wh, const bf16* __restrict__ Wl,
    const float* __restrict__ bias, float* __restrict__ Cf)
{
    extern __shared__ __align__(16) char dyn[];
    const uint32_t sb = smem_u32(dyn);
    const int tid  = threadIdx.x;
    const int lane = tid & 31;
    const int warp = tid >> 5;
    const int wm = warp & 3, wn = warp >> 2;
    const int bm = blockIdx.y * 128;
    const int bn = blockIdx.x * 128;

    float acc[2][8][4];
#pragma unroll
    for (int mi = 0; mi < 2; mi++)
#pragma unroll
        for (int nj = 0; nj < 8; nj++)
#pragma unroll
            for (int e = 0; e < 4; e++) acc[mi][nj][e] = 0.0f;

    gemm_mainloop(sb,
                  Ah + (size_t)bm * DD, Al + (size_t)bm * DD,
                  Wh + (size_t)bn * DD, Wl + (size_t)bn * DD,
                  tid, lane, wm, wn, acc);

    const int g = lane >> 2, c = lane & 3;
#pragma unroll
    for (int mi = 0; mi < 2; mi++) {
#pragma unroll
        for (int nj = 0; nj < 8; nj++) {
            int row = bm + wm * 32 + mi * 16 + g;
            int col = bn + wn * 64 + nj * 8 + c * 2;
            float b0 = bias[col], b1 = bias[col + 1];
            *(float2*)&Cf[(size_t)row * DD + col] =
                make_float2(acc[mi][nj][0] + b0, acc[mi][nj][1] + b1);
            *(float2*)&Cf[(size_t)(row + 8) * DD + col] =
                make_float2(acc[mi][nj][2] + b0, acc[mi][nj][3] + b1);
        }
    }
}

// ---------------------------------------------------------------------------
// Flash attention over COMPACTED keys.
// 128 threads / 4 warps / 64 q-rows per CTA (-> 2 CTAs per SM).
// 3-stage cp.async KV pipeline, ONE __syncthreads per KV tile.
// QK: bf16 x3 terms.  PV: single fp16 MMA.
// ---------------------------------------------------------------------------
#define AS 72
#define AT_TILEB  (64 * AS * 2)        // 9216 B per operand tile
#define AT_STAGEB (3 * AT_TILEB)       // 27648 B per stage (Kh | Kl | Vf)
#define AT_SMEM   (3 * AT_STAGEB)      // 82944 B (3 stages)

__device__ __forceinline__ void att_stage_load(
    uint32_t sbase, const bf16* __restrict__ Kh, const bf16* __restrict__ Kl,
    const __half* __restrict__ Vf, size_t gbase, int tid)
{
#pragma unroll
    for (int i = tid; i < 512; i += 128) {
        int r = i >> 3, c8 = i & 7;
        size_t go = gbase + (size_t)r * DD + c8 * 8;
        uint32_t so = (uint32_t)(r * AS + c8 * 8) * 2;
        CP16(sbase + so,                Kh + go);
        CP16(sbase + AT_TILEB + so,     Kl + go);
        CP16(sbase + 2 * AT_TILEB + so, Vf + go);
    }
}

__global__ __launch_bounds__(128) void flash_mma_k(
    const bf16* __restrict__ Qh, const bf16* __restrict__ Ql,
    const bf16* __restrict__ Kh, const bf16* __restrict__ Kl,
    const __half* __restrict__ Vf,
    const float* __restrict__ cb, const int* __restrict__ nvp,
    bf16* __restrict__ Oh, bf16* __restrict__ Ol)
{
    extern __shared__ __align__(16) char dyn[];
    __shared__ __align__(16) float sBias[3][64];
    const uint32_t sb = smem_u32(dyn);
    const uint32_t sbias_u32 = smem_u32(&sBias[0][0]);

    const int tid  = threadIdx.x;
    const int lane = tid & 31;
    const int w    = tid >> 5;             // 0..3
    const int b  = blockIdx.y >> 4;
    const int h  = blockIdx.y & 15;
    const int q0 = blockIdx.x * 64;
    const int g = lane >> 2, c = lane & 3;
    const int nt = (clamp_nv(nvp[b]) + 63) >> 6;

    // ---- Phase 1: Q tile (64 rows) -> fragments ----
    {
        bf16* sQh = (bf16*)dyn;
        bf16* sQl = (bf16*)(dyn + 64 * AS * 2);
        const bf16* gQh = Qh + (size_t)(b * SSQ + q0) * DD + h * DKK;
        const bf16* gQl = Ql + (size_t)(b * SSQ + q0) * DD + h * DKK;
#pragma unroll
        for (int i = tid; i < 512; i += 128) {
            int r = i >> 3, c8 = i & 7;
            size_t go = (size_t)r * DD + c8 * 8;
            int so = r * AS + c8 * 8;
            *(uint4*)&sQh[so] = *(const uint4*)&gQh[go];
            *(uint4*)&sQl[so] = *(const uint4*)&gQl[go];
        }
    }
    __syncthreads();

    uint32_t qh[4][4], ql[4][4];
    {
        const int lrQ = w * 16 + (lane & 15);
        const int lcQ = (lane >> 4) * 8;
        const uint32_t bQh = sb;
        const uint32_t bQl = sb + 64 * AS * 2;
#pragma unroll
        for (int kb = 0; kb < 4; kb++) {
            uint32_t off = (lrQ * AS + kb * 16 + lcQ) * 2;
            ldsm4(qh[kb], bQh + off);
            ldsm4(ql[kb], bQl + off);
        }
    }
    __syncthreads();   // Q smem (stage-0 region) free for KV stages

    float m0 = -INFINITY, m1 = -INFINITY, l0 = 0.0f, l1 = 0.0f;
    float acc[8][4];
#pragma unroll
    for (int on = 0; on < 8; on++)
#pragma unroll
        for (int e = 0; e < 4; e++) acc[on][e] = 0.0f;

    const int lrK = ((lane >> 4) & 1) * 8 + (lane & 7);
    const int lcK = ((lane >> 3) & 1) * 8;
    const int lrV = ((lane >> 3) & 1) * 8 + (lane & 7);
    const int lcV = (lane >> 4) * 8;
    const float scale2 = 0.125f * LOG2E;
    const size_t gKV0 = (size_t)(b * SSQ) * DD + h * DKK;

    // prologue: stages 0 and 1
    if (nt > 0) {
        att_stage_load(sb, Kh, Kl, Vf, gKV0, tid);
        if (tid < 16) CP16(sbias_u32 + tid * 16, &cb[b * SSQ + tid * 4]);
        CPCOMMIT();
    }
    if (nt > 1) {
        att_stage_load(sb + AT_STAGEB, Kh, Kl, Vf, gKV0 + (size_t)64 * DD, tid);
        if (tid < 16) CP16(sbias_u32 + 256 + tid * 16, &cb[b * SSQ + 64 + tid * 4]);
        CPCOMMIT();
    }

    for (int t = 0; t < nt; ++t) {
        const int s3 = t % 3;
        if (t + 1 < nt) { CPWAIT1(); } else { CPWAIT0(); }
        __syncthreads();   // all warps done with stage (t-1)%3 == (t+2)%3

        if (t + 2 < nt) {
            int sp = (t + 2) % 3;
            att_stage_load(sb + sp * AT_STAGEB, Kh, Kl, Vf,
                           gKV0 + (size_t)(t + 2) * 64 * DD, tid);
            if (tid < 16)
                CP16(sbias_u32 + sp * 256 + tid * 16,
                     &cb[b * SSQ + (t + 2) * 64 + tid * 4]);
            CPCOMMIT();
        }

        const uint32_t bKh = sb + s3 * AT_STAGEB;
        const uint32_t bKl = bKh + AT_TILEB;
        const uint32_t bVf = bKh + 2 * AT_TILEB;

        // ---- S = Q K^T (bf16 x3) ----
        float s[8][4];
#pragma unroll
        for (int nj = 0; nj < 8; nj++)
#pragma unroll
            for (int e = 0; e < 4; e++) s[nj][e] = 0.0f;

#pragma unroll
        for (int kb = 0; kb < 4; kb++) {
#pragma unroll
            for (int np = 0; np < 2; np++) {
                uint32_t kh0[4], kl0[4], kh1[4], kl1[4];
                uint32_t off0 = (((np * 2 + 0) * 16 + lrK) * AS + kb * 16 + lcK) * 2;
                uint32_t off1 = (((np * 2 + 1) * 16 + lrK) * AS + kb * 16 + lcK) * 2;
                ldsm4(kh0, bKh + off0);
                ldsm4(kl0, bKl + off0);
                ldsm4(kh1, bKh + off1);
                ldsm4(kl1, bKl + off1);
                float* c0 = s[np * 4 + 0];
                float* c1 = s[np * 4 + 1];
                float* c2 = s[np * 4 + 2];
                float* c3 = s[np * 4 + 3];
                mma16816(c0, qh[kb], kh0[0], kh0[1]);
                mma16816(c1, qh[kb], kh0[2], kh0[3]);
                mma16816(c2, qh[kb], kh1[0], kh1[1]);
                mma16816(c3, qh[kb], kh1[2], kh1[3]);
                mma16816(c0, qh[kb], kl0[0], kl0[1]);
                mma16816(c1, qh[kb], kl0[2], kl0[3]);
                mma16816(c2, qh[kb], kl1[0], kl1[1]);
                mma16816(c3, qh[kb], kl1[2], kl1[3]);
                mma16816(c0, ql[kb], kh0[0], kh0[1]);
                mma16816(c1, ql[kb], kh0[2], kh0[3]);
                mma16816(c2, ql[kb], kh1[0], kh1[1]);
                mma16816(c3, ql[kb], kh1[2], kh1[3]);
            }
        }

        // ---- scale + bias (exp2 domain; pad slots get -BIG) ----
#pragma unroll
        for (int nj = 0; nj < 8; nj++) {
            float b0 = sBias[s3][nj * 8 + c * 2];
            float b1 = sBias[s3][nj * 8 + c * 2 + 1];
            s[nj][0] = fmaf(s[nj][0], scale2, b0);
            s[nj][1] = fmaf(s[nj][1], scale2, b1);
            s[nj][2] = fmaf(s[nj][2], scale2, b0);
            s[nj][3] = fmaf(s[nj][3], scale2, b1);
        }

        // ---- online softmax ----
        float mx0 = -INFINITY, mx1 = -INFINITY;
#pragma unroll
        for (int nj = 0; nj < 8; nj++) {
            mx0 = fmaxf(mx0, fmaxf(s[nj][0], s[nj][1]));
            mx1 = fmaxf(mx1, fmaxf(s[nj][2], s[nj][3]));
        }
        mx0 = fmaxf(mx0, __shfl_xor_sync(0xffffffffu, mx0, 1));
        mx0 = fmaxf(mx0, __shfl_xor_sync(0xffffffffu, mx0, 2));
        mx1 = fmaxf(mx1, __shfl_xor_sync(0xffffffffu, mx1, 1));
        mx1 = fmaxf(mx1, __shfl_xor_sync(0xffffffffu, mx1, 2));
        float mn0 = fmaxf(m0, mx0), mn1 = fmaxf(m1, mx1);
        float f0 = ex2f(m0 - mn0), f1 = ex2f(m1 - mn1);
        m0 = mn0; m1 = mn1;

        float sum0 = 0.0f, sum1 = 0.0f;
#pragma unroll
        for (int nj = 0; nj < 8; nj++) {
            s[nj][0] = ex2f(s[nj][0] - m0);
            s[nj][1] = ex2f(s[nj][1] - m0);
            s[nj][2] = ex2f(s[nj][2] - m1);
            s[nj][3] = ex2f(s[nj][3] - m1);
            sum0 += s[nj][0] + s[nj][1];
            sum1 += s[nj][2] + s[nj][3];
        }
        sum0 += __shfl_xor_sync(0xffffffffu, sum0, 1);
        sum0 += __shfl_xor_sync(0xffffffffu, sum0, 2);
        sum1 += __shfl_xor_sync(0xffffffffu, sum1, 1);
        sum1 += __shfl_xor_sync(0xffffffffu, sum1, 2);
        l0 = l0 * f0 + sum0;
        l1 = l1 * f1 + sum1;
#pragma unroll
        for (int on = 0; on < 8; on++) {
            acc[on][0] *= f0; acc[on][1] *= f0;
            acc[on][2] *= f1; acc[on][3] *= f1;
        }

        // ---- O += P V : single fp16 MMA ----
#pragma unroll
        for (int kb2 = 0; kb2 < 4; kb2++) {
            uint32_t pa[4];
#pragma unroll
            for (int q2 = 0; q2 < 2; q2++) {
                float* sp = s[2 * kb2 + q2];
                pa[q2 * 2]     = bitsh(__float22half2_rn(make_float2(sp[0], sp[1])));
                pa[q2 * 2 + 1] = bitsh(__float22half2_rn(make_float2(sp[2], sp[3])));
            }
#pragma unroll
            for (int op = 0; op < 2; op++) {
                uint32_t vh0[4], vh1[4];
                uint32_t off0 = ((kb2 * 16 + lrV) * AS + (op * 2 + 0) * 16 + lcV) * 2;
                uint32_t off1 = ((kb2 * 16 + lrV) * AS + (op * 2 + 1) * 16 + lcV) * 2;
                ldsm4t(vh0, bVf + off0);
                ldsm4t(vh1, bVf + off1);
                mma16816h(acc[op * 4 + 0], pa, vh0[0], vh0[1]);
                mma16816h(acc[op * 4 + 1], pa, vh0[2], vh0[3]);
                mma16816h(acc[op * 4 + 2], pa, vh1[0], vh1[1]);
                mma16816h(acc[op * 4 + 3], pa, vh1[2], vh1[3]);
            }
        }
        // no trailing sync: next iteration's top sync covers the stage reuse
    }

    // ---- epilogue ----
    float inv0 = l0 > 0.f ? 1.0f / l0 : 0.f;
    float inv1 = l1 > 0.f ? 1.0f / l1 : 0.f;
    int rowg = b * SSQ + q0 + w * 16 + g;
#pragma unroll
    for (int on = 0; on < 8; on++) {
        int col = h * DKK + on * 8 + c * 2;
        float x0 = acc[on][0] * inv0, x1 = acc[on][1] * inv0;
        float x2 = acc[on][2] * inv1, x3 = acc[on][3] * inv1;
        bf162 h01 = __float22bfloat162_rn(make_float2(x0, x1));
        bf162 h23 = __float22bfloat162_rn(make_float2(x2, x3));
        bf162 l01 = __float22bfloat162_rn(make_float2(
            x0 - __low2float(h01), x1 - __high2float(h01)));
        bf162 l23 = __float22bfloat162_rn(make_float2(
            x2 - __low2float(h23), x3 - __high2float(h23)));
        *(bf162*)&Oh[(size_t)rowg * DD + col] = h01;
        *(bf162*)&Ol[(size_t)rowg * DD + col] = l01;
        *(bf162*)&Oh[(size_t)(rowg + 8) * DD + col] = h23;
        *(bf162*)&Ol[(size_t)(rowg + 8) * DD + col] = l23;
    }
}

// ---------------------------------------------------------------------------
// Launch. Index 3 (profiled) = flash_mma_k this round.
// ---------------------------------------------------------------------------
extern "C" void kernel_launch(void* const* d_in, const int* in_sizes, int n_in,
                              void* d_out, int out_size)
{
    const float* q    = (const float*)d_in[0];
    const float* k    = (const float*)d_in[1];
    const float* v    = (const float*)d_in[2];
    const int*   mask = (const int*)  d_in[3];
    const float* Wq   = (const float*)d_in[4];
    const float* bq   = (const float*)d_in[5];
    const float* Wk   = (const float*)d_in[6];
    const float* bk   = (const float*)d_in[7];
    const float* Wv   = (const float*)d_in[8];
    const float* bv   = (const float*)d_in[9];
    const float* Wo   = (const float*)d_in[10];
    const float* bo   = (const float*)d_in[11];
    float* out = (float*)d_out;

    bf16 *qAh, *qAl, *kAh, *kAl, *vAh, *vAl;
    bf16 *WqH, *WqL, *WkH, *WkL, *WvH, *WvL, *WoH, *WoL;
    bf16 *Qh, *Ql, *Kh, *Kl, *Oh, *Ol;
    __half* Vf;
    float *cb; int *idx, *nv;
    cudaGetSymbolAddress((void**)&qAh, g_qAh); cudaGetSymbolAddress((void**)&qAl, g_qAl);
    cudaGetSymbolAddress((void**)&kAh, g_kAh); cudaGetSymbolAddress((void**)&kAl, g_kAl);
    cudaGetSymbolAddress((void**)&vAh, g_vAh); cudaGetSymbolAddress((void**)&vAl, g_vAl);
    cudaGetSymbolAddress((void**)&WqH, g_WqH); cudaGetSymbolAddress((void**)&WqL, g_WqL);
    cudaGetSymbolAddress((void**)&WkH, g_WkH); cudaGetSymbolAddress((void**)&WkL, g_WkL);
    cudaGetSymbolAddress((void**)&WvH, g_WvH); cudaGetSymbolAddress((void**)&WvL, g_WvL);
    cudaGetSymbolAddress((void**)&WoH, g_WoH); cudaGetSymbolAddress((void**)&WoL, g_WoL);
    cudaGetSymbolAddress((void**)&Qh, g_Qh);   cudaGetSymbolAddress((void**)&Ql, g_Ql);
    cudaGetSymbolAddress((void**)&Kh, g_Kh);   cudaGetSymbolAddress((void**)&Kl, g_Kl);
    cudaGetSymbolAddress((void**)&Vf, g_Vf);
    cudaGetSymbolAddress((void**)&Oh, g_Oh);   cudaGetSymbolAddress((void**)&Ol, g_Ol);
    cudaGetSymbolAddress((void**)&cb, g_cbias);
    cudaGetSymbolAddress((void**)&idx, g_idx);
    cudaGetSymbolAddress((void**)&nv, g_nv);

    cudaFuncSetAttribute(gemm3_mma,
                         cudaFuncAttributeMaxDynamicSharedMemorySize, GT_SMEM);
    cudaFuncSetAttribute(gemm_out_mma,
                         cudaFuncAttributeMaxDynamicSharedMemorySize, GT_SMEM);
    cudaFuncSetAttribute(flash_mma_k,
                         cudaFuncAttributeMaxDynamicSharedMemorySize, AT_SMEM);

    // 0: mask scan/compaction
    scan_mask_k<<<BB, 512>>>(mask, idx, nv, cb);

    // 1: all splits fused (q + gathered k/v + 4 weight matrices)
    SplitArgs sa;
    sa.q = q; sa.k = k; sa.v = v;
    sa.wq = Wq; sa.wk = Wk; sa.wv = Wv; sa.wo = Wo;
    sa.qh = qAh; sa.ql = qAl; sa.kch = kAh; sa.kcl = kAl;
    sa.vch = vAh; sa.vcl = vAl;
    sa.wqh = WqH; sa.wql = WqL; sa.wkh = WkH; sa.wkl = WkL;
    sa.wvh = WvH; sa.wvl = WvL; sa.woh = WoH; sa.wol = WoL;
    sa.idx = idx; sa.nv = nv;
    split_all_k<<<1024, 256>>>(sa);

    // 2: fused QKV projections
    G3Args p;
    p.Ah[0] = qAh; p.Al[0] = qAl; p.Bh[0] = WqH; p.Bl[0] = WqL;
    p.bias[0] = bq; p.Ch[0] = Qh; p.Cl[0] = Ql;
    p.Ah[1] = kAh; p.Al[1] = kAl; p.Bh[1] = WkH; p.Bl[1] = WkL;
    p.bias[1] = bk; p.Ch[1] = Kh; p.Cl[1] = Kl;
    p.Ah[2] = vAh; p.Al[2] = vAl; p.Bh[2] = WvH; p.Bl[2] = WvL;
    p.bias[2] = bv; p.Ch[2] = nullptr; p.Cl[2] = nullptr;
    p.Vf = Vf;
    p.nv = nv;
    dim3 gg3(DD / 128, MTOT / 128, 3);
    gemm3_mma<<<gg3, 256, GT_SMEM>>>(p);

    // 3: attention over compacted keys (profiled)
    dim3 ga(SSQ / 64, BB * HHD);   // (32, 32) = 1024 CTAs, 128 thr
    flash_mma_k<<<ga, 128, AT_SMEM>>>(Qh, Ql, Kh, Kl, Vf, cb, nv, Oh, Ol);

    // 4: output projection
    dim3 gg(DD / 128, MTOT / 128);
    gemm_out_mma<<<gg, 256, GT_SMEM>>>(Oh, Ol, WoH, WoL, bo, out);
}

// round 13
// speedup vs baseline: 1.0866x; 1.0866x over previous
#include <cuda_runtime.h>
#include <cuda_bf16.h>
#include <cuda_fp16.h>
#include <math.h>
#include <stdint.h>

// Problem dims
#define BB   2
#define SSQ  2048
#define DD   1024
#define HHD  16
#define DKK  64
#define MTOT (BB * SSQ)   // 4096

typedef __nv_bfloat16 bf16;
typedef __nv_bfloat162 bf162;

#define LOG2E 1.44269504f

// ---------------------------------------------------------------------------
// Scratch (__device__ globals; no allocation allowed)
// ---------------------------------------------------------------------------
__device__ bf16 g_qAh[MTOT * DD], g_qAl[MTOT * DD];
__device__ bf16 g_kAh[MTOT * DD], g_kAl[MTOT * DD];   // compacted k input
__device__ bf16 g_vAh[MTOT * DD], g_vAl[MTOT * DD];   // compacted v input
__device__ bf16 g_WqH[DD * DD], g_WqL[DD * DD];
__device__ bf16 g_WkH[DD * DD], g_WkL[DD * DD];
__device__ bf16 g_WvH[DD * DD], g_WvL[DD * DD];
__device__ __half g_WoH[DD * DD], g_WoL[DD * DD];     // Wo split in fp16
__device__ bf16 g_Qh[MTOT * DD], g_Ql[MTOT * DD];
__device__ bf16 g_Kh[MTOT * DD], g_Kl[MTOT * DD];     // compacted projected K
__device__ __half g_Vf[MTOT * DD];                    // compacted projected V (fp16)
__device__ __half g_Of[MTOT * DD];                    // attention output (fp16)
__device__ float g_cbias[MTOT];                       // compacted bias
__device__ int   g_idx[MTOT];                         // compaction permutation
__device__ int   g_nv[BB];                            // valid keys per batch

// ---------------------------------------------------------------------------
// PTX helpers
// ---------------------------------------------------------------------------
__device__ __forceinline__ uint32_t smem_u32(const void* p) {
    uint32_t a;
    asm("{ .reg .u64 t; cvta.to.shared.u64 t, %1; cvt.u32.u64 %0, t; }"
        : "=r"(a) : "l"(p));
    return a;
}
__device__ __forceinline__ void ldsm4(uint32_t r[4], uint32_t a) {
    asm volatile("ldmatrix.sync.aligned.m8n8.x4.shared.b16 {%0,%1,%2,%3}, [%4];"
                 : "=r"(r[0]), "=r"(r[1]), "=r"(r[2]), "=r"(r[3]) : "r"(a));
}
__device__ __forceinline__ void ldsm4t(uint32_t r[4], uint32_t a) {
    asm volatile("ldmatrix.sync.aligned.m8n8.x4.trans.shared.b16 {%0,%1,%2,%3}, [%4];"
                 : "=r"(r[0]), "=r"(r[1]), "=r"(r[2]), "=r"(r[3]) : "r"(a));
}
__device__ __forceinline__ void mma16816(float* c, const uint32_t* a,
                                         uint32_t b0, uint32_t b1) {
    asm("mma.sync.aligned.m16n8k16.row.col.f32.bf16.bf16.f32 "
        "{%0,%1,%2,%3}, {%4,%5,%6,%7}, {%8,%9}, {%0,%1,%2,%3};"
        : "+f"(c[0]), "+f"(c[1]), "+f"(c[2]), "+f"(c[3])
        : "r"(a[0]), "r"(a[1]), "r"(a[2]), "r"(a[3]), "r"(b0), "r"(b1));
}
// fp16 variant (f32 accumulate)
__device__ __forceinline__ void mma16816h(float* c, const uint32_t* a,
                                          uint32_t b0, uint32_t b1) {
    asm("mma.sync.aligned.m16n8k16.row.col.f32.f16.f16.f32 "
        "{%0,%1,%2,%3}, {%4,%5,%6,%7}, {%8,%9}, {%0,%1,%2,%3};"
        : "+f"(c[0]), "+f"(c[1]), "+f"(c[2]), "+f"(c[3])
        : "r"(a[0]), "r"(a[1]), "r"(a[2]), "r"(a[3]), "r"(b0), "r"(b1));
}
__device__ __forceinline__ uint32_t bits(bf162 h) {
    return *reinterpret_cast<uint32_t*>(&h);
}
__device__ __forceinline__ uint32_t bitsh(__half2 h) {
    return *reinterpret_cast<uint32_t*>(&h);
}
__device__ __forceinline__ float ex2f(float x) {
    float y;
    asm("ex2.approx.ftz.f32 %0, %1;" : "=f"(y) : "f"(x));
    return y;
}
#define CP16(dst, src) \
    asm volatile("cp.async.cg.shared.global [%0], [%1], 16;" \
                 :: "r"(dst), "l"(src) : "memory")
#define CPCOMMIT() asm volatile("cp.async.commit_group;" ::: "memory")
#define CPWAIT1()  asm volatile("cp.async.wait_group 1;" ::: "memory")
#define CPWAIT0()  asm volatile("cp.async.wait_group 0;" ::: "memory")

// defensive clamp for scratch-derived control values
__device__ __forceinline__ int clamp_nv(int x) {
    return x < 0 ? 0 : (x > SSQ ? SSQ : x);
}

// ---------------------------------------------------------------------------
// Mask compaction: deterministic (stable) prefix scan, one block per batch.
// ---------------------------------------------------------------------------
__global__ void scan_mask_k(const int* __restrict__ mask, int* __restrict__ idx,
                            int* __restrict__ nv, float* __restrict__ cbias)
{
    __shared__ int warp_sums[16];
    __shared__ int s_nv;
    const int b = blockIdx.x;
    const int tid = threadIdx.x;          // 512 threads, 4 keys each
    const int lane = tid & 31, wrp = tid >> 5;
    const int base = tid * 4;

    int m[4];
#pragma unroll
    for (int u = 0; u < 4; u++) m[u] = mask[b * SSQ + base + u] != 0;
    int local = m[0] + m[1] + m[2] + m[3];

    int pre = local;   // inclusive warp scan
#pragma unroll
    for (int d = 1; d < 32; d <<= 1) {
        int y = __shfl_up_sync(0xffffffffu, pre, d);
        if (lane >= d) pre += y;
    }
    if (lane == 31) warp_sums[wrp] = pre;
    __syncthreads();
    if (wrp == 0) {
        int ws = (lane < 16) ? warp_sums[lane] : 0;
#pragma unroll
        for (int d = 1; d < 16; d <<= 1) {
            int y = __shfl_up_sync(0xffffffffu, ws, d);
            if (lane >= d) ws += y;
        }
        if (lane < 16) warp_sums[lane] = ws;
        if (lane == 15) s_nv = ws;
    }
    __syncthreads();

    int offset = (pre - local) + (wrp > 0 ? warp_sums[wrp - 1] : 0);
#pragma unroll
    for (int u = 0; u < 4; u++) {
        if (m[u] && offset < SSQ) { idx[b * SSQ + offset] = base + u; offset++; }
    }
    const int total = s_nv;
    if (tid == 0) nv[b] = total;
#pragma unroll
    for (int u = 0; u < 4; u++) {
        int j = base + u;
        cbias[b * SSQ + j] = (j < total) ? 0.0f : -1e9f * LOG2E;
    }
}

// ---------------------------------------------------------------------------
// split helpers
// ---------------------------------------------------------------------------
__device__ __forceinline__ void split_store(float4 v, bf16* __restrict__ hi,
                                            bf16* __restrict__ lo, int i)
{
    bf16 h0 = __float2bfloat16_rn(v.x), h1 = __float2bfloat16_rn(v.y);
    bf16 h2 = __float2bfloat16_rn(v.z), h3 = __float2bfloat16_rn(v.w);
    bf16 l0 = __float2bfloat16_rn(v.x - __bfloat162float(h0));
    bf16 l1 = __float2bfloat16_rn(v.y - __bfloat162float(h1));
    bf16 l2 = __float2bfloat16_rn(v.z - __bfloat162float(h2));
    bf16 l3 = __float2bfloat16_rn(v.w - __bfloat162float(h3));
    ((bf162*)hi)[2 * i + 0] = bf162(h0, h1);
    ((bf162*)hi)[2 * i + 1] = bf162(h2, h3);
    ((bf162*)lo)[2 * i + 0] = bf162(l0, l1);
    ((bf162*)lo)[2 * i + 1] = bf162(l2, l3);
}

__device__ __forceinline__ void split_store_h(float4 v, __half* __restrict__ hi,
                                              __half* __restrict__ lo, int i)
{
    __half h0 = __float2half_rn(v.x), h1 = __float2half_rn(v.y);
    __half h2 = __float2half_rn(v.z), h3 = __float2half_rn(v.w);
    __half l0 = __float2half_rn(v.x - __half2float(h0));
    __half l1 = __float2half_rn(v.y - __half2float(h1));
    __half l2 = __float2half_rn(v.z - __half2float(h2));
    __half l3 = __float2half_rn(v.w - __half2float(h3));
    ((__half2*)hi)[2 * i + 0] = __half2(h0, h1);
    ((__half2*)hi)[2 * i + 1] = __half2(h2, h3);
    ((__half2*)lo)[2 * i + 0] = __half2(l0, l1);
    ((__half2*)lo)[2 * i + 1] = __half2(l2, l3);
}

// All splits in one kernel:
//   [0, 1M)   : q full split (bf16 hi/lo)
//   [1M, 3M)  : k,v gathered-compacted split (+ zero pad to rnd128)
//   [3M, 4M)  : 4 weight matrices; Wo -> fp16 hi/lo, others bf16 hi/lo
struct SplitArgs {
    const float *q, *k, *v;
    const float *wq, *wk, *wv, *wo;
    bf16 *qh, *ql, *kch, *kcl, *vch, *vcl;
    bf16 *wqh, *wql, *wkh, *wkl, *wvh, *wvl;
    __half *woh, *wol;
    const int *idx, *nv;
};

__global__ void split_all_k(SplitArgs a)
{
    const int n4q = MTOT * DD / 4;          // 1M
    const int n4kv = 2 * MTOT * DD / 4;     // 2M
    const int n4w = DD * DD / 4;            // 256K
    const int total = n4q + n4kv + 4 * n4w; // 4M
    int i = blockIdx.x * blockDim.x + threadIdx.x;
    int stride = gridDim.x * blockDim.x;
    for (; i < total; i += stride) {
        if (i < n4q) {
            split_store(((const float4*)a.q)[i], a.qh, a.ql, i);
            continue;
        }
        if (i < n4q + n4kv) {
            int r = i - n4q;                // [0, 2M)
            int tsel = r >> 20;             // 0=k, 1=v
            int rem = r & ((1 << 20) - 1);
            int b = rem >> 19;
            int loc = rem & ((1 << 19) - 1);
            int row = loc >> 8;             // 0..2047
            int c4 = loc & 255;
            int nvb = clamp_nv(a.nv[b]);
            int rnd = (nvb + 127) & ~127;
            if (row >= rnd) continue;
            bf16* hi = tsel ? a.vch : a.kch;
            bf16* lo = tsel ? a.vcl : a.kcl;
            int dsti = (b * SSQ + row) * 256 + c4;
            if (row < nvb) {
                const float* src = tsel ? a.v : a.k;
                int srow = a.idx[b * SSQ + row] & (SSQ - 1);
                split_store(((const float4*)src)[(b * SSQ + srow) * 256 + c4],
                            hi, lo, dsti);
            } else {
                split_store(make_float4(0.f, 0.f, 0.f, 0.f), hi, lo, dsti);
            }
            continue;
        }
        int r = i - n4q - n4kv;             // [0, 1M)
        int wsel = r / n4w;
        int wi = r - wsel * n4w;
        if (wsel == 0)      split_store(((const float4*)a.wq)[wi], a.wqh, a.wql, wi);
        else if (wsel == 1) split_store(((const float4*)a.wk)[wi], a.wkh, a.wkl, wi);
        else if (wsel == 2) split_store(((const float4*)a.wv)[wi], a.wvh, a.wvl, wi);
        else                split_store_h(((const float4*)a.wo)[wi], a.woh, a.wol, wi);
    }
}

// ---------------------------------------------------------------------------
// GEMM tiles: 128x128, BK=32, 8 warps (4m x 2n), warp 32x64, cp.async 2-stage
// ---------------------------------------------------------------------------
#define GS 40
#define GT_TILEB  (128 * GS * 2)
#define GT_STAGEB (4 * GT_TILEB)
#define GT_SMEM   (2 * GT_STAGEB)

__device__ __forceinline__ void gemm_stage_load(
    uint32_t sbase, const bf16* __restrict__ gAh, const bf16* __restrict__ gAl,
    const bf16* __restrict__ gBh, const bf16* __restrict__ gBl,
    int k0, int tid)
{
#pragma unroll
    for (int i = tid; i < 512; i += 256) {
        int r = i >> 2, c4 = i & 3;
        size_t go = (size_t)r * DD + k0 + c4 * 8;
        uint32_t so = (uint32_t)(r * GS + c4 * 8) * 2;
        CP16(sbase + so,                gAh + go);
        CP16(sbase + GT_TILEB + so,     gAl + go);
        CP16(sbase + 2 * GT_TILEB + so, gBh + go);
        CP16(sbase + 3 * GT_TILEB + so, gBl + go);
    }
}

__device__ __forceinline__ void gemm_mainloop(
    uint32_t sb, const bf16* gAh, const bf16* gAl,
    const bf16* gBh, const bf16* gBl,
    int tid, int lane, int wm, int wn, float acc[2][8][4])
{
    const int lrA = wm * 32 + (lane & 15);
    const int lcA = (lane >> 4) * 8;
    const int lrB = wn * 64 + ((lane >> 4) & 1) * 8 + (lane & 7);
    const int lcB = ((lane >> 3) & 1) * 8;

    gemm_stage_load(sb, gAh, gAl, gBh, gBl, 0, tid);
    CPCOMMIT();

    for (int t = 0; t < 32; ++t) {
        const int st = t & 1;
        if (t < 31) {
            gemm_stage_load(sb + (st ^ 1) * GT_STAGEB, gAh, gAl, gBh, gBl,
                            (t + 1) * 32, tid);
            CPCOMMIT();
            CPWAIT1();
        } else {
            CPWAIT0();
        }
        __syncthreads();

        const uint32_t bAh = sb + st * GT_STAGEB;
        const uint32_t bAl = bAh + GT_TILEB;
        const uint32_t bBh = bAh + 2 * GT_TILEB;
        const uint32_t bBl = bAh + 3 * GT_TILEB;

#pragma unroll
        for (int kb = 0; kb < 2; kb++) {
            uint32_t ah[2][4], al[2][4];
#pragma unroll
            for (int mi = 0; mi < 2; mi++) {
                uint32_t off = ((lrA + mi * 16) * GS + kb * 16 + lcA) * 2;
                ldsm4(ah[mi], bAh + off);
                ldsm4(al[mi], bAl + off);
            }
#pragma unroll
            for (int njp = 0; njp < 4; njp++) {
                uint32_t off = ((lrB + njp * 16) * GS + kb * 16 + lcB) * 2;
                uint32_t bh[4], bl[4];
                ldsm4(bh, bBh + off);
                ldsm4(bl, bBl + off);
                float* c00 = acc[0][njp * 2];
                float* c01 = acc[0][njp * 2 + 1];
                float* c10 = acc[1][njp * 2];
                float* c11 = acc[1][njp * 2 + 1];
                mma16816(c00, ah[0], bh[0], bh[1]);
                mma16816(c10, ah[1], bh[0], bh[1]);
                mma16816(c01, ah[0], bh[2], bh[3]);
                mma16816(c11, ah[1], bh[2], bh[3]);
                mma16816(c00, ah[0], bl[0], bl[1]);
                mma16816(c10, ah[1], bl[0], bl[1]);
                mma16816(c01, ah[0], bl[2], bl[3]);
                mma16816(c11, ah[1], bl[2], bl[3]);
                mma16816(c00, al[0], bh[0], bh[1]);
                mma16816(c10, al[1], bh[0], bh[1]);
                mma16816(c01, al[0], bh[2], bh[3]);
                mma16816(c11, al[1], bh[2], bh[3]);
            }
        }
        __syncthreads();
    }
}

// Fused QKV projections; K/V (z>0) skip CTAs above the valid compacted rows.
// z==2 (V) writes SINGLE fp16 output; z<2 write bf16 hi/lo.
struct G3Args {
    const bf16 *Ah[3], *Al[3], *Bh[3], *Bl[3];
    const float* bias[3];
    bf16 *Ch[3], *Cl[3];
    __half* Vf;
    const int* nv;
};

__global__ __launch_bounds__(256, 2) void gemm3_mma(G3Args p)
{
    extern __shared__ __align__(16) char dyn[];
    const uint32_t sb = smem_u32(dyn);
    const int z = blockIdx.z;
    const int bm = blockIdx.y * 128;
    const int bn = blockIdx.x * 128;

    if (z > 0) {   // K or V projection: skip masked-out row tiles
        int batch = bm >> 11;
        int local = bm & 2047;
        int rnd = (clamp_nv(p.nv[batch]) + 127) & ~127;
        if (local >= rnd) return;
    }

    const int tid  = threadIdx.x;
    const int lane = tid & 31;
    const int warp = tid >> 5;
    const int wm = warp & 3, wn = warp >> 2;

    float acc[2][8][4];
#pragma unroll
    for (int mi = 0; mi < 2; mi++)
#pragma unroll
        for (int nj = 0; nj < 8; nj++)
#pragma unroll
            for (int e = 0; e < 4; e++) acc[mi][nj][e] = 0.0f;

    gemm_mainloop(sb,
                  p.Ah[z] + (size_t)bm * DD, p.Al[z] + (size_t)bm * DD,
                  p.Bh[z] + (size_t)bn * DD, p.Bl[z] + (size_t)bn * DD,
                  tid, lane, wm, wn, acc);

    const float* bias = p.bias[z];
    const int g = lane >> 2, c = lane & 3;
    if (z == 2) {
        __half* Vf = p.Vf;
#pragma unroll
        for (int mi = 0; mi < 2; mi++) {
#pragma unroll
            for (int nj = 0; nj < 8; nj++) {
                int row = bm + wm * 32 + mi * 16 + g;
                int col = bn + wn * 64 + nj * 8 + c * 2;
                float b0 = bias[col], b1 = bias[col + 1];
                __half2 v01 = __float22half2_rn(
                    make_float2(acc[mi][nj][0] + b0, acc[mi][nj][1] + b1));
                __half2 v23 = __float22half2_rn(
                    make_float2(acc[mi][nj][2] + b0, acc[mi][nj][3] + b1));
                *(__half2*)&Vf[(size_t)row * DD + col] = v01;
                *(__half2*)&Vf[(size_t)(row + 8) * DD + col] = v23;
            }
        }
    } else {
        bf16* Chi = p.Ch[z];
        bf16* Clo = p.Cl[z];
#pragma unroll
        for (int mi = 0; mi < 2; mi++) {
#pragma unroll
            for (int nj = 0; nj < 8; nj++) {
                int row = bm + wm * 32 + mi * 16 + g;
                int col = bn + wn * 64 + nj * 8 + c * 2;
                float b0 = bias[col], b1 = bias[col + 1];
                float x0 = acc[mi][nj][0] + b0, x1 = acc[mi][nj][1] + b1;
                float x2 = acc[mi][nj][2] + b0, x3 = acc[mi][nj][3] + b1;
                bf162 h01 = __float22bfloat162_rn(make_float2(x0, x1));
                bf162 h23 = __float22bfloat162_rn(make_float2(x2, x3));
                bf162 l01 = __float22bfloat162_rn(make_float2(
                    x0 - __low2float(h01), x1 - __high2float(h01)));
                bf162 l23 = __float22bfloat162_rn(make_float2(
                    x2 - __low2float(h23), x3 - __high2float(h23)));
                *(bf162*)&Chi[(size_t)row * DD + col] = h01;
                *(bf162*)&Clo[(size_t)row * DD + col] = l01;
                *(bf162*)&Chi[(size_t)(row + 8) * DD + col] = h23;
                *(bf162*)&Clo[(size_t)(row + 8) * DD + col] = l23;
            }
        }
    }
}

// ---------------------------------------------------------------------------
// Output projection: A = Of (single fp16), W = WoH/WoL (fp16 hi/lo).
// 2 fp16 MMAs per product. 3-tile stages.
// ---------------------------------------------------------------------------
#define GO_TILEB  (128 * GS * 2)      // 10240 B
#define GO_STAGEB (3 * GO_TILEB)      // 30720 B
#define GO_SMEM   (2 * GO_STAGEB)     // 61440 B

__global__ __launch_bounds__(256, 2) void gemm_out_mma(
    const __half* __restrict__ Af,
    const __half* __restrict__ Wh, const __half* __restrict__ Wl,
    const float* __restrict__ bias, float* __restrict__ Cf)
{
    extern __shared__ __align__(16) char dyn[];
    const uint32_t sb = smem_u32(dyn);
    const int tid  = threadIdx.x;
    const int lane = tid & 31;
    const int warp = tid >> 5;
    const int wm = warp & 3, wn = warp >> 2;
    const int bm = blockIdx.y * 128;
    const int bn = blockIdx.x * 128;

    const __half* gA  = Af + (size_t)bm * DD;
    const __half* gWh = Wh + (size_t)bn * DD;
    const __half* gWl = Wl + (size_t)bn * DD;

    float acc[2][8][4];
#pragma unroll
    for (int mi = 0; mi < 2; mi++)
#pragma unroll
        for (int nj = 0; nj < 8; nj++)
#pragma unroll
            for (int e = 0; e < 4; e++) acc[mi][nj][e] = 0.0f;

    const int lrA = wm * 32 + (lane & 15);
    const int lcA = (lane >> 4) * 8;
    const int lrB = wn * 64 + ((lane >> 4) & 1) * 8 + (lane & 7);
    const int lcB = ((lane >> 3) & 1) * 8;

    // stage loader (lambda-free)
#define GO_LOAD(stage, k0)                                              \
    do {                                                                \
        uint32_t sbase = sb + (stage) * GO_STAGEB;                      \
        _Pragma("unroll")                                               \
        for (int i = tid; i < 512; i += 256) {                          \
            int r = i >> 2, c4 = i & 3;                                 \
            size_t go = (size_t)r * DD + (k0) + c4 * 8;                 \
            uint32_t so = (uint32_t)(r * GS + c4 * 8) * 2;              \
            CP16(sbase + so,                gA + go);                   \
            CP16(sbase + GO_TILEB + so,     gWh + go);                  \
            CP16(sbase + 2 * GO_TILEB + so, gWl + go);                  \
        }                                                               \
    } while (0)

    GO_LOAD(0, 0);
    CPCOMMIT();

    for (int t = 0; t < 32; ++t) {
        const int st = t & 1;
        if (t < 31) {
            GO_LOAD(st ^ 1, (t + 1) * 32);
            CPCOMMIT();
            CPWAIT1();
        } else {
            CPWAIT0();
        }
        __syncthreads();

        const uint32_t bA  = sb + st * GO_STAGEB;
        const uint32_t bWh = bA + GO_TILEB;
        const uint32_t bWl = bA + 2 * GO_TILEB;

#pragma unroll
        for (int kb = 0; kb < 2; kb++) {
            uint32_t av[2][4];
#pragma unroll
            for (int mi = 0; mi < 2; mi++) {
                uint32_t off = ((lrA + mi * 16) * GS + kb * 16 + lcA) * 2;
                ldsm4(av[mi], bA + off);
            }
#pragma unroll
            for (int njp = 0; njp < 4; njp++) {
                uint32_t off = ((lrB + njp * 16) * GS + kb * 16 + lcB) * 2;
                uint32_t bh[4], bl[4];
                ldsm4(bh, bWh + off);
                ldsm4(bl, bWl + off);
                float* c00 = acc[0][njp * 2];
                float* c01 = acc[0][njp * 2 + 1];
                float* c10 = acc[1][njp * 2];
                float* c11 = acc[1][njp * 2 + 1];
                mma16816h(c00, av[0], bh[0], bh[1]);
                mma16816h(c10, av[1], bh[0], bh[1]);
                mma16816h(c01, av[0], bh[2], bh[3]);
                mma16816h(c11, av[1], bh[2], bh[3]);
                mma16816h(c00, av[0], bl[0], bl[1]);
                mma16816h(c10, av[1], bl[0], bl[1]);
                mma16816h(c01, av[0], bl[2], bl[3]);
                mma16816h(c11, av[1], bl[2], bl[3]);
            }
        }
        __syncthreads();
    }
#undef GO_LOAD

    const int g = lane >> 2, c = lane & 3;
#pragma unroll
    for (int mi = 0; mi < 2; mi++) {
#pragma unroll
        for (int nj = 0; nj < 8; nj++) {
            int row = bm + wm * 32 + mi * 16 + g;
            int col = bn + wn * 64 + nj * 8 + c * 2;
            float b0 = bias[col], b1 = bias[col + 1];
            *(float2*)&Cf[(size_t)row * DD + col] =
                make_float2(acc[mi][nj][0] + b0, acc[mi][nj][1] + b1);
            *(float2*)&Cf[(size_t)(row + 8) * DD + col] =
                make_float2(acc[mi][nj][2] + b0, acc[mi][nj][3] + b1);
        }
    }
}

// ---------------------------------------------------------------------------
// Flash attention over COMPACTED keys (R10-proven geometry):
// 256 threads / 8 warps / 128 q-rows per CTA, 2-stage cp.async KV pipeline.
// QK: bf16 x3 terms.  PV: single fp16 MMA.  Output: single fp16.
// ---------------------------------------------------------------------------
#define AS 72
#define AT_TILEB  (64 * AS * 2)        // 9216 B per operand tile
#define AT_STAGEB (3 * AT_TILEB)       // 27648 B per stage (Kh | Kl | Vf)
#define AT_SMEM   (2 * AT_STAGEB)      // 55296 B

__device__ __forceinline__ void att_stage_load(
    uint32_t sbase, const bf16* __restrict__ Kh, const bf16* __restrict__ Kl,
    const __half* __restrict__ Vf, size_t gbase, int tid)
{
#pragma unroll
    for (int i = tid; i < 512; i += 256) {
        int r = i >> 3, c8 = i & 7;
        size_t go = gbase + (size_t)r * DD + c8 * 8;
        uint32_t so = (uint32_t)(r * AS + c8 * 8) * 2;
        CP16(sbase + so,                Kh + go);
        CP16(sbase + AT_TILEB + so,     Kl + go);
        CP16(sbase + 2 * AT_TILEB + so, Vf + go);
    }
}

__global__ __launch_bounds__(256) void flash_mma_k(
    const bf16* __restrict__ Qh, const bf16* __restrict__ Ql,
    const bf16* __restrict__ Kh, const bf16* __restrict__ Kl,
    const __half* __restrict__ Vf,
    const float* __restrict__ cb, const int* __restrict__ nvp,
    __half* __restrict__ Of)
{
    extern __shared__ __align__(16) char dyn[];
    __shared__ __align__(16) float sBias[2][64];
    const uint32_t sb = smem_u32(dyn);
    const uint32_t sbias_u32 = smem_u32(&sBias[0][0]);

    const int tid  = threadIdx.x;
    const int lane = tid & 31;
    const int w    = tid >> 5;
    const int b  = blockIdx.y >> 4;
    const int h  = blockIdx.y & 15;
    const int q0 = blockIdx.x * 128;
    const int g = lane >> 2, c = lane & 3;
    const int nt = (clamp_nv(nvp[b]) + 63) >> 6;

    // ---- Phase 1: Q tile -> fragments ----
    {
        bf16* sQh = (bf16*)dyn;
        bf16* sQl = (bf16*)(dyn + 128 * AS * 2);
        const bf16* gQh = Qh + (size_t)(b * SSQ + q0) * DD + h * DKK;
        const bf16* gQl = Ql + (size_t)(b * SSQ + q0) * DD + h * DKK;
#pragma unroll
        for (int i = tid; i < 1024; i += 256) {
            int r = i >> 3, c8 = i & 7;
            size_t go = (size_t)r * DD + c8 * 8;
            int so = r * AS + c8 * 8;
            *(uint4*)&sQh[so] = *(const uint4*)&gQh[go];
            *(uint4*)&sQl[so] = *(const uint4*)&gQl[go];
        }
    }
    __syncthreads();

    uint32_t qh[4][4], ql[4][4];
    {
        const int lrQ = w * 16 + (lane & 15);
        const int lcQ = (lane >> 4) * 8;
        const uint32_t bQh = sb;
        const uint32_t bQl = sb + 128 * AS * 2;
#pragma unroll
        for (int kb = 0; kb < 4; kb++) {
            uint32_t off = (lrQ * AS + kb * 16 + lcQ) * 2;
            ldsm4(qh[kb], bQh + off);
            ldsm4(ql[kb], bQl + off);
        }
    }
    __syncthreads();

    float m0 = -INFINITY, m1 = -INFINITY, l0 = 0.0f, l1 = 0.0f;
    float acc[8][4];
#pragma unroll
    for (int on = 0; on < 8; on++)
#pragma unroll
        for (int e = 0; e < 4; e++) acc[on][e] = 0.0f;

    const int lrK = ((lane >> 4) & 1) * 8 + (lane & 7);
    const int lcK = ((lane >> 3) & 1) * 8;
    const int lrV = ((lane >> 3) & 1) * 8 + (lane & 7);
    const int lcV = (lane >> 4) * 8;
    const float scale2 = 0.125f * LOG2E;
    const size_t gKV0 = (size_t)(b * SSQ) * DD + h * DKK;

    if (nt > 0) {
        att_stage_load(sb, Kh, Kl, Vf, gKV0, tid);
        if (tid < 16) CP16(sbias_u32 + tid * 16, &cb[b * SSQ + tid * 4]);
        CPCOMMIT();
    }

    for (int t = 0; t < nt; ++t) {
        const int st = t & 1;
        if (t + 1 < nt) {
            att_stage_load(sb + (st ^ 1) * AT_STAGEB, Kh, Kl, Vf,
                           gKV0 + (size_t)(t + 1) * 64 * DD, tid);
            if (tid < 16)
                CP16(sbias_u32 + (st ^ 1) * 256 + tid * 16,
                     &cb[b * SSQ + (t + 1) * 64 + tid * 4]);
            CPCOMMIT();
            CPWAIT1();
        } else {
            CPWAIT0();
        }
        __syncthreads();

        const uint32_t bKh = sb + st * AT_STAGEB;
        const uint32_t bKl = bKh + AT_TILEB;
        const uint32_t bVf = bKh + 2 * AT_TILEB;

        // ---- S = Q K^T (bf16 x3) ----
        float s[8][4];
#pragma unroll
        for (int nj = 0; nj < 8; nj++)
#pragma unroll
            for (int e = 0; e < 4; e++) s[nj][e] = 0.0f;

#pragma unroll
        for (int kb = 0; kb < 4; kb++) {
#pragma unroll
            for (int np = 0; np < 2; np++) {
                uint32_t kh0[4], kl0[4], kh1[4], kl1[4];
                uint32_t off0 = (((np * 2 + 0) * 16 + lrK) * AS + kb * 16 + lcK) * 2;
                uint32_t off1 = (((np * 2 + 1) * 16 + lrK) * AS + kb * 16 + lcK) * 2;
                ldsm4(kh0, bKh + off0);
                ldsm4(kl0, bKl + off0);
                ldsm4(kh1, bKh + off1);
                ldsm4(kl1, bKl + off1);
                float* c0 = s[np * 4 + 0];
                float* c1 = s[np * 4 + 1];
                float* c2 = s[np * 4 + 2];
                float* c3 = s[np * 4 + 3];
                mma16816(c0, qh[kb], kh0[0], kh0[1]);
                mma16816(c1, qh[kb], kh0[2], kh0[3]);
                mma16816(c2, qh[kb], kh1[0], kh1[1]);
                mma16816(c3, qh[kb], kh1[2], kh1[3]);
                mma16816(c0, qh[kb], kl0[0], kl0[1]);
                mma16816(c1, qh[kb], kl0[2], kl0[3]);
                mma16816(c2, qh[kb], kl1[0], kl1[1]);
                mma16816(c3, qh[kb], kl1[2], kl1[3]);
                mma16816(c0, ql[kb], kh0[0], kh0[1]);
                mma16816(c1, ql[kb], kh0[2], kh0[3]);
                mma16816(c2, ql[kb], kh1[0], kh1[1]);
                mma16816(c3, ql[kb], kh1[2], kh1[3]);
            }
        }

        // ---- scale + bias (exp2 domain; pad slots get -BIG) ----
#pragma unroll
        for (int nj = 0; nj < 8; nj++) {
            float b0 = sBias[st][nj * 8 + c * 2];
            float b1 = sBias[st][nj * 8 + c * 2 + 1];
            s[nj][0] = fmaf(s[nj][0], scale2, b0);
            s[nj][1] = fmaf(s[nj][1], scale2, b1);
            s[nj][2] = fmaf(s[nj][2], scale2, b0);
            s[nj][3] = fmaf(s[nj][3], scale2, b1);
        }

        // ---- online softmax ----
        float mx0 = -INFINITY, mx1 = -INFINITY;
#pragma unroll
        for (int nj = 0; nj < 8; nj++) {
            mx0 = fmaxf(mx0, fmaxf(s[nj][0], s[nj][1]));
            mx1 = fmaxf(mx1, fmaxf(s[nj][2], s[nj][3]));
        }
        mx0 = fmaxf(mx0, __shfl_xor_sync(0xffffffffu, mx0, 1));
        mx0 = fmaxf(mx0, __shfl_xor_sync(0xffffffffu, mx0, 2));
        mx1 = fmaxf(mx1, __shfl_xor_sync(0xffffffffu, mx1, 1));
        mx1 = fmaxf(mx1, __shfl_xor_sync(0xffffffffu, mx1, 2));
        float mn0 = fmaxf(m0, mx0), mn1 = fmaxf(m1, mx1);
        float f0 = ex2f(m0 - mn0), f1 = ex2f(m1 - mn1);
        m0 = mn0; m1 = mn1;

        float sum0 = 0.0f, sum1 = 0.0f;
#pragma unroll
        for (int nj = 0; nj < 8; nj++) {
            s[nj][0] = ex2f(s[nj][0] - m0);
            s[nj][1] = ex2f(s[nj][1] - m0);
            s[nj][2] = ex2f(s[nj][2] - m1);
            s[nj][3] = ex2f(s[nj][3] - m1);
            sum0 += s[nj][0] + s[nj][1];
            sum1 += s[nj][2] + s[nj][3];
        }
        sum0 += __shfl_xor_sync(0xffffffffu, sum0, 1);
        sum0 += __shfl_xor_sync(0xffffffffu, sum0, 2);
        sum1 += __shfl_xor_sync(0xffffffffu, sum1, 1);
        sum1 += __shfl_xor_sync(0xffffffffu, sum1, 2);
        l0 = l0 * f0 + sum0;
        l1 = l1 * f1 + sum1;
#pragma unroll
        for (int on = 0; on < 8; on++) {
            acc[on][0] *= f0; acc[on][1] *= f0;
            acc[on][2] *= f1; acc[on][3] *= f1;
        }

        // ---- O += P V : single fp16 MMA ----
#pragma unroll
        for (int kb2 = 0; kb2 < 4; kb2++) {
            uint32_t pa[4];
#pragma unroll
            for (int q2 = 0; q2 < 2; q2++) {
                float* sp = s[2 * kb2 + q2];
                pa[q2 * 2]     = bitsh(__float22half2_rn(make_float2(sp[0], sp[1])));
                pa[q2 * 2 + 1] = bitsh(__float22half2_rn(make_float2(sp[2], sp[3])));
            }
#pragma unroll
            for (int op = 0; op < 2; op++) {
                uint32_t vh0[4], vh1[4];
                uint32_t off0 = ((kb2 * 16 + lrV) * AS + (op * 2 + 0) * 16 + lcV) * 2;
                uint32_t off1 = ((kb2 * 16 + lrV) * AS + (op * 2 + 1) * 16 + lcV) * 2;
                ldsm4t(vh0, bVf + off0);
                ldsm4t(vh1, bVf + off1);
                mma16816h(acc[op * 4 + 0], pa, vh0[0], vh0[1]);
                mma16816h(acc[op * 4 + 1], pa, vh0[2], vh0[3]);
                mma16816h(acc[op * 4 + 2], pa, vh1[0], vh1[1]);
                mma16816h(acc[op * 4 + 3], pa, vh1[2], vh1[3]);
            }
        }
        __syncthreads();
    }

    // ---- epilogue: normalize, single fp16 store ----
    float inv0 = l0 > 0.f ? 1.0f / l0 : 0.f;
    float inv1 = l1 > 0.f ? 1.0f / l1 : 0.f;
    int rowg = b * SSQ + q0 + w * 16 + g;
#pragma unroll
    for (int on = 0; on < 8; on++) {
        int col = h * DKK + on * 8 + c * 2;
        __half2 o01 = __float22half2_rn(
            make_float2(acc[on][0] * inv0, acc[on][1] * inv0));
        __half2 o23 = __float22half2_rn(
            make_float2(acc[on][2] * inv1, acc[on][3] * inv1));
        *(__half2*)&Of[(size_t)rowg * DD + col] = o01;
        *(__half2*)&Of[(size_t)(rowg + 8) * DD + col] = o23;
    }
}

// ---------------------------------------------------------------------------
// Launch. Index 3 (profiled) = flash_mma_k.
// ---------------------------------------------------------------------------
extern "C" void kernel_launch(void* const* d_in, const int* in_sizes, int n_in,
                              void* d_out, int out_size)
{
    const float* q    = (const float*)d_in[0];
    const float* k    = (const float*)d_in[1];
    const float* v    = (const float*)d_in[2];
    const int*   mask = (const int*)  d_in[3];
    const float* Wq   = (const float*)d_in[4];
    const float* bq   = (const float*)d_in[5];
    const float* Wk   = (const float*)d_in[6];
    const float* bk   = (const float*)d_in[7];
    const float* Wv   = (const float*)d_in[8];
    const float* bv   = (const float*)d_in[9];
    const float* Wo   = (const float*)d_in[10];
    const float* bo   = (const float*)d_in[11];
    float* out = (float*)d_out;

    bf16 *qAh, *qAl, *kAh, *kAl, *vAh, *vAl;
    bf16 *WqH, *WqL, *WkH, *WkL, *WvH, *WvL;
    __half *WoH, *WoL;
    bf16 *Qh, *Ql, *Kh, *Kl;
    __half *Vf, *Of;
    float *cb; int *idx, *nv;
    cudaGetSymbolAddress((void**)&qAh, g_qAh); cudaGetSymbolAddress((void**)&qAl, g_qAl);
    cudaGetSymbolAddress((void**)&kAh, g_kAh); cudaGetSymbolAddress((void**)&kAl, g_kAl);
    cudaGetSymbolAddress((void**)&vAh, g_vAh); cudaGetSymbolAddress((void**)&vAl, g_vAl);
    cudaGetSymbolAddress((void**)&WqH, g_WqH); cudaGetSymbolAddress((void**)&WqL, g_WqL);
    cudaGetSymbolAddress((void**)&WkH, g_WkH); cudaGetSymbolAddress((void**)&WkL, g_WkL);
    cudaGetSymbolAddress((void**)&WvH, g_WvH); cudaGetSymbolAddress((void**)&WvL, g_WvL);
    cudaGetSymbolAddress((void**)&WoH, g_WoH); cudaGetSymbolAddress((void**)&WoL, g_WoL);
    cudaGetSymbolAddress((void**)&Qh, g_Qh);   cudaGetSymbolAddress((void**)&Ql, g_Ql);
    cudaGetSymbolAddress((void**)&Kh, g_Kh);   cudaGetSymbolAddress((void**)&Kl, g_Kl);
    cudaGetSymbolAddress((void**)&Vf, g_Vf);
    cudaGetSymbolAddress((void**)&Of, g_Of);
    cudaGetSymbolAddress((void**)&cb, g_cbias);
    cudaGetSymbolAddress((void**)&idx, g_idx);
    cudaGetSymbolAddress((void**)&nv, g_nv);

    cudaFuncSetAttribute(gemm3_mma,
                         cudaFuncAttributeMaxDynamicSharedMemorySize, GT_SMEM);
    cudaFuncSetAttribute(gemm_out_mma,
                         cudaFuncAttributeMaxDynamicSharedMemorySize, GO_SMEM);
    cudaFuncSetAttribute(flash_mma_k,
                         cudaFuncAttributeMaxDynamicSharedMemorySize, AT_SMEM);

    // 0: mask scan/compaction
    scan_mask_k<<<BB, 512>>>(mask, idx, nv, cb);

    // 1: all splits fused (q + gathered k/v + 4 weight matrices)
    SplitArgs sa;
    sa.q = q; sa.k = k; sa.v = v;
    sa.wq = Wq; sa.wk = Wk; sa.wv = Wv; sa.wo = Wo;
    sa.qh = qAh; sa.ql = qAl; sa.kch = kAh; sa.kcl = kAl;
    sa.vch = vAh; sa.vcl = vAl;
    sa.wqh = WqH; sa.wql = WqL; sa.wkh = WkH; sa.wkl = WkL;
    sa.wvh = WvH; sa.wvl = WvL; sa.woh = WoH; sa.wol = WoL;
    sa.idx = idx; sa.nv = nv;
    split_all_k<<<1024, 256>>>(sa);

    // 2: fused QKV projections
    G3Args p;
    p.Ah[0] = qAh; p.Al[0] = qAl; p.Bh[0] = WqH; p.Bl[0] = WqL;
    p.bias[0] = bq; p.Ch[0] = Qh; p.Cl[0] = Ql;
    p.Ah[1] = kAh; p.Al[1] = kAl; p.Bh[1] = WkH; p.Bl[1] = WkL;
    p.bias[1] = bk; p.Ch[1] = Kh; p.Cl[1] = Kl;
    p.Ah[2] = vAh; p.Al[2] = vAl; p.Bh[2] = WvH; p.Bl[2] = WvL;
    p.bias[2] = bv; p.Ch[2] = nullptr; p.Cl[2] = nullptr;
    p.Vf = Vf;
    p.nv = nv;
    dim3 gg3(DD / 128, MTOT / 128, 3);
    gemm3_mma<<<gg3, 256, GT_SMEM>>>(p);

    // 3: attention over compacted keys (profiled)
    dim3 ga(SSQ / 128, BB * HHD);   // (16, 32), 256 thr
    flash_mma_k<<<ga, 256, AT_SMEM>>>(Qh, Ql, Kh, Kl, Vf, cb, nv, Of);

    // 4: output projection (fp16 x2)
    dim3 gg(DD / 128, MTOT / 128);
    gemm_out_mma<<<gg, 256, GO_SMEM>>>(Of, WoH, WoL, bo, out);
}

// round 14
// speedup vs baseline: 1.2749x; 1.1733x over previous
#include <cuda_runtime.h>
#include <cuda_bf16.h>
#include <cuda_fp16.h>
#include <math.h>
#include <stdint.h>

// Problem dims
#define BB   2
#define SSQ  2048
#define DD   1024
#define HHD  16
#define DKK  64
#define MTOT (BB * SSQ)   // 4096

typedef __nv_bfloat16 bf16;
typedef __nv_bfloat162 bf162;

#define LOG2E 1.44269504f

// ---------------------------------------------------------------------------
// Scratch (__device__ globals; no allocation allowed)
// ---------------------------------------------------------------------------
__device__ bf16 g_qAh[MTOT * DD], g_qAl[MTOT * DD];
__device__ bf16 g_kAh[MTOT * DD], g_kAl[MTOT * DD];   // compacted k input
__device__ bf16 g_vAh[MTOT * DD], g_vAl[MTOT * DD];   // compacted v input
__device__ bf16 g_WqH[DD * DD], g_WqL[DD * DD];
__device__ bf16 g_WkH[DD * DD], g_WkL[DD * DD];
__device__ bf16 g_WvH[DD * DD], g_WvL[DD * DD];
__device__ __half g_WoH[DD * DD], g_WoL[DD * DD];     // Wo split in fp16
__device__ __half g_Qf[MTOT * DD];                    // projected Q (fp16)
__device__ __half g_Kf[MTOT * DD];                    // compacted projected K (fp16)
__device__ __half g_Vf[MTOT * DD];                    // compacted projected V (fp16)
__device__ __half g_Of[MTOT * DD];                    // attention output (fp16)
__device__ float g_cbias[MTOT];                       // compacted bias
__device__ int   g_idx[MTOT];                         // compaction permutation
__device__ int   g_nv[BB];                            // valid keys per batch

// ---------------------------------------------------------------------------
// PTX helpers
// ---------------------------------------------------------------------------
__device__ __forceinline__ uint32_t smem_u32(const void* p) {
    uint32_t a;
    asm("{ .reg .u64 t; cvta.to.shared.u64 t, %1; cvt.u32.u64 %0, t; }"
        : "=r"(a) : "l"(p));
    return a;
}
__device__ __forceinline__ void ldsm4(uint32_t r[4], uint32_t a) {
    asm volatile("ldmatrix.sync.aligned.m8n8.x4.shared.b16 {%0,%1,%2,%3}, [%4];"
                 : "=r"(r[0]), "=r"(r[1]), "=r"(r[2]), "=r"(r[3]) : "r"(a));
}
__device__ __forceinline__ void ldsm4t(uint32_t r[4], uint32_t a) {
    asm volatile("ldmatrix.sync.aligned.m8n8.x4.trans.shared.b16 {%0,%1,%2,%3}, [%4];"
                 : "=r"(r[0]), "=r"(r[1]), "=r"(r[2]), "=r"(r[3]) : "r"(a));
}
__device__ __forceinline__ void mma16816(float* c, const uint32_t* a,
                                         uint32_t b0, uint32_t b1) {
    asm("mma.sync.aligned.m16n8k16.row.col.f32.bf16.bf16.f32 "
        "{%0,%1,%2,%3}, {%4,%5,%6,%7}, {%8,%9}, {%0,%1,%2,%3};"
        : "+f"(c[0]), "+f"(c[1]), "+f"(c[2]), "+f"(c[3])
        : "r"(a[0]), "r"(a[1]), "r"(a[2]), "r"(a[3]), "r"(b0), "r"(b1));
}
// fp16 variant (f32 accumulate)
__device__ __forceinline__ void mma16816h(float* c, const uint32_t* a,
                                          uint32_t b0, uint32_t b1) {
    asm("mma.sync.aligned.m16n8k16.row.col.f32.f16.f16.f32 "
        "{%0,%1,%2,%3}, {%4,%5,%6,%7}, {%8,%9}, {%0,%1,%2,%3};"
        : "+f"(c[0]), "+f"(c[1]), "+f"(c[2]), "+f"(c[3])
        : "r"(a[0]), "r"(a[1]), "r"(a[2]), "r"(a[3]), "r"(b0), "r"(b1));
}
__device__ __forceinline__ uint32_t bitsh(__half2 h) {
    return *reinterpret_cast<uint32_t*>(&h);
}
__device__ __forceinline__ float ex2f(float x) {
    float y;
    asm("ex2.approx.ftz.f32 %0, %1;" : "=f"(y) : "f"(x));
    return y;
}
#define CP16(dst, src) \
    asm volatile("cp.async.cg.shared.global [%0], [%1], 16;" \
                 :: "r"(dst), "l"(src) : "memory")
#define CPCOMMIT() asm volatile("cp.async.commit_group;" ::: "memory")
#define CPWAIT1()  asm volatile("cp.async.wait_group 1;" ::: "memory")
#define CPWAIT0()  asm volatile("cp.async.wait_group 0;" ::: "memory")

__device__ __forceinline__ int clamp_nv(int x) {
    return x < 0 ? 0 : (x > SSQ ? SSQ : x);
}

// ---------------------------------------------------------------------------
// Mask compaction: deterministic (stable) prefix scan, one block per batch.
// ---------------------------------------------------------------------------
__global__ void scan_mask_k(const int* __restrict__ mask, int* __restrict__ idx,
                            int* __restrict__ nv, float* __restrict__ cbias)
{
    __shared__ int warp_sums[16];
    __shared__ int s_nv;
    const int b = blockIdx.x;
    const int tid = threadIdx.x;
    const int lane = tid & 31, wrp = tid >> 5;
    const int base = tid * 4;

    int m[4];
#pragma unroll
    for (int u = 0; u < 4; u++) m[u] = mask[b * SSQ + base + u] != 0;
    int local = m[0] + m[1] + m[2] + m[3];

    int pre = local;
#pragma unroll
    for (int d = 1; d < 32; d <<= 1) {
        int y = __shfl_up_sync(0xffffffffu, pre, d);
        if (lane >= d) pre += y;
    }
    if (lane == 31) warp_sums[wrp] = pre;
    __syncthreads();
    if (wrp == 0) {
        int ws = (lane < 16) ? warp_sums[lane] : 0;
#pragma unroll
        for (int d = 1; d < 16; d <<= 1) {
            int y = __shfl_up_sync(0xffffffffu, ws, d);
            if (lane >= d) ws += y;
        }
        if (lane < 16) warp_sums[lane] = ws;
        if (lane == 15) s_nv = ws;
    }
    __syncthreads();

    int offset = (pre - local) + (wrp > 0 ? warp_sums[wrp - 1] : 0);
#pragma unroll
    for (int u = 0; u < 4; u++) {
        if (m[u] && offset < SSQ) { idx[b * SSQ + offset] = base + u; offset++; }
    }
    const int total = s_nv;
    if (tid == 0) nv[b] = total;
#pragma unroll
    for (int u = 0; u < 4; u++) {
        int j = base + u;
        cbias[b * SSQ + j] = (j < total) ? 0.0f : -1e9f * LOG2E;
    }
}

// ---------------------------------------------------------------------------
// split helpers
// ---------------------------------------------------------------------------
__device__ __forceinline__ void split_store(float4 v, bf16* __restrict__ hi,
                                            bf16* __restrict__ lo, int i)
{
    bf16 h0 = __float2bfloat16_rn(v.x), h1 = __float2bfloat16_rn(v.y);
    bf16 h2 = __float2bfloat16_rn(v.z), h3 = __float2bfloat16_rn(v.w);
    bf16 l0 = __float2bfloat16_rn(v.x - __bfloat162float(h0));
    bf16 l1 = __float2bfloat16_rn(v.y - __bfloat162float(h1));
    bf16 l2 = __float2bfloat16_rn(v.z - __bfloat162float(h2));
    bf16 l3 = __float2bfloat16_rn(v.w - __bfloat162float(h3));
    ((bf162*)hi)[2 * i + 0] = bf162(h0, h1);
    ((bf162*)hi)[2 * i + 1] = bf162(h2, h3);
    ((bf162*)lo)[2 * i + 0] = bf162(l0, l1);
    ((bf162*)lo)[2 * i + 1] = bf162(l2, l3);
}

__device__ __forceinline__ void split_store_h(float4 v, __half* __restrict__ hi,
                                              __half* __restrict__ lo, int i)
{
    __half h0 = __float2half_rn(v.x), h1 = __float2half_rn(v.y);
    __half h2 = __float2half_rn(v.z), h3 = __float2half_rn(v.w);
    __half l0 = __float2half_rn(v.x - __half2float(h0));
    __half l1 = __float2half_rn(v.y - __half2float(h1));
    __half l2 = __float2half_rn(v.z - __half2float(h2));
    __half l3 = __float2half_rn(v.w - __half2float(h3));
    ((__half2*)hi)[2 * i + 0] = __half2(h0, h1);
    ((__half2*)hi)[2 * i + 1] = __half2(h2, h3);
    ((__half2*)lo)[2 * i + 0] = __half2(l0, l1);
    ((__half2*)lo)[2 * i + 1] = __half2(l2, l3);
}

// All splits in one kernel (layout identical to R13)
struct SplitArgs {
    const float *q, *k, *v;
    const float *wq, *wk, *wv, *wo;
    bf16 *qh, *ql, *kch, *kcl, *vch, *vcl;
    bf16 *wqh, *wql, *wkh, *wkl, *wvh, *wvl;
    __half *woh, *wol;
    const int *idx, *nv;
};

__global__ void split_all_k(SplitArgs a)
{
    const int n4q = MTOT * DD / 4;          // 1M
    const int n4kv = 2 * MTOT * DD / 4;     // 2M
    const int n4w = DD * DD / 4;            // 256K
    const int total = n4q + n4kv + 4 * n4w; // 4M
    int i = blockIdx.x * blockDim.x + threadIdx.x;
    int stride = gridDim.x * blockDim.x;
    for (; i < total; i += stride) {
        if (i < n4q) {
            split_store(((const float4*)a.q)[i], a.qh, a.ql, i);
            continue;
        }
        if (i < n4q + n4kv) {
            int r = i - n4q;
            int tsel = r >> 20;
            int rem = r & ((1 << 20) - 1);
            int b = rem >> 19;
            int loc = rem & ((1 << 19) - 1);
            int row = loc >> 8;
            int c4 = loc & 255;
            int nvb = clamp_nv(a.nv[b]);
            int rnd = (nvb + 127) & ~127;
            if (row >= rnd) continue;
            bf16* hi = tsel ? a.vch : a.kch;
            bf16* lo = tsel ? a.vcl : a.kcl;
            int dsti = (b * SSQ + row) * 256 + c4;
            if (row < nvb) {
                const float* src = tsel ? a.v : a.k;
                int srow = a.idx[b * SSQ + row] & (SSQ - 1);
                split_store(((const float4*)src)[(b * SSQ + srow) * 256 + c4],
                            hi, lo, dsti);
            } else {
                split_store(make_float4(0.f, 0.f, 0.f, 0.f), hi, lo, dsti);
            }
            continue;
        }
        int r = i - n4q - n4kv;
        int wsel = r / n4w;
        int wi = r - wsel * n4w;
        if (wsel == 0)      split_store(((const float4*)a.wq)[wi], a.wqh, a.wql, wi);
        else if (wsel == 1) split_store(((const float4*)a.wk)[wi], a.wkh, a.wkl, wi);
        else if (wsel == 2) split_store(((const float4*)a.wv)[wi], a.wvh, a.wvl, wi);
        else                split_store_h(((const float4*)a.wo)[wi], a.woh, a.wol, wi);
    }
}

// ---------------------------------------------------------------------------
// GEMM tiles: 128x128, BK=32, 8 warps (4m x 2n), warp 32x64, cp.async 2-stage
// ---------------------------------------------------------------------------
#define GS 40
#define GT_TILEB  (128 * GS * 2)
#define GT_STAGEB (4 * GT_TILEB)
#define GT_SMEM   (2 * GT_STAGEB)

__device__ __forceinline__ void gemm_stage_load(
    uint32_t sbase, const bf16* __restrict__ gAh, const bf16* __restrict__ gAl,
    const bf16* __restrict__ gBh, const bf16* __restrict__ gBl,
    int k0, int tid)
{
#pragma unroll
    for (int i = tid; i < 512; i += 256) {
        int r = i >> 2, c4 = i & 3;
        size_t go = (size_t)r * DD + k0 + c4 * 8;
        uint32_t so = (uint32_t)(r * GS + c4 * 8) * 2;
        CP16(sbase + so,                gAh + go);
        CP16(sbase + GT_TILEB + so,     gAl + go);
        CP16(sbase + 2 * GT_TILEB + so, gBh + go);
        CP16(sbase + 3 * GT_TILEB + so, gBl + go);
    }
}

__device__ __forceinline__ void gemm_mainloop(
    uint32_t sb, const bf16* gAh, const bf16* gAl,
    const bf16* gBh, const bf16* gBl,
    int tid, int lane, int wm, int wn, float acc[2][8][4])
{
    const int lrA = wm * 32 + (lane & 15);
    const int lcA = (lane >> 4) * 8;
    const int lrB = wn * 64 + ((lane >> 4) & 1) * 8 + (lane & 7);
    const int lcB = ((lane >> 3) & 1) * 8;

    gemm_stage_load(sb, gAh, gAl, gBh, gBl, 0, tid);
    CPCOMMIT();

    for (int t = 0; t < 32; ++t) {
        const int st = t & 1;
        if (t < 31) {
            gemm_stage_load(sb + (st ^ 1) * GT_STAGEB, gAh, gAl, gBh, gBl,
                            (t + 1) * 32, tid);
            CPCOMMIT();
            CPWAIT1();
        } else {
            CPWAIT0();
        }
        __syncthreads();

        const uint32_t bAh = sb + st * GT_STAGEB;
        const uint32_t bAl = bAh + GT_TILEB;
        const uint32_t bBh = bAh + 2 * GT_TILEB;
        const uint32_t bBl = bAh + 3 * GT_TILEB;

#pragma unroll
        for (int kb = 0; kb < 2; kb++) {
            uint32_t ah[2][4], al[2][4];
#pragma unroll
            for (int mi = 0; mi < 2; mi++) {
                uint32_t off = ((lrA + mi * 16) * GS + kb * 16 + lcA) * 2;
                ldsm4(ah[mi], bAh + off);
                ldsm4(al[mi], bAl + off);
            }
#pragma unroll
            for (int njp = 0; njp < 4; njp++) {
                uint32_t off = ((lrB + njp * 16) * GS + kb * 16 + lcB) * 2;
                uint32_t bh[4], bl[4];
                ldsm4(bh, bBh + off);
                ldsm4(bl, bBl + off);
                float* c00 = acc[0][njp * 2];
                float* c01 = acc[0][njp * 2 + 1];
                float* c10 = acc[1][njp * 2];
                float* c11 = acc[1][njp * 2 + 1];
                mma16816(c00, ah[0], bh[0], bh[1]);
                mma16816(c10, ah[1], bh[0], bh[1]);
                mma16816(c01, ah[0], bh[2], bh[3]);
                mma16816(c11, ah[1], bh[2], bh[3]);
                mma16816(c00, ah[0], bl[0], bl[1]);
                mma16816(c10, ah[1], bl[0], bl[1]);
                mma16816(c01, ah[0], bl[2], bl[3]);
                mma16816(c11, ah[1], bl[2], bl[3]);
                mma16816(c00, al[0], bh[0], bh[1]);
                mma16816(c10, al[1], bh[0], bh[1]);
                mma16816(c01, al[0], bh[2], bh[3]);
                mma16816(c11, al[1], bh[2], bh[3]);
            }
        }
        __syncthreads();
    }
}

// Fused QKV projections; K/V (z>0) skip masked-out row tiles.
// ALL outputs are single fp16 now (Qf / Kf / Vf).
struct G3Args {
    const bf16 *Ah[3], *Al[3], *Bh[3], *Bl[3];
    const float* bias[3];
    __half* Cf[3];
    const int* nv;
};

__global__ __launch_bounds__(256, 2) void gemm3_mma(G3Args p)
{
    extern __shared__ __align__(16) char dyn[];
    const uint32_t sb = smem_u32(dyn);
    const int z = blockIdx.z;
    const int bm = blockIdx.y * 128;
    const int bn = blockIdx.x * 128;

    if (z > 0) {
        int batch = bm >> 11;
        int local = bm & 2047;
        int rnd = (clamp_nv(p.nv[batch]) + 127) & ~127;
        if (local >= rnd) return;
    }

    const int tid  = threadIdx.x;
    const int lane = tid & 31;
    const int warp = tid >> 5;
    const int wm = warp & 3, wn = warp >> 2;

    float acc[2][8][4];
#pragma unroll
    for (int mi = 0; mi < 2; mi++)
#pragma unroll
        for (int nj = 0; nj < 8; nj++)
#pragma unroll
            for (int e = 0; e < 4; e++) acc[mi][nj][e] = 0.0f;

    gemm_mainloop(sb,
                  p.Ah[z] + (size_t)bm * DD, p.Al[z] + (size_t)bm * DD,
                  p.Bh[z] + (size_t)bn * DD, p.Bl[z] + (size_t)bn * DD,
                  tid, lane, wm, wn, acc);

    const float* bias = p.bias[z];
    __half* Cf = p.Cf[z];
    const int g = lane >> 2, c = lane & 3;
#pragma unroll
    for (int mi = 0; mi < 2; mi++) {
#pragma unroll
        for (int nj = 0; nj < 8; nj++) {
            int row = bm + wm * 32 + mi * 16 + g;
            int col = bn + wn * 64 + nj * 8 + c * 2;
            float b0 = bias[col], b1 = bias[col + 1];
            __half2 v01 = __float22half2_rn(
                make_float2(acc[mi][nj][0] + b0, acc[mi][nj][1] + b1));
            __half2 v23 = __float22half2_rn(
                make_float2(acc[mi][nj][2] + b0, acc[mi][nj][3] + b1));
            *(__half2*)&Cf[(size_t)row * DD + col] = v01;
            *(__half2*)&Cf[(size_t)(row + 8) * DD + col] = v23;
        }
    }
}

// ---------------------------------------------------------------------------
// Output projection: A = Of (single fp16), W = WoH/WoL (fp16 hi/lo), 2 MMAs.
// ---------------------------------------------------------------------------
#define GO_TILEB  (128 * GS * 2)
#define GO_STAGEB (3 * GO_TILEB)
#define GO_SMEM   (2 * GO_STAGEB)

__global__ __launch_bounds__(256, 2) void gemm_out_mma(
    const __half* __restrict__ Af,
    const __half* __restrict__ Wh, const __half* __restrict__ Wl,
    const float* __restrict__ bias, float* __restrict__ Cf)
{
    extern __shared__ __align__(16) char dyn[];
    const uint32_t sb = smem_u32(dyn);
    const int tid  = threadIdx.x;
    const int lane = tid & 31;
    const int warp = tid >> 5;
    const int wm = warp & 3, wn = warp >> 2;
    const int bm = blockIdx.y * 128;
    const int bn = blockIdx.x * 128;

    const __half* gA  = Af + (size_t)bm * DD;
    const __half* gWh = Wh + (size_t)bn * DD;
    const __half* gWl = Wl + (size_t)bn * DD;

    float acc[2][8][4];
#pragma unroll
    for (int mi = 0; mi < 2; mi++)
#pragma unroll
        for (int nj = 0; nj < 8; nj++)
#pragma unroll
            for (int e = 0; e < 4; e++) acc[mi][nj][e] = 0.0f;

    const int lrA = wm * 32 + (lane & 15);
    const int lcA = (lane >> 4) * 8;
    const int lrB = wn * 64 + ((lane >> 4) & 1) * 8 + (lane & 7);
    const int lcB = ((lane >> 3) & 1) * 8;

#define GO_LOAD(stage, k0)                                              \
    do {                                                                \
        uint32_t sbase = sb + (stage) * GO_STAGEB;                      \
        _Pragma("unroll")                                               \
        for (int i = tid; i < 512; i += 256) {                          \
            int r = i >> 2, c4 = i & 3;                                 \
            size_t go = (size_t)r * DD + (k0) + c4 * 8;                 \
            uint32_t so = (uint32_t)(r * GS + c4 * 8) * 2;              \
            CP16(sbase + so,                gA + go);                   \
            CP16(sbase + GO_TILEB + so,     gWh + go);                  \
            CP16(sbase + 2 * GO_TILEB + so, gWl + go);                  \
        }                                                               \
    } while (0)

    GO_LOAD(0, 0);
    CPCOMMIT();

    for (int t = 0; t < 32; ++t) {
        const int st = t & 1;
        if (t < 31) {
            GO_LOAD(st ^ 1, (t + 1) * 32);
            CPCOMMIT();
            CPWAIT1();
        } else {
            CPWAIT0();
        }
        __syncthreads();

        const uint32_t bA  = sb + st * GO_STAGEB;
        const uint32_t bWh = bA + GO_TILEB;
        const uint32_t bWl = bA + 2 * GO_TILEB;

#pragma unroll
        for (int kb = 0; kb < 2; kb++) {
            uint32_t av[2][4];
#pragma unroll
            for (int mi = 0; mi < 2; mi++) {
                uint32_t off = ((lrA + mi * 16) * GS + kb * 16 + lcA) * 2;
                ldsm4(av[mi], bA + off);
            }
#pragma unroll
            for (int njp = 0; njp < 4; njp++) {
                uint32_t off = ((lrB + njp * 16) * GS + kb * 16 + lcB) * 2;
                uint32_t bh[4], bl[4];
                ldsm4(bh, bWh + off);
                ldsm4(bl, bWl + off);
                float* c00 = acc[0][njp * 2];
                float* c01 = acc[0][njp * 2 + 1];
                float* c10 = acc[1][njp * 2];
                float* c11 = acc[1][njp * 2 + 1];
                mma16816h(c00, av[0], bh[0], bh[1]);
                mma16816h(c10, av[1], bh[0], bh[1]);
                mma16816h(c01, av[0], bh[2], bh[3]);
                mma16816h(c11, av[1], bh[2], bh[3]);
                mma16816h(c00, av[0], bl[0], bl[1]);
                mma16816h(c10, av[1], bl[0], bl[1]);
                mma16816h(c01, av[0], bl[2], bl[3]);
                mma16816h(c11, av[1], bl[2], bl[3]);
            }
        }
        __syncthreads();
    }
#undef GO_LOAD

    const int g = lane >> 2, c = lane & 3;
#pragma unroll
    for (int mi = 0; mi < 2; mi++) {
#pragma unroll
        for (int nj = 0; nj < 8; nj++) {
            int row = bm + wm * 32 + mi * 16 + g;
            int col = bn + wn * 64 + nj * 8 + c * 2;
            float b0 = bias[col], b1 = bias[col + 1];
            *(float2*)&Cf[(size_t)row * DD + col] =
                make_float2(acc[mi][nj][0] + b0, acc[mi][nj][1] + b1);
            *(float2*)&Cf[(size_t)(row + 8) * DD + col] =
                make_float2(acc[mi][nj][2] + b0, acc[mi][nj][3] + b1);
        }
    }
}

// ---------------------------------------------------------------------------
// Flash attention over COMPACTED keys.
// 256 threads / 8 warps / 128 q-rows per CTA, 2-stage cp.async KV pipeline.
// ALL-fp16 MMAs: QK = 1 fp16 MMA, PV = 1 fp16 MMA.  Output fp16.
// KV stage: [Kf | Vf] = 2 tiles.
// ---------------------------------------------------------------------------
#define AS 72
#define AT_TILEB  (64 * AS * 2)        // 9216 B per operand tile
#define AT_STAGEB (2 * AT_TILEB)       // 18432 B per stage (Kf | Vf)
#define AT_SMEM   (2 * AT_STAGEB)      // 36864 B

__device__ __forceinline__ void att_stage_load(
    uint32_t sbase, const __half* __restrict__ Kf,
    const __half* __restrict__ Vf, size_t gbase, int tid)
{
#pragma unroll
    for (int i = tid; i < 512; i += 256) {
        int r = i >> 3, c8 = i & 7;
        size_t go = gbase + (size_t)r * DD + c8 * 8;
        uint32_t so = (uint32_t)(r * AS + c8 * 8) * 2;
        CP16(sbase + so,            Kf + go);
        CP16(sbase + AT_TILEB + so, Vf + go);
    }
}

__global__ __launch_bounds__(256) void flash_mma_k(
    const __half* __restrict__ Qf,
    const __half* __restrict__ Kf, const __half* __restrict__ Vf,
    const float* __restrict__ cb, const int* __restrict__ nvp,
    __half* __restrict__ Of)
{
    extern __shared__ __align__(16) char dyn[];
    __shared__ __align__(16) float sBias[2][64];
    const uint32_t sb = smem_u32(dyn);
    const uint32_t sbias_u32 = smem_u32(&sBias[0][0]);

    const int tid  = threadIdx.x;
    const int lane = tid & 31;
    const int w    = tid >> 5;
    const int b  = blockIdx.y >> 4;
    const int h  = blockIdx.y & 15;
    const int q0 = blockIdx.x * 128;
    const int g = lane >> 2, c = lane & 3;
    const int nt = (clamp_nv(nvp[b]) + 63) >> 6;

    // ---- Phase 1: Q tile (fp16) -> fragments ----
    {
        __half* sQ = (__half*)dyn;
        const __half* gQ = Qf + (size_t)(b * SSQ + q0) * DD + h * DKK;
#pragma unroll
        for (int i = tid; i < 1024; i += 256) {
            int r = i >> 3, c8 = i & 7;
            *(uint4*)&sQ[r * AS + c8 * 8] =
                *(const uint4*)&gQ[(size_t)r * DD + c8 * 8];
        }
    }
    __syncthreads();

    uint32_t qf[4][4];
    {
        const int lrQ = w * 16 + (lane & 15);
        const int lcQ = (lane >> 4) * 8;
#pragma unroll
        for (int kb = 0; kb < 4; kb++) {
            uint32_t off = (lrQ * AS + kb * 16 + lcQ) * 2;
            ldsm4(qf[kb], sb + off);
        }
    }
    __syncthreads();

    float m0 = -INFINITY, m1 = -INFINITY, l0 = 0.0f, l1 = 0.0f;
    float acc[8][4];
#pragma unroll
    for (int on = 0; on < 8; on++)
#pragma unroll
        for (int e = 0; e < 4; e++) acc[on][e] = 0.0f;

    const int lrK = ((lane >> 4) & 1) * 8 + (lane & 7);
    const int lcK = ((lane >> 3) & 1) * 8;
    const int lrV = ((lane >> 3) & 1) * 8 + (lane & 7);
    const int lcV = (lane >> 4) * 8;
    const float scale2 = 0.125f * LOG2E;
    const size_t gKV0 = (size_t)(b * SSQ) * DD + h * DKK;

    if (nt > 0) {
        att_stage_load(sb, Kf, Vf, gKV0, tid);
        if (tid < 16) CP16(sbias_u32 + tid * 16, &cb[b * SSQ + tid * 4]);
        CPCOMMIT();
    }

    for (int t = 0; t < nt; ++t) {
        const int st = t & 1;
        if (t + 1 < nt) {
            att_stage_load(sb + (st ^ 1) * AT_STAGEB, Kf, Vf,
                           gKV0 + (size_t)(t + 1) * 64 * DD, tid);
            if (tid < 16)
                CP16(sbias_u32 + (st ^ 1) * 256 + tid * 16,
                     &cb[b * SSQ + (t + 1) * 64 + tid * 4]);
            CPCOMMIT();
            CPWAIT1();
        } else {
            CPWAIT0();
        }
        __syncthreads();

        const uint32_t bKf = sb + st * AT_STAGEB;
        const uint32_t bVf = bKf + AT_TILEB;

        // ---- S = Q K^T : single fp16 MMA per 16x8 output ----
        float s[8][4];
#pragma unroll
        for (int nj = 0; nj < 8; nj++)
#pragma unroll
            for (int e = 0; e < 4; e++) s[nj][e] = 0.0f;

#pragma unroll
        for (int kb = 0; kb < 4; kb++) {
#pragma unroll
            for (int np = 0; np < 2; np++) {
                uint32_t kf0[4], kf1[4];
                uint32_t off0 = (((np * 2 + 0) * 16 + lrK) * AS + kb * 16 + lcK) * 2;
                uint32_t off1 = (((np * 2 + 1) * 16 + lrK) * AS + kb * 16 + lcK) * 2;
                ldsm4(kf0, bKf + off0);
                ldsm4(kf1, bKf + off1);
                mma16816h(s[np * 4 + 0], qf[kb], kf0[0], kf0[1]);
                mma16816h(s[np * 4 + 1], qf[kb], kf0[2], kf0[3]);
                mma16816h(s[np * 4 + 2], qf[kb], kf1[0], kf1[1]);
                mma16816h(s[np * 4 + 3], qf[kb], kf1[2], kf1[3]);
            }
        }

        // ---- scale + bias (exp2 domain; pad slots get -BIG) ----
#pragma unroll
        for (int nj = 0; nj < 8; nj++) {
            float b0 = sBias[st][nj * 8 + c * 2];
            float b1 = sBias[st][nj * 8 + c * 2 + 1];
            s[nj][0] = fmaf(s[nj][0], scale2, b0);
            s[nj][1] = fmaf(s[nj][1], scale2, b1);
            s[nj][2] = fmaf(s[nj][2], scale2, b0);
            s[nj][3] = fmaf(s[nj][3], scale2, b1);
        }

        // ---- online softmax ----
        float mx0 = -INFINITY, mx1 = -INFINITY;
#pragma unroll
        for (int nj = 0; nj < 8; nj++) {
            mx0 = fmaxf(mx0, fmaxf(s[nj][0], s[nj][1]));
            mx1 = fmaxf(mx1, fmaxf(s[nj][2], s[nj][3]));
        }
        mx0 = fmaxf(mx0, __shfl_xor_sync(0xffffffffu, mx0, 1));
        mx0 = fmaxf(mx0, __shfl_xor_sync(0xffffffffu, mx0, 2));
        mx1 = fmaxf(mx1, __shfl_xor_sync(0xffffffffu, mx1, 1));
        mx1 = fmaxf(mx1, __shfl_xor_sync(0xffffffffu, mx1, 2));
        float mn0 = fmaxf(m0, mx0), mn1 = fmaxf(m1, mx1);
        float f0 = ex2f(m0 - mn0), f1 = ex2f(m1 - mn1);
        m0 = mn0; m1 = mn1;

        float sum0 = 0.0f, sum1 = 0.0f;
#pragma unroll
        for (int nj = 0; nj < 8; nj++) {
            s[nj][0] = ex2f(s[nj][0] - m0);
            s[nj][1] = ex2f(s[nj][1] - m0);
            s[nj][2] = ex2f(s[nj][2] - m1);
            s[nj][3] = ex2f(s[nj][3] - m1);
            sum0 += s[nj][0] + s[nj][1];
            sum1 += s[nj][2] + s[nj][3];
        }
        sum0 += __shfl_xor_sync(0xffffffffu, sum0, 1);
        sum0 += __shfl_xor_sync(0xffffffffu, sum0, 2);
        sum1 += __shfl_xor_sync(0xffffffffu, sum1, 1);
        sum1 += __shfl_xor_sync(0xffffffffu, sum1, 2);
        l0 = l0 * f0 + sum0;
        l1 = l1 * f1 + sum1;
#pragma unroll
        for (int on = 0; on < 8; on++) {
            acc[on][0] *= f0; acc[on][1] *= f0;
            acc[on][2] *= f1; acc[on][3] *= f1;
        }

        // ---- O += P V : single fp16 MMA ----
#pragma unroll
        for (int kb2 = 0; kb2 < 4; kb2++) {
            uint32_t pa[4];
#pragma unroll
            for (int q2 = 0; q2 < 2; q2++) {
                float* sp = s[2 * kb2 + q2];
                pa[q2 * 2]     = bitsh(__float22half2_rn(make_float2(sp[0], sp[1])));
                pa[q2 * 2 + 1] = bitsh(__float22half2_rn(make_float2(sp[2], sp[3])));
            }
#pragma unroll
            for (int op = 0; op < 2; op++) {
                uint32_t vh0[4], vh1[4];
                uint32_t off0 = ((kb2 * 16 + lrV) * AS + (op * 2 + 0) * 16 + lcV) * 2;
                uint32_t off1 = ((kb2 * 16 + lrV) * AS + (op * 2 + 1) * 16 + lcV) * 2;
                ldsm4t(vh0, bVf + off0);
                ldsm4t(vh1, bVf + off1);
                mma16816h(acc[op * 4 + 0], pa, vh0[0], vh0[1]);
                mma16816h(acc[op * 4 + 1], pa, vh0[2], vh0[3]);
                mma16816h(acc[op * 4 + 2], pa, vh1[0], vh1[1]);
                mma16816h(acc[op * 4 + 3], pa, vh1[2], vh1[3]);
            }
        }
        __syncthreads();
    }

    // ---- epilogue: normalize, fp16 store ----
    float inv0 = l0 > 0.f ? 1.0f / l0 : 0.f;
    float inv1 = l1 > 0.f ? 1.0f / l1 : 0.f;
    int rowg = b * SSQ + q0 + w * 16 + g;
#pragma unroll
    for (int on = 0; on < 8; on++) {
        int col = h * DKK + on * 8 + c * 2;
        __half2 o01 = __float22half2_rn(
            make_float2(acc[on][0] * inv0, acc[on][1] * inv0));
        __half2 o23 = __float22half2_rn(
            make_float2(acc[on][2] * inv1, acc[on][3] * inv1));
        *(__half2*)&Of[(size_t)rowg * DD + col] = o01;
        *(__half2*)&Of[(size_t)(rowg + 8) * DD + col] = o23;
    }
}

// ---------------------------------------------------------------------------
// Launch. Index 3 (profiled) = flash_mma_k.
// ---------------------------------------------------------------------------
extern "C" void kernel_launch(void* const* d_in, const int* in_sizes, int n_in,
                              void* d_out, int out_size)
{
    const float* q    = (const float*)d_in[0];
    const float* k    = (const float*)d_in[1];
    const float* v    = (const float*)d_in[2];
    const int*   mask = (const int*)  d_in[3];
    const float* Wq   = (const float*)d_in[4];
    const float* bq   = (const float*)d_in[5];
    const float* Wk   = (const float*)d_in[6];
    const float* bk   = (const float*)d_in[7];
    const float* Wv   = (const float*)d_in[8];
    const float* bv   = (const float*)d_in[9];
    const float* Wo   = (const float*)d_in[10];
    const float* bo   = (const float*)d_in[11];
    float* out = (float*)d_out;

    bf16 *qAh, *qAl, *kAh, *kAl, *vAh, *vAl;
    bf16 *WqH, *WqL, *WkH, *WkL, *WvH, *WvL;
    __half *WoH, *WoL;
    __half *Qf, *Kf, *Vf, *Of;
    float *cb; int *idx, *nv;
    cudaGetSymbolAddress((void**)&qAh, g_qAh); cudaGetSymbolAddress((void**)&qAl, g_qAl);
    cudaGetSymbolAddress((void**)&kAh, g_kAh); cudaGetSymbolAddress((void**)&kAl, g_kAl);
    cudaGetSymbolAddress((void**)&vAh, g_vAh); cudaGetSymbolAddress((void**)&vAl, g_vAl);
    cudaGetSymbolAddress((void**)&WqH, g_WqH); cudaGetSymbolAddress((void**)&WqL, g_WqL);
    cudaGetSymbolAddress((void**)&WkH, g_WkH); cudaGetSymbolAddress((void**)&WkL, g_WkL);
    cudaGetSymbolAddress((void**)&WvH, g_WvH); cudaGetSymbolAddress((void**)&WvL, g_WvL);
    cudaGetSymbolAddress((void**)&WoH, g_WoH); cudaGetSymbolAddress((void**)&WoL, g_WoL);
    cudaGetSymbolAddress((void**)&Qf, g_Qf);
    cudaGetSymbolAddress((void**)&Kf, g_Kf);
    cudaGetSymbolAddress((void**)&Vf, g_Vf);
    cudaGetSymbolAddress((void**)&Of, g_Of);
    cudaGetSymbolAddress((void**)&cb, g_cbias);
    cudaGetSymbolAddress((void**)&idx, g_idx);
    cudaGetSymbolAddress((void**)&nv, g_nv);

    cudaFuncSetAttribute(gemm3_mma,
                         cudaFuncAttributeMaxDynamicSharedMemorySize, GT_SMEM);
    cudaFuncSetAttribute(gemm_out_mma,
                         cudaFuncAttributeMaxDynamicSharedMemorySize, GO_SMEM);
    cudaFuncSetAttribute(flash_mma_k,
                         cudaFuncAttributeMaxDynamicSharedMemorySize, AT_SMEM);

    // 0: mask scan/compaction
    scan_mask_k<<<BB, 512>>>(mask, idx, nv, cb);

    // 1: all splits fused
    SplitArgs sa;
    sa.q = q; sa.k = k; sa.v = v;
    sa.wq = Wq; sa.wk = Wk; sa.wv = Wv; sa.wo = Wo;
    sa.qh = qAh; sa.ql = qAl; sa.kch = kAh; sa.kcl = kAl;
    sa.vch = vAh; sa.vcl = vAl;
    sa.wqh = WqH; sa.wql = WqL; sa.wkh = WkH; sa.wkl = WkL;
    sa.wvh = WvH; sa.wvl = WvL; sa.woh = WoH; sa.wol = WoL;
    sa.idx = idx; sa.nv = nv;
    split_all_k<<<1024, 256>>>(sa);

    // 2: fused QKV projections (fp16 outputs)
    G3Args p;
    p.Ah[0] = qAh; p.Al[0] = qAl; p.Bh[0] = WqH; p.Bl[0] = WqL;
    p.bias[0] = bq; p.Cf[0] = Qf;
    p.Ah[1] = kAh; p.Al[1] = kAl; p.Bh[1] = WkH; p.Bl[1] = WkL;
    p.bias[1] = bk; p.Cf[1] = Kf;
    p.Ah[2] = vAh; p.Al[2] = vAl; p.Bh[2] = WvH; p.Bl[2] = WvL;
    p.bias[2] = bv; p.Cf[2] = Vf;
    p.nv = nv;
    dim3 gg3(DD / 128, MTOT / 128, 3);
    gemm3_mma<<<gg3, 256, GT_SMEM>>>(p);

    // 3: attention over compacted keys (profiled), all-fp16 MMA
    dim3 ga(SSQ / 128, BB * HHD);
    flash_mma_k<<<ga, 256, AT_SMEM>>>(Qf, Kf, Vf, cb, nv, Of);

    // 4: output projection (fp16 x2)
    dim3 gg(DD / 128, MTOT / 128);
    gemm_out_mma<<<gg, 256, GO_SMEM>>>(Of, WoH, WoL, bo, out);
}

// round 15
// speedup vs baseline: 1.4958x; 1.1733x over previous
#include <cuda_runtime.h>
#include <cuda_bf16.h>
#include <cuda_fp16.h>
#include <math.h>
#include <stdint.h>

// Problem dims
#define BB   2
#define SSQ  2048
#define DD   1024
#define HHD  16
#define DKK  64
#define MTOT (BB * SSQ)   // 4096

#define LOG2E 1.44269504f

// ---------------------------------------------------------------------------
// Scratch (__device__ globals; no allocation allowed)
// ---------------------------------------------------------------------------
__device__ __half g_qAf[MTOT * DD];                   // q input (fp16)
__device__ __half g_kAf[MTOT * DD];                   // compacted k input (fp16)
__device__ __half g_vAf[MTOT * DD];                   // compacted v input (fp16)
__device__ __half g_WqH[DD * DD], g_WqL[DD * DD];     // all weights fp16 hi/lo
__device__ __half g_WkH[DD * DD], g_WkL[DD * DD];
__device__ __half g_WvH[DD * DD], g_WvL[DD * DD];
__device__ __half g_WoH[DD * DD], g_WoL[DD * DD];
__device__ __half g_Qf[MTOT * DD];                    // projected Q (fp16)
__device__ __half g_Kf[MTOT * DD];                    // compacted projected K (fp16)
__device__ __half g_Vf[MTOT * DD];                    // compacted projected V (fp16)
__device__ __half g_Of[MTOT * DD];                    // attention output (fp16)
__device__ float g_cbias[MTOT];                       // compacted bias
__device__ int   g_idx[MTOT];                         // compaction permutation
__device__ int   g_nv[BB];                            // valid keys per batch

// ---------------------------------------------------------------------------
// PTX helpers
// ---------------------------------------------------------------------------
__device__ __forceinline__ uint32_t smem_u32(const void* p) {
    uint32_t a;
    asm("{ .reg .u64 t; cvta.to.shared.u64 t, %1; cvt.u32.u64 %0, t; }"
        : "=r"(a) : "l"(p));
    return a;
}
__device__ __forceinline__ void ldsm4(uint32_t r[4], uint32_t a) {
    asm volatile("ldmatrix.sync.aligned.m8n8.x4.shared.b16 {%0,%1,%2,%3}, [%4];"
                 : "=r"(r[0]), "=r"(r[1]), "=r"(r[2]), "=r"(r[3]) : "r"(a));
}
__device__ __forceinline__ void ldsm4t(uint32_t r[4], uint32_t a) {
    asm volatile("ldmatrix.sync.aligned.m8n8.x4.trans.shared.b16 {%0,%1,%2,%3}, [%4];"
                 : "=r"(r[0]), "=r"(r[1]), "=r"(r[2]), "=r"(r[3]) : "r"(a));
}
// fp16 MMA (f32 accumulate)
__device__ __forceinline__ void mma16816h(float* c, const uint32_t* a,
                                          uint32_t b0, uint32_t b1) {
    asm("mma.sync.aligned.m16n8k16.row.col.f32.f16.f16.f32 "
        "{%0,%1,%2,%3}, {%4,%5,%6,%7}, {%8,%9}, {%0,%1,%2,%3};"
        : "+f"(c[0]), "+f"(c[1]), "+f"(c[2]), "+f"(c[3])
        : "r"(a[0]), "r"(a[1]), "r"(a[2]), "r"(a[3]), "r"(b0), "r"(b1));
}
__device__ __forceinline__ uint32_t bitsh(__half2 h) {
    return *reinterpret_cast<uint32_t*>(&h);
}
__device__ __forceinline__ float ex2f(float x) {
    float y;
    asm("ex2.approx.ftz.f32 %0, %1;" : "=f"(y) : "f"(x));
    return y;
}
#define CP16(dst, src) \
    asm volatile("cp.async.cg.shared.global [%0], [%1], 16;" \
                 :: "r"(dst), "l"(src) : "memory")
#define CPCOMMIT() asm volatile("cp.async.commit_group;" ::: "memory")
#define CPWAIT1()  asm volatile("cp.async.wait_group 1;" ::: "memory")
#define CPWAIT0()  asm volatile("cp.async.wait_group 0;" ::: "memory")

__device__ __forceinline__ int clamp_nv(int x) {
    return x < 0 ? 0 : (x > SSQ ? SSQ : x);
}

// ---------------------------------------------------------------------------
// Mask compaction: deterministic (stable) prefix scan, one block per batch.
// ---------------------------------------------------------------------------
__global__ void scan_mask_k(const int* __restrict__ mask, int* __restrict__ idx,
                            int* __restrict__ nv, float* __restrict__ cbias)
{
    __shared__ int warp_sums[16];
    __shared__ int s_nv;
    const int b = blockIdx.x;
    const int tid = threadIdx.x;
    const int lane = tid & 31, wrp = tid >> 5;
    const int base = tid * 4;

    int m[4];
#pragma unroll
    for (int u = 0; u < 4; u++) m[u] = mask[b * SSQ + base + u] != 0;
    int local = m[0] + m[1] + m[2] + m[3];

    int pre = local;
#pragma unroll
    for (int d = 1; d < 32; d <<= 1) {
        int y = __shfl_up_sync(0xffffffffu, pre, d);
        if (lane >= d) pre += y;
    }
    if (lane == 31) warp_sums[wrp] = pre;
    __syncthreads();
    if (wrp == 0) {
        int ws = (lane < 16) ? warp_sums[lane] : 0;
#pragma unroll
        for (int d = 1; d < 16; d <<= 1) {
            int y = __shfl_up_sync(0xffffffffu, ws, d);
            if (lane >= d) ws += y;
        }
        if (lane < 16) warp_sums[lane] = ws;
        if (lane == 15) s_nv = ws;
    }
    __syncthreads();

    int offset = (pre - local) + (wrp > 0 ? warp_sums[wrp - 1] : 0);
#pragma unroll
    for (int u = 0; u < 4; u++) {
        if (m[u] && offset < SSQ) { idx[b * SSQ + offset] = base + u; offset++; }
    }
    const int total = s_nv;
    if (tid == 0) nv[b] = total;
#pragma unroll
    for (int u = 0; u < 4; u++) {
        int j = base + u;
        cbias[b * SSQ + j] = (j < total) ? 0.0f : -1e9f * LOG2E;
    }
}

// ---------------------------------------------------------------------------
// split helpers
// ---------------------------------------------------------------------------
__device__ __forceinline__ void store_h(float4 v, __half* __restrict__ o, int i)
{
    ((__half2*)o)[2 * i + 0] = __float22half2_rn(make_float2(v.x, v.y));
    ((__half2*)o)[2 * i + 1] = __float22half2_rn(make_float2(v.z, v.w));
}

__device__ __forceinline__ void split_store_h(float4 v, __half* __restrict__ hi,
                                              __half* __restrict__ lo, int i)
{
    __half h0 = __float2half_rn(v.x), h1 = __float2half_rn(v.y);
    __half h2 = __float2half_rn(v.z), h3 = __float2half_rn(v.w);
    __half l0 = __float2half_rn(v.x - __half2float(h0));
    __half l1 = __float2half_rn(v.y - __half2float(h1));
    __half l2 = __float2half_rn(v.z - __half2float(h2));
    __half l3 = __float2half_rn(v.w - __half2float(h3));
    ((__half2*)hi)[2 * i + 0] = __half2(h0, h1);
    ((__half2*)hi)[2 * i + 1] = __half2(h2, h3);
    ((__half2*)lo)[2 * i + 0] = __half2(l0, l1);
    ((__half2*)lo)[2 * i + 1] = __half2(l2, l3);
}

// All splits in one kernel:
//   [0, 1M)   : q -> fp16 single
//   [1M, 3M)  : k,v gathered-compacted -> fp16 single (+ zero pad to rnd128)
//   [3M, 4M)  : 4 weight matrices -> fp16 hi/lo
struct SplitArgs {
    const float *q, *k, *v;
    const float *wq, *wk, *wv, *wo;
    __half *qf, *kf, *vf;
    __half *wqh, *wql, *wkh, *wkl, *wvh, *wvl, *woh, *wol;
    const int *idx, *nv;
};

__global__ void split_all_k(SplitArgs a)
{
    const int n4q = MTOT * DD / 4;          // 1M
    const int n4kv = 2 * MTOT * DD / 4;     // 2M
    const int n4w = DD * DD / 4;            // 256K
    const int total = n4q + n4kv + 4 * n4w; // 4M
    int i = blockIdx.x * blockDim.x + threadIdx.x;
    int stride = gridDim.x * blockDim.x;
    for (; i < total; i += stride) {
        if (i < n4q) {
            store_h(((const float4*)a.q)[i], a.qf, i);
            continue;
        }
        if (i < n4q + n4kv) {
            int r = i - n4q;
            int tsel = r >> 20;             // 0=k, 1=v
            int rem = r & ((1 << 20) - 1);
            int b = rem >> 19;
            int loc = rem & ((1 << 19) - 1);
            int row = loc >> 8;
            int c4 = loc & 255;
            int nvb = clamp_nv(a.nv[b]);
            int rnd = (nvb + 127) & ~127;
            if (row >= rnd) continue;
            __half* o = tsel ? a.vf : a.kf;
            int dsti = (b * SSQ + row) * 256 + c4;
            if (row < nvb) {
                const float* src = tsel ? a.v : a.k;
                int srow = a.idx[b * SSQ + row] & (SSQ - 1);
                store_h(((const float4*)src)[(b * SSQ + srow) * 256 + c4], o, dsti);
            } else {
                store_h(make_float4(0.f, 0.f, 0.f, 0.f), o, dsti);
            }
            continue;
        }
        int r = i - n4q - n4kv;
        int wsel = r / n4w;
        int wi = r - wsel * n4w;
        if (wsel == 0)      split_store_h(((const float4*)a.wq)[wi], a.wqh, a.wql, wi);
        else if (wsel == 1) split_store_h(((const float4*)a.wk)[wi], a.wkh, a.wkl, wi);
        else if (wsel == 2) split_store_h(((const float4*)a.wv)[wi], a.wvh, a.wvl, wi);
        else                split_store_h(((const float4*)a.wo)[wi], a.woh, a.wol, wi);
    }
}

// ---------------------------------------------------------------------------
// Unified fp16x2 GEMM mainloop: C = A(fp16) @ [Wh+Wl](fp16)^T
// 128x128 tile, BK=32, 8 warps (4m x 2n), 3-tile stages, cp.async 2-stage.
// ---------------------------------------------------------------------------
#define GS 40
#define GH_TILEB  (128 * GS * 2)      // 10240 B
#define GH_STAGEB (3 * GH_TILEB)      // 30720 B
#define GH_SMEM   (2 * GH_STAGEB)     // 61440 B

__device__ __forceinline__ void gemmh_stage_load(
    uint32_t sbase, const __half* __restrict__ gA,
    const __half* __restrict__ gWh, const __half* __restrict__ gWl,
    int k0, int tid)
{
#pragma unroll
    for (int i = tid; i < 512; i += 256) {
        int r = i >> 2, c4 = i & 3;
        size_t go = (size_t)r * DD + k0 + c4 * 8;
        uint32_t so = (uint32_t)(r * GS + c4 * 8) * 2;
        CP16(sbase + so,                gA + go);
        CP16(sbase + GH_TILEB + so,     gWh + go);
        CP16(sbase + 2 * GH_TILEB + so, gWl + go);
    }
}

__device__ __forceinline__ void gemmh_mainloop(
    uint32_t sb, const __half* gA, const __half* gWh, const __half* gWl,
    int tid, int lane, int wm, int wn, float acc[2][8][4])
{
    const int lrA = wm * 32 + (lane & 15);
    const int lcA = (lane >> 4) * 8;
    const int lrB = wn * 64 + ((lane >> 4) & 1) * 8 + (lane & 7);
    const int lcB = ((lane >> 3) & 1) * 8;

    gemmh_stage_load(sb, gA, gWh, gWl, 0, tid);
    CPCOMMIT();

    for (int t = 0; t < 32; ++t) {
        const int st = t & 1;
        if (t < 31) {
            gemmh_stage_load(sb + (st ^ 1) * GH_STAGEB, gA, gWh, gWl,
                             (t + 1) * 32, tid);
            CPCOMMIT();
            CPWAIT1();
        } else {
            CPWAIT0();
        }
        __syncthreads();

        const uint32_t bA  = sb + st * GH_STAGEB;
        const uint32_t bWh = bA + GH_TILEB;
        const uint32_t bWl = bA + 2 * GH_TILEB;

#pragma unroll
        for (int kb = 0; kb < 2; kb++) {
            uint32_t av[2][4];
#pragma unroll
            for (int mi = 0; mi < 2; mi++) {
                uint32_t off = ((lrA + mi * 16) * GS + kb * 16 + lcA) * 2;
                ldsm4(av[mi], bA + off);
            }
#pragma unroll
            for (int njp = 0; njp < 4; njp++) {
                uint32_t off = ((lrB + njp * 16) * GS + kb * 16 + lcB) * 2;
                uint32_t bh[4], bl[4];
                ldsm4(bh, bWh + off);
                ldsm4(bl, bWl + off);
                float* c00 = acc[0][njp * 2];
                float* c01 = acc[0][njp * 2 + 1];
                float* c10 = acc[1][njp * 2];
                float* c11 = acc[1][njp * 2 + 1];
                mma16816h(c00, av[0], bh[0], bh[1]);
                mma16816h(c10, av[1], bh[0], bh[1]);
                mma16816h(c01, av[0], bh[2], bh[3]);
                mma16816h(c11, av[1], bh[2], bh[3]);
                mma16816h(c00, av[0], bl[0], bl[1]);
                mma16816h(c10, av[1], bl[0], bl[1]);
                mma16816h(c01, av[0], bl[2], bl[3]);
                mma16816h(c11, av[1], bl[2], bl[3]);
            }
        }
        __syncthreads();
    }
}

// Fused QKV projections (fp16 in, fp16 out); K/V (z>0) skip masked-out tiles.
struct G3Args {
    const __half *Af[3], *Wh[3], *Wl[3];
    const float* bias[3];
    __half* Cf[3];
    const int* nv;
};

__global__ __launch_bounds__(256, 2) void gemm3_mma(G3Args p)
{
    extern __shared__ __align__(16) char dyn[];
    const uint32_t sb = smem_u32(dyn);
    const int z = blockIdx.z;
    const int bm = blockIdx.y * 128;
    const int bn = blockIdx.x * 128;

    if (z > 0) {
        int batch = bm >> 11;
        int local = bm & 2047;
        int rnd = (clamp_nv(p.nv[batch]) + 127) & ~127;
        if (local >= rnd) return;
    }

    const int tid  = threadIdx.x;
    const int lane = tid & 31;
    const int warp = tid >> 5;
    const int wm = warp & 3, wn = warp >> 2;

    float acc[2][8][4];
#pragma unroll
    for (int mi = 0; mi < 2; mi++)
#pragma unroll
        for (int nj = 0; nj < 8; nj++)
#pragma unroll
            for (int e = 0; e < 4; e++) acc[mi][nj][e] = 0.0f;

    gemmh_mainloop(sb,
                   p.Af[z] + (size_t)bm * DD,
                   p.Wh[z] + (size_t)bn * DD, p.Wl[z] + (size_t)bn * DD,
                   tid, lane, wm, wn, acc);

    const float* bias = p.bias[z];
    __half* Cf = p.Cf[z];
    const int g = lane >> 2, c = lane & 3;
#pragma unroll
    for (int mi = 0; mi < 2; mi++) {
#pragma unroll
        for (int nj = 0; nj < 8; nj++) {
            int row = bm + wm * 32 + mi * 16 + g;
            int col = bn + wn * 64 + nj * 8 + c * 2;
            float b0 = bias[col], b1 = bias[col + 1];
            __half2 v01 = __float22half2_rn(
                make_float2(acc[mi][nj][0] + b0, acc[mi][nj][1] + b1));
            __half2 v23 = __float22half2_rn(
                make_float2(acc[mi][nj][2] + b0, acc[mi][nj][3] + b1));
            *(__half2*)&Cf[(size_t)row * DD + col] = v01;
            *(__half2*)&Cf[(size_t)(row + 8) * DD + col] = v23;
        }
    }
}

// Output projection (fp16 in, fp32 out)
__global__ __launch_bounds__(256, 2) void gemm_out_mma(
    const __half* __restrict__ Af,
    const __half* __restrict__ Wh, const __half* __restrict__ Wl,
    const float* __restrict__ bias, float* __restrict__ Cf)
{
    extern __shared__ __align__(16) char dyn[];
    const uint32_t sb = smem_u32(dyn);
    const int tid  = threadIdx.x;
    const int lane = tid & 31;
    const int warp = tid >> 5;
    const int wm = warp & 3, wn = warp >> 2;
    const int bm = blockIdx.y * 128;
    const int bn = blockIdx.x * 128;

    float acc[2][8][4];
#pragma unroll
    for (int mi = 0; mi < 2; mi++)
#pragma unroll
        for (int nj = 0; nj < 8; nj++)
#pragma unroll
            for (int e = 0; e < 4; e++) acc[mi][nj][e] = 0.0f;

    gemmh_mainloop(sb,
                   Af + (size_t)bm * DD,
                   Wh + (size_t)bn * DD, Wl + (size_t)bn * DD,
                   tid, lane, wm, wn, acc);

    const int g = lane >> 2, c = lane & 3;
#pragma unroll
    for (int mi = 0; mi < 2; mi++) {
#pragma unroll
        for (int nj = 0; nj < 8; nj++) {
            int row = bm + wm * 32 + mi * 16 + g;
            int col = bn + wn * 64 + nj * 8 + c * 2;
            float b0 = bias[col], b1 = bias[col + 1];
            *(float2*)&Cf[(size_t)row * DD + col] =
                make_float2(acc[mi][nj][0] + b0, acc[mi][nj][1] + b1);
            *(float2*)&Cf[(size_t)(row + 8) * DD + col] =
                make_float2(acc[mi][nj][2] + b0, acc[mi][nj][3] + b1);
        }
    }
}

// ---------------------------------------------------------------------------
// Flash attention over COMPACTED keys (unchanged from R14 winner).
// 256 threads / 8 warps / 128 q-rows per CTA, 2-stage cp.async KV pipeline.
// QK = 1 fp16 MMA, PV = 1 fp16 MMA.  Output fp16.
// ---------------------------------------------------------------------------
#define AS 72
#define AT_TILEB  (64 * AS * 2)
#define AT_STAGEB (2 * AT_TILEB)
#define AT_SMEM   (2 * AT_STAGEB)

__device__ __forceinline__ void att_stage_load(
    uint32_t sbase, const __half* __restrict__ Kf,
    const __half* __restrict__ Vf, size_t gbase, int tid)
{
#pragma unroll
    for (int i = tid; i < 512; i += 256) {
        int r = i >> 3, c8 = i & 7;
        size_t go = gbase + (size_t)r * DD + c8 * 8;
        uint32_t so = (uint32_t)(r * AS + c8 * 8) * 2;
        CP16(sbase + so,            Kf + go);
        CP16(sbase + AT_TILEB + so, Vf + go);
    }
}

__global__ __launch_bounds__(256) void flash_mma_k(
    const __half* __restrict__ Qf,
    const __half* __restrict__ Kf, const __half* __restrict__ Vf,
    const float* __restrict__ cb, const int* __restrict__ nvp,
    __half* __restrict__ Of)
{
    extern __shared__ __align__(16) char dyn[];
    __shared__ __align__(16) float sBias[2][64];
    const uint32_t sb = smem_u32(dyn);
    const uint32_t sbias_u32 = smem_u32(&sBias[0][0]);

    const int tid  = threadIdx.x;
    const int lane = tid & 31;
    const int w    = tid >> 5;
    const int b  = blockIdx.y >> 4;
    const int h  = blockIdx.y & 15;
    const int q0 = blockIdx.x * 128;
    const int g = lane >> 2, c = lane & 3;
    const int nt = (clamp_nv(nvp[b]) + 63) >> 6;

    {
        __half* sQ = (__half*)dyn;
        const __half* gQ = Qf + (size_t)(b * SSQ + q0) * DD + h * DKK;
#pragma unroll
        for (int i = tid; i < 1024; i += 256) {
            int r = i >> 3, c8 = i & 7;
            *(uint4*)&sQ[r * AS + c8 * 8] =
                *(const uint4*)&gQ[(size_t)r * DD + c8 * 8];
        }
    }
    __syncthreads();

    uint32_t qf[4][4];
    {
        const int lrQ = w * 16 + (lane & 15);
        const int lcQ = (lane >> 4) * 8;
#pragma unroll
        for (int kb = 0; kb < 4; kb++) {
            uint32_t off = (lrQ * AS + kb * 16 + lcQ) * 2;
            ldsm4(qf[kb], sb + off);
        }
    }
    __syncthreads();

    float m0 = -INFINITY, m1 = -INFINITY, l0 = 0.0f, l1 = 0.0f;
    float acc[8][4];
#pragma unroll
    for (int on = 0; on < 8; on++)
#pragma unroll
        for (int e = 0; e < 4; e++) acc[on][e] = 0.0f;

    const int lrK = ((lane >> 4) & 1) * 8 + (lane & 7);
    const int lcK = ((lane >> 3) & 1) * 8;
    const int lrV = ((lane >> 3) & 1) * 8 + (lane & 7);
    const int lcV = (lane >> 4) * 8;
    const float scale2 = 0.125f * LOG2E;
    const size_t gKV0 = (size_t)(b * SSQ) * DD + h * DKK;

    if (nt > 0) {
        att_stage_load(sb, Kf, Vf, gKV0, tid);
        if (tid < 16) CP16(sbias_u32 + tid * 16, &cb[b * SSQ + tid * 4]);
        CPCOMMIT();
    }

    for (int t = 0; t < nt; ++t) {
        const int st = t & 1;
        if (t + 1 < nt) {
            att_stage_load(sb + (st ^ 1) * AT_STAGEB, Kf, Vf,
                           gKV0 + (size_t)(t + 1) * 64 * DD, tid);
            if (tid < 16)
                CP16(sbias_u32 + (st ^ 1) * 256 + tid * 16,
                     &cb[b * SSQ + (t + 1) * 64 + tid * 4]);
            CPCOMMIT();
            CPWAIT1();
        } else {
            CPWAIT0();
        }
        __syncthreads();

        const uint32_t bKf = sb + st * AT_STAGEB;
        const uint32_t bVf = bKf + AT_TILEB;

        float s[8][4];
#pragma unroll
        for (int nj = 0; nj < 8; nj++)
#pragma unroll
            for (int e = 0; e < 4; e++) s[nj][e] = 0.0f;

#pragma unroll
        for (int kb = 0; kb < 4; kb++) {
#pragma unroll
            for (int np = 0; np < 2; np++) {
                uint32_t kf0[4], kf1[4];
                uint32_t off0 = (((np * 2 + 0) * 16 + lrK) * AS + kb * 16 + lcK) * 2;
                uint32_t off1 = (((np * 2 + 1) * 16 + lrK) * AS + kb * 16 + lcK) * 2;
                ldsm4(kf0, bKf + off0);
                ldsm4(kf1, bKf + off1);
                mma16816h(s[np * 4 + 0], qf[kb], kf0[0], kf0[1]);
                mma16816h(s[np * 4 + 1], qf[kb], kf0[2], kf0[3]);
                mma16816h(s[np * 4 + 2], qf[kb], kf1[0], kf1[1]);
                mma16816h(s[np * 4 + 3], qf[kb], kf1[2], kf1[3]);
            }
        }

#pragma unroll
        for (int nj = 0; nj < 8; nj++) {
            float b0 = sBias[st][nj * 8 + c * 2];
            float b1 = sBias[st][nj * 8 + c * 2 + 1];
            s[nj][0] = fmaf(s[nj][0], scale2, b0);
            s[nj][1] = fmaf(s[nj][1], scale2, b1);
            s[nj][2] = fmaf(s[nj][2], scale2, b0);
            s[nj][3] = fmaf(s[nj][3], scale2, b1);
        }

        float mx0 = -INFINITY, mx1 = -INFINITY;
#pragma unroll
        for (int nj = 0; nj < 8; nj++) {
            mx0 = fmaxf(mx0, fmaxf(s[nj][0], s[nj][1]));
            mx1 = fmaxf(mx1, fmaxf(s[nj][2], s[nj][3]));
        }
        mx0 = fmaxf(mx0, __shfl_xor_sync(0xffffffffu, mx0, 1));
        mx0 = fmaxf(mx0, __shfl_xor_sync(0xffffffffu, mx0, 2));
        mx1 = fmaxf(mx1, __shfl_xor_sync(0xffffffffu, mx1, 1));
        mx1 = fmaxf(mx1, __shfl_xor_sync(0xffffffffu, mx1, 2));
        float mn0 = fmaxf(m0, mx0), mn1 = fmaxf(m1, mx1);
        float f0 = ex2f(m0 - mn0), f1 = ex2f(m1 - mn1);
        m0 = mn0; m1 = mn1;

        float sum0 = 0.0f, sum1 = 0.0f;
#pragma unroll
        for (int nj = 0; nj < 8; nj++) {
            s[nj][0] = ex2f(s[nj][0] - m0);
            s[nj][1] = ex2f(s[nj][1] - m0);
            s[nj][2] = ex2f(s[nj][2] - m1);
            s[nj][3] = ex2f(s[nj][3] - m1);
            sum0 += s[nj][0] + s[nj][1];
            sum1 += s[nj][2] + s[nj][3];
        }
        sum0 += __shfl_xor_sync(0xffffffffu, sum0, 1);
        sum0 += __shfl_xor_sync(0xffffffffu, sum0, 2);
        sum1 += __shfl_xor_sync(0xffffffffu, sum1, 1);
        sum1 += __shfl_xor_sync(0xffffffffu, sum1, 2);
        l0 = l0 * f0 + sum0;
        l1 = l1 * f1 + sum1;
#pragma unroll
        for (int on = 0; on < 8; on++) {
            acc[on][0] *= f0; acc[on][1] *= f0;
            acc[on][2] *= f1; acc[on][3] *= f1;
        }

#pragma unroll
        for (int kb2 = 0; kb2 < 4; kb2++) {
            uint32_t pa[4];
#pragma unroll
            for (int q2 = 0; q2 < 2; q2++) {
                float* sp = s[2 * kb2 + q2];
                pa[q2 * 2]     = bitsh(__float22half2_rn(make_float2(sp[0], sp[1])));
                pa[q2 * 2 + 1] = bitsh(__float22half2_rn(make_float2(sp[2], sp[3])));
            }
#pragma unroll
            for (int op = 0; op < 2; op++) {
                uint32_t vh0[4], vh1[4];
                uint32_t off0 = ((kb2 * 16 + lrV) * AS + (op * 2 + 0) * 16 + lcV) * 2;
                uint32_t off1 = ((kb2 * 16 + lrV) * AS + (op * 2 + 1) * 16 + lcV) * 2;
                ldsm4t(vh0, bVf + off0);
                ldsm4t(vh1, bVf + off1);
                mma16816h(acc[op * 4 + 0], pa, vh0[0], vh0[1]);
                mma16816h(acc[op * 4 + 1], pa, vh0[2], vh0[3]);
                mma16816h(acc[op * 4 + 2], pa, vh1[0], vh1[1]);
                mma16816h(acc[op * 4 + 3], pa, vh1[2], vh1[3]);
            }
        }
        __syncthreads();
    }

    float inv0 = l0 > 0.f ? 1.0f / l0 : 0.f;
    float inv1 = l1 > 0.f ? 1.0f / l1 : 0.f;
    int rowg = b * SSQ + q0 + w * 16 + g;
#pragma unroll
    for (int on = 0; on < 8; on++) {
        int col = h * DKK + on * 8 + c * 2;
        __half2 o01 = __float22half2_rn(
            make_float2(acc[on][0] * inv0, acc[on][1] * inv0));
        __half2 o23 = __float22half2_rn(
            make_float2(acc[on][2] * inv1, acc[on][3] * inv1));
        *(__half2*)&Of[(size_t)rowg * DD + col] = o01;
        *(__half2*)&Of[(size_t)(rowg + 8) * DD + col] = o23;
    }
}

// ---------------------------------------------------------------------------
// Launch. Index 3 (profiled) = flash_mma_k.
// ---------------------------------------------------------------------------
extern "C" void kernel_launch(void* const* d_in, const int* in_sizes, int n_in,
                              void* d_out, int out_size)
{
    const float* q    = (const float*)d_in[0];
    const float* k    = (const float*)d_in[1];
    const float* v    = (const float*)d_in[2];
    const int*   mask = (const int*)  d_in[3];
    const float* Wq   = (const float*)d_in[4];
    const float* bq   = (const float*)d_in[5];
    const float* Wk   = (const float*)d_in[6];
    const float* bk   = (const float*)d_in[7];
    const float* Wv   = (const float*)d_in[8];
    const float* bv   = (const float*)d_in[9];
    const float* Wo   = (const float*)d_in[10];
    const float* bo   = (const float*)d_in[11];
    float* out = (float*)d_out;

    __half *qAf, *kAf, *vAf;
    __half *WqH, *WqL, *WkH, *WkL, *WvH, *WvL, *WoH, *WoL;
    __half *Qf, *Kf, *Vf, *Of;
    float *cb; int *idx, *nv;
    cudaGetSymbolAddress((void**)&qAf, g_qAf);
    cudaGetSymbolAddress((void**)&kAf, g_kAf);
    cudaGetSymbolAddress((void**)&vAf, g_vAf);
    cudaGetSymbolAddress((void**)&WqH, g_WqH); cudaGetSymbolAddress((void**)&WqL, g_WqL);
    cudaGetSymbolAddress((void**)&WkH, g_WkH); cudaGetSymbolAddress((void**)&WkL, g_WkL);
    cudaGetSymbolAddress((void**)&WvH, g_WvH); cudaGetSymbolAddress((void**)&WvL, g_WvL);
    cudaGetSymbolAddress((void**)&WoH, g_WoH); cudaGetSymbolAddress((void**)&WoL, g_WoL);
    cudaGetSymbolAddress((void**)&Qf, g_Qf);
    cudaGetSymbolAddress((void**)&Kf, g_Kf);
    cudaGetSymbolAddress((void**)&Vf, g_Vf);
    cudaGetSymbolAddress((void**)&Of, g_Of);
    cudaGetSymbolAddress((void**)&cb, g_cbias);
    cudaGetSymbolAddress((void**)&idx, g_idx);
    cudaGetSymbolAddress((void**)&nv, g_nv);

    cudaFuncSetAttribute(gemm3_mma,
                         cudaFuncAttributeMaxDynamicSharedMemorySize, GH_SMEM);
    cudaFuncSetAttribute(gemm_out_mma,
                         cudaFuncAttributeMaxDynamicSharedMemorySize, GH_SMEM);
    cudaFuncSetAttribute(flash_mma_k,
                         cudaFuncAttributeMaxDynamicSharedMemorySize, AT_SMEM);

    // 0: mask scan/compaction
    scan_mask_k<<<BB, 512>>>(mask, idx, nv, cb);

    // 1: all splits fused
    SplitArgs sa;
    sa.q = q; sa.k = k; sa.v = v;
    sa.wq = Wq; sa.wk = Wk; sa.wv = Wv; sa.wo = Wo;
    sa.qf = qAf; sa.kf = kAf; sa.vf = vAf;
    sa.wqh = WqH; sa.wql = WqL; sa.wkh = WkH; sa.wkl = WkL;
    sa.wvh = WvH; sa.wvl = WvL; sa.woh = WoH; sa.wol = WoL;
    sa.idx = idx; sa.nv = nv;
    split_all_k<<<1024, 256>>>(sa);

    // 2: fused QKV projections (fp16 x2)
    G3Args p;
    p.Af[0] = qAf; p.Wh[0] = WqH; p.Wl[0] = WqL; p.bias[0] = bq; p.Cf[0] = Qf;
    p.Af[1] = kAf; p.Wh[1] = WkH; p.Wl[1] = WkL; p.bias[1] = bk; p.Cf[1] = Kf;
    p.Af[2] = vAf; p.Wh[2] = WvH; p.Wl[2] = WvL; p.bias[2] = bv; p.Cf[2] = Vf;
    p.nv = nv;
    dim3 gg3(DD / 128, MTOT / 128, 3);
    gemm3_mma<<<gg3, 256, GH_SMEM>>>(p);

    // 3: attention over compacted keys (profiled), all-fp16 MMA
    dim3 ga(SSQ / 128, BB * HHD);
    flash_mma_k<<<ga, 256, AT_SMEM>>>(Qf, Kf, Vf, cb, nv, Of);

    // 4: output projection (fp16 x2)
    dim3 gg(DD / 128, MTOT / 128);
    gemm_out_mma<<<gg, 256, GH_SMEM>>>(Of, WoH, WoL, bo, out);
}

// round 16
// speedup vs baseline: 1.7906x; 1.1970x over previous
#include <cuda_runtime.h>
#include <cuda_bf16.h>
#include <cuda_fp16.h>
#include <math.h>
#include <stdint.h>

// Problem dims
#define BB   2
#define SSQ  2048
#define DD   1024
#define HHD  16
#define DKK  64
#define MTOT (BB * SSQ)   // 4096

#define LOG2E 1.44269504f

// ---------------------------------------------------------------------------
// Scratch (__device__ globals; no allocation allowed)
// ---------------------------------------------------------------------------
__device__ __half g_qAf[MTOT * DD];                   // q input (fp16)
__device__ __half g_kAf[MTOT * DD];                   // compacted k input (fp16)
__device__ __half g_vAf[MTOT * DD];                   // compacted v input (fp16)
__device__ __half g_WqF[DD * DD];                     // Wq single fp16
__device__ __half g_WkF[DD * DD];                     // Wk single fp16
__device__ __half g_WvF[DD * DD];                     // Wv single fp16
__device__ __half g_WoH[DD * DD], g_WoL[DD * DD];     // Wo fp16 hi/lo (kept)
__device__ __half g_Qf[MTOT * DD];                    // projected Q (fp16)
__device__ __half g_Kf[MTOT * DD];                    // compacted projected K (fp16)
__device__ __half g_Vf[MTOT * DD];                    // compacted projected V (fp16)
__device__ __half g_Of[MTOT * DD];                    // attention output (fp16)
__device__ float g_cbias[MTOT];                       // compacted bias
__device__ int   g_idx[MTOT];                         // compaction permutation
__device__ int   g_nv[BB];                            // valid keys per batch

// ---------------------------------------------------------------------------
// PTX helpers
// ---------------------------------------------------------------------------
__device__ __forceinline__ uint32_t smem_u32(const void* p) {
    uint32_t a;
    asm("{ .reg .u64 t; cvta.to.shared.u64 t, %1; cvt.u32.u64 %0, t; }"
        : "=r"(a) : "l"(p));
    return a;
}
__device__ __forceinline__ void ldsm4(uint32_t r[4], uint32_t a) {
    asm volatile("ldmatrix.sync.aligned.m8n8.x4.shared.b16 {%0,%1,%2,%3}, [%4];"
                 : "=r"(r[0]), "=r"(r[1]), "=r"(r[2]), "=r"(r[3]) : "r"(a));
}
__device__ __forceinline__ void ldsm4t(uint32_t r[4], uint32_t a) {
    asm volatile("ldmatrix.sync.aligned.m8n8.x4.trans.shared.b16 {%0,%1,%2,%3}, [%4];"
                 : "=r"(r[0]), "=r"(r[1]), "=r"(r[2]), "=r"(r[3]) : "r"(a));
}
// fp16 MMA (f32 accumulate)
__device__ __forceinline__ void mma16816h(float* c, const uint32_t* a,
                                          uint32_t b0, uint32_t b1) {
    asm("mma.sync.aligned.m16n8k16.row.col.f32.f16.f16.f32 "
        "{%0,%1,%2,%3}, {%4,%5,%6,%7}, {%8,%9}, {%0,%1,%2,%3};"
        : "+f"(c[0]), "+f"(c[1]), "+f"(c[2]), "+f"(c[3])
        : "r"(a[0]), "r"(a[1]), "r"(a[2]), "r"(a[3]), "r"(b0), "r"(b1));
}
__device__ __forceinline__ uint32_t bitsh(__half2 h) {
    return *reinterpret_cast<uint32_t*>(&h);
}
__device__ __forceinline__ float ex2f(float x) {
    float y;
    asm("ex2.approx.ftz.f32 %0, %1;" : "=f"(y) : "f"(x));
    return y;
}
#define CP16(dst, src) \
    asm volatile("cp.async.cg.shared.global [%0], [%1], 16;" \
                 :: "r"(dst), "l"(src) : "memory")
#define CPCOMMIT() asm volatile("cp.async.commit_group;" ::: "memory")
#define CPWAIT1()  asm volatile("cp.async.wait_group 1;" ::: "memory")
#define CPWAIT0()  asm volatile("cp.async.wait_group 0;" ::: "memory")

__device__ __forceinline__ int clamp_nv(int x) {
    return x < 0 ? 0 : (x > SSQ ? SSQ : x);
}

// ---------------------------------------------------------------------------
// Mask compaction: deterministic (stable) prefix scan, one block per batch.
// ---------------------------------------------------------------------------
__global__ void scan_mask_k(const int* __restrict__ mask, int* __restrict__ idx,
                            int* __restrict__ nv, float* __restrict__ cbias)
{
    __shared__ int warp_sums[16];
    __shared__ int s_nv;
    const int b = blockIdx.x;
    const int tid = threadIdx.x;
    const int lane = tid & 31, wrp = tid >> 5;
    const int base = tid * 4;

    int m[4];
#pragma unroll
    for (int u = 0; u < 4; u++) m[u] = mask[b * SSQ + base + u] != 0;
    int local = m[0] + m[1] + m[2] + m[3];

    int pre = local;
#pragma unroll
    for (int d = 1; d < 32; d <<= 1) {
        int y = __shfl_up_sync(0xffffffffu, pre, d);
        if (lane >= d) pre += y;
    }
    if (lane == 31) warp_sums[wrp] = pre;
    __syncthreads();
    if (wrp == 0) {
        int ws = (lane < 16) ? warp_sums[lane] : 0;
#pragma unroll
        for (int d = 1; d < 16; d <<= 1) {
            int y = __shfl_up_sync(0xffffffffu, ws, d);
            if (lane >= d) ws += y;
        }
        if (lane < 16) warp_sums[lane] = ws;
        if (lane == 15) s_nv = ws;
    }
    __syncthreads();

    int offset = (pre - local) + (wrp > 0 ? warp_sums[wrp - 1] : 0);
#pragma unroll
    for (int u = 0; u < 4; u++) {
        if (m[u] && offset < SSQ) { idx[b * SSQ + offset] = base + u; offset++; }
    }
    const int total = s_nv;
    if (tid == 0) nv[b] = total;
#pragma unroll
    for (int u = 0; u < 4; u++) {
        int j = base + u;
        cbias[b * SSQ + j] = (j < total) ? 0.0f : -1e9f * LOG2E;
    }
}

// ---------------------------------------------------------------------------
// split helpers
// ---------------------------------------------------------------------------
__device__ __forceinline__ void store_h(float4 v, __half* __restrict__ o, int i)
{
    ((__half2*)o)[2 * i + 0] = __float22half2_rn(make_float2(v.x, v.y));
    ((__half2*)o)[2 * i + 1] = __float22half2_rn(make_float2(v.z, v.w));
}

__device__ __forceinline__ void split_store_h(float4 v, __half* __restrict__ hi,
                                              __half* __restrict__ lo, int i)
{
    __half h0 = __float2half_rn(v.x), h1 = __float2half_rn(v.y);
    __half h2 = __float2half_rn(v.z), h3 = __float2half_rn(v.w);
    __half l0 = __float2half_rn(v.x - __half2float(h0));
    __half l1 = __float2half_rn(v.y - __half2float(h1));
    __half l2 = __float2half_rn(v.z - __half2float(h2));
    __half l3 = __float2half_rn(v.w - __half2float(h3));
    ((__half2*)hi)[2 * i + 0] = __half2(h0, h1);
    ((__half2*)hi)[2 * i + 1] = __half2(h2, h3);
    ((__half2*)lo)[2 * i + 0] = __half2(l0, l1);
    ((__half2*)lo)[2 * i + 1] = __half2(l2, l3);
}

// All splits in one kernel:
//   [0, 1M)   : q -> fp16 single
//   [1M, 3M)  : k,v gathered-compacted -> fp16 single (+ zero pad to rnd128)
//   [3M, 4M)  : Wq/Wk/Wv -> fp16 single; Wo -> fp16 hi/lo
struct SplitArgs {
    const float *q, *k, *v;
    const float *wq, *wk, *wv, *wo;
    __half *qf, *kf, *vf;
    __half *wqf, *wkf, *wvf, *woh, *wol;
    const int *idx, *nv;
};

__global__ void split_all_k(SplitArgs a)
{
    const int n4q = MTOT * DD / 4;          // 1M
    const int n4kv = 2 * MTOT * DD / 4;     // 2M
    const int n4w = DD * DD / 4;            // 256K
    const int total = n4q + n4kv + 4 * n4w; // 4M
    int i = blockIdx.x * blockDim.x + threadIdx.x;
    int stride = gridDim.x * blockDim.x;
    for (; i < total; i += stride) {
        if (i < n4q) {
            store_h(((const float4*)a.q)[i], a.qf, i);
            continue;
        }
        if (i < n4q + n4kv) {
            int r = i - n4q;
            int tsel = r >> 20;             // 0=k, 1=v
            int rem = r & ((1 << 20) - 1);
            int b = rem >> 19;
            int loc = rem & ((1 << 19) - 1);
            int row = loc >> 8;
            int c4 = loc & 255;
            int nvb = clamp_nv(a.nv[b]);
            int rnd = (nvb + 127) & ~127;
            if (row >= rnd) continue;
            __half* o = tsel ? a.vf : a.kf;
            int dsti = (b * SSQ + row) * 256 + c4;
            if (row < nvb) {
                const float* src = tsel ? a.v : a.k;
                int srow = a.idx[b * SSQ + row] & (SSQ - 1);
                store_h(((const float4*)src)[(b * SSQ + srow) * 256 + c4], o, dsti);
            } else {
                store_h(make_float4(0.f, 0.f, 0.f, 0.f), o, dsti);
            }
            continue;
        }
        int r = i - n4q - n4kv;
        int wsel = r / n4w;
        int wi = r - wsel * n4w;
        if (wsel == 0)      store_h(((const float4*)a.wq)[wi], a.wqf, wi);
        else if (wsel == 1) store_h(((const float4*)a.wk)[wi], a.wkf, wi);
        else if (wsel == 2) store_h(((const float4*)a.wv)[wi], a.wvf, wi);
        else                split_store_h(((const float4*)a.wo)[wi], a.woh, a.wol, wi);
    }
}

// ---------------------------------------------------------------------------
// Common tile geometry
// ---------------------------------------------------------------------------
#define GS 40
#define GH_TILEB  (128 * GS * 2)      // 10240 B

// ---- fp16 x1 mainloop (gemm3): stages = [A | W], 1 MMA per product --------
#define G1_STAGEB (2 * GH_TILEB)      // 20480 B
#define G1_SMEM   (2 * G1_STAGEB)     // 40960 B

__device__ __forceinline__ void gemm1_stage_load(
    uint32_t sbase, const __half* __restrict__ gA,
    const __half* __restrict__ gW, int k0, int tid)
{
#pragma unroll
    for (int i = tid; i < 512; i += 256) {
        int r = i >> 2, c4 = i & 3;
        size_t go = (size_t)r * DD + k0 + c4 * 8;
        uint32_t so = (uint32_t)(r * GS + c4 * 8) * 2;
        CP16(sbase + so,            gA + go);
        CP16(sbase + GH_TILEB + so, gW + go);
    }
}

__device__ __forceinline__ void gemm1_mainloop(
    uint32_t sb, const __half* gA, const __half* gW,
    int tid, int lane, int wm, int wn, float acc[2][8][4])
{
    const int lrA = wm * 32 + (lane & 15);
    const int lcA = (lane >> 4) * 8;
    const int lrB = wn * 64 + ((lane >> 4) & 1) * 8 + (lane & 7);
    const int lcB = ((lane >> 3) & 1) * 8;

    gemm1_stage_load(sb, gA, gW, 0, tid);
    CPCOMMIT();

    for (int t = 0; t < 32; ++t) {
        const int st = t & 1;
        if (t < 31) {
            gemm1_stage_load(sb + (st ^ 1) * G1_STAGEB, gA, gW, (t + 1) * 32, tid);
            CPCOMMIT();
            CPWAIT1();
        } else {
            CPWAIT0();
        }
        __syncthreads();

        const uint32_t bA = sb + st * G1_STAGEB;
        const uint32_t bW = bA + GH_TILEB;

#pragma unroll
        for (int kb = 0; kb < 2; kb++) {
            uint32_t av[2][4];
#pragma unroll
            for (int mi = 0; mi < 2; mi++) {
                uint32_t off = ((lrA + mi * 16) * GS + kb * 16 + lcA) * 2;
                ldsm4(av[mi], bA + off);
            }
#pragma unroll
            for (int njp = 0; njp < 4; njp++) {
                uint32_t off = ((lrB + njp * 16) * GS + kb * 16 + lcB) * 2;
                uint32_t bw[4];
                ldsm4(bw, bW + off);
                mma16816h(acc[0][njp * 2],     av[0], bw[0], bw[1]);
                mma16816h(acc[1][njp * 2],     av[1], bw[0], bw[1]);
                mma16816h(acc[0][njp * 2 + 1], av[0], bw[2], bw[3]);
                mma16816h(acc[1][njp * 2 + 1], av[1], bw[2], bw[3]);
            }
        }
        __syncthreads();
    }
}

// ---- fp16 x2 mainloop (gemm_out): stages = [A | Wh | Wl] ------------------
#define GO_STAGEB (3 * GH_TILEB)      // 30720 B
#define GO_SMEM   (2 * GO_STAGEB)     // 61440 B

__device__ __forceinline__ void gemm2_stage_load(
    uint32_t sbase, const __half* __restrict__ gA,
    const __half* __restrict__ gWh, const __half* __restrict__ gWl,
    int k0, int tid)
{
#pragma unroll
    for (int i = tid; i < 512; i += 256) {
        int r = i >> 2, c4 = i & 3;
        size_t go = (size_t)r * DD + k0 + c4 * 8;
        uint32_t so = (uint32_t)(r * GS + c4 * 8) * 2;
        CP16(sbase + so,                gA + go);
        CP16(sbase + GH_TILEB + so,     gWh + go);
        CP16(sbase + 2 * GH_TILEB + so, gWl + go);
    }
}

__device__ __forceinline__ void gemm2_mainloop(
    uint32_t sb, const __half* gA, const __half* gWh, const __half* gWl,
    int tid, int lane, int wm, int wn, float acc[2][8][4])
{
    const int lrA = wm * 32 + (lane & 15);
    const int lcA = (lane >> 4) * 8;
    const int lrB = wn * 64 + ((lane >> 4) & 1) * 8 + (lane & 7);
    const int lcB = ((lane >> 3) & 1) * 8;

    gemm2_stage_load(sb, gA, gWh, gWl, 0, tid);
    CPCOMMIT();

    for (int t = 0; t < 32; ++t) {
        const int st = t & 1;
        if (t < 31) {
            gemm2_stage_load(sb + (st ^ 1) * GO_STAGEB, gA, gWh, gWl,
                             (t + 1) * 32, tid);
            CPCOMMIT();
            CPWAIT1();
        } else {
            CPWAIT0();
        }
        __syncthreads();

        const uint32_t bA  = sb + st * GO_STAGEB;
        const uint32_t bWh = bA + GH_TILEB;
        const uint32_t bWl = bA + 2 * GH_TILEB;

#pragma unroll
        for (int kb = 0; kb < 2; kb++) {
            uint32_t av[2][4];
#pragma unroll
            for (int mi = 0; mi < 2; mi++) {
                uint32_t off = ((lrA + mi * 16) * GS + kb * 16 + lcA) * 2;
                ldsm4(av[mi], bA + off);
            }
#pragma unroll
            for (int njp = 0; njp < 4; njp++) {
                uint32_t off = ((lrB + njp * 16) * GS + kb * 16 + lcB) * 2;
                uint32_t bh[4], bl[4];
                ldsm4(bh, bWh + off);
                ldsm4(bl, bWl + off);
                float* c00 = acc[0][njp * 2];
                float* c01 = acc[0][njp * 2 + 1];
                float* c10 = acc[1][njp * 2];
                float* c11 = acc[1][njp * 2 + 1];
                mma16816h(c00, av[0], bh[0], bh[1]);
                mma16816h(c10, av[1], bh[0], bh[1]);
                mma16816h(c01, av[0], bh[2], bh[3]);
                mma16816h(c11, av[1], bh[2], bh[3]);
                mma16816h(c00, av[0], bl[0], bl[1]);
                mma16816h(c10, av[1], bl[0], bl[1]);
                mma16816h(c01, av[0], bl[2], bl[3]);
                mma16816h(c11, av[1], bl[2], bl[3]);
            }
        }
        __syncthreads();
    }
}

// Fused QKV projections (fp16 x1); K/V (z>0) skip masked-out tiles.
struct G3Args {
    const __half *Af[3], *Wf[3];
    const float* bias[3];
    __half* Cf[3];
    const int* nv;
};

__global__ __launch_bounds__(256, 2) void gemm3_mma(G3Args p)
{
    extern __shared__ __align__(16) char dyn[];
    const uint32_t sb = smem_u32(dyn);
    const int z = blockIdx.z;
    const int bm = blockIdx.y * 128;
    const int bn = blockIdx.x * 128;

    if (z > 0) {
        int batch = bm >> 11;
        int local = bm & 2047;
        int rnd = (clamp_nv(p.nv[batch]) + 127) & ~127;
        if (local >= rnd) return;
    }

    const int tid  = threadIdx.x;
    const int lane = tid & 31;
    const int warp = tid >> 5;
    const int wm = warp & 3, wn = warp >> 2;

    float acc[2][8][4];
#pragma unroll
    for (int mi = 0; mi < 2; mi++)
#pragma unroll
        for (int nj = 0; nj < 8; nj++)
#pragma unroll
            for (int e = 0; e < 4; e++) acc[mi][nj][e] = 0.0f;

    gemm1_mainloop(sb,
                   p.Af[z] + (size_t)bm * DD, p.Wf[z] + (size_t)bn * DD,
                   tid, lane, wm, wn, acc);

    const float* bias = p.bias[z];
    __half* Cf = p.Cf[z];
    const int g = lane >> 2, c = lane & 3;
#pragma unroll
    for (int mi = 0; mi < 2; mi++) {
#pragma unroll
        for (int nj = 0; nj < 8; nj++) {
            int row = bm + wm * 32 + mi * 16 + g;
            int col = bn + wn * 64 + nj * 8 + c * 2;
            float b0 = bias[col], b1 = bias[col + 1];
            __half2 v01 = __float22half2_rn(
                make_float2(acc[mi][nj][0] + b0, acc[mi][nj][1] + b1));
            __half2 v23 = __float22half2_rn(
                make_float2(acc[mi][nj][2] + b0, acc[mi][nj][3] + b1));
            *(__half2*)&Cf[(size_t)row * DD + col] = v01;
            *(__half2*)&Cf[(size_t)(row + 8) * DD + col] = v23;
        }
    }
}

// Output projection (fp16 in, Wo hi/lo, fp32 out)
__global__ __launch_bounds__(256, 2) void gemm_out_mma(
    const __half* __restrict__ Af,
    const __half* __restrict__ Wh, const __half* __restrict__ Wl,
    const float* __restrict__ bias, float* __restrict__ Cf)
{
    extern __shared__ __align__(16) char dyn[];
    const uint32_t sb = smem_u32(dyn);
    const int tid  = threadIdx.x;
    const int lane = tid & 31;
    const int warp = tid >> 5;
    const int wm = warp & 3, wn = warp >> 2;
    const int bm = blockIdx.y * 128;
    const int bn = blockIdx.x * 128;

    float acc[2][8][4];
#pragma unroll
    for (int mi = 0; mi < 2; mi++)
#pragma unroll
        for (int nj = 0; nj < 8; nj++)
#pragma unroll
            for (int e = 0; e < 4; e++) acc[mi][nj][e] = 0.0f;

    gemm2_mainloop(sb,
                   Af + (size_t)bm * DD,
                   Wh + (size_t)bn * DD, Wl + (size_t)bn * DD,
                   tid, lane, wm, wn, acc);

    const int g = lane >> 2, c = lane & 3;
#pragma unroll
    for (int mi = 0; mi < 2; mi++) {
#pragma unroll
        for (int nj = 0; nj < 8; nj++) {
            int row = bm + wm * 32 + mi * 16 + g;
            int col = bn + wn * 64 + nj * 8 + c * 2;
            float b0 = bias[col], b1 = bias[col + 1];
            *(float2*)&Cf[(size_t)row * DD + col] =
                make_float2(acc[mi][nj][0] + b0, acc[mi][nj][1] + b1);
            *(float2*)&Cf[(size_t)(row + 8) * DD + col] =
                make_float2(acc[mi][nj][2] + b0, acc[mi][nj][3] + b1);
        }
    }
}

// ---------------------------------------------------------------------------
// Flash attention over COMPACTED keys (unchanged R14/R15 winner).
// ---------------------------------------------------------------------------
#define AS 72
#define AT_TILEB  (64 * AS * 2)
#define AT_STAGEB (2 * AT_TILEB)
#define AT_SMEM   (2 * AT_STAGEB)

__device__ __forceinline__ void att_stage_load(
    uint32_t sbase, const __half* __restrict__ Kf,
    const __half* __restrict__ Vf, size_t gbase, int tid)
{
#pragma unroll
    for (int i = tid; i < 512; i += 256) {
        int r = i >> 3, c8 = i & 7;
        size_t go = gbase + (size_t)r * DD + c8 * 8;
        uint32_t so = (uint32_t)(r * AS + c8 * 8) * 2;
        CP16(sbase + so,            Kf + go);
        CP16(sbase + AT_TILEB + so, Vf + go);
    }
}

__global__ __launch_bounds__(256) void flash_mma_k(
    const __half* __restrict__ Qf,
    const __half* __restrict__ Kf, const __half* __restrict__ Vf,
    const float* __restrict__ cb, const int* __restrict__ nvp,
    __half* __restrict__ Of)
{
    extern __shared__ __align__(16) char dyn[];
    __shared__ __align__(16) float sBias[2][64];
    const uint32_t sb = smem_u32(dyn);
    const uint32_t sbias_u32 = smem_u32(&sBias[0][0]);

    const int tid  = threadIdx.x;
    const int lane = tid & 31;
    const int w    = tid >> 5;
    const int b  = blockIdx.y >> 4;
    const int h  = blockIdx.y & 15;
    const int q0 = blockIdx.x * 128;
    const int g = lane >> 2, c = lane & 3;
    const int nt = (clamp_nv(nvp[b]) + 63) >> 6;

    {
        __half* sQ = (__half*)dyn;
        const __half* gQ = Qf + (size_t)(b * SSQ + q0) * DD + h * DKK;
#pragma unroll
        for (int i = tid; i < 1024; i += 256) {
            int r = i >> 3, c8 = i & 7;
            *(uint4*)&sQ[r * AS + c8 * 8] =
                *(const uint4*)&gQ[(size_t)r * DD + c8 * 8];
        }
    }
    __syncthreads();

    uint32_t qf[4][4];
    {
        const int lrQ = w * 16 + (lane & 15);
        const int lcQ = (lane >> 4) * 8;
#pragma unroll
        for (int kb = 0; kb < 4; kb++) {
            uint32_t off = (lrQ * AS + kb * 16 + lcQ) * 2;
            ldsm4(qf[kb], sb + off);
        }
    }
    __syncthreads();

    float m0 = -INFINITY, m1 = -INFINITY, l0 = 0.0f, l1 = 0.0f;
    float acc[8][4];
#pragma unroll
    for (int on = 0; on < 8; on++)
#pragma unroll
        for (int e = 0; e < 4; e++) acc[on][e] = 0.0f;

    const int lrK = ((lane >> 4) & 1) * 8 + (lane & 7);
    const int lcK = ((lane >> 3) & 1) * 8;
    const int lrV = ((lane >> 3) & 1) * 8 + (lane & 7);
    const int lcV = (lane >> 4) * 8;
    const float scale2 = 0.125f * LOG2E;
    const size_t gKV0 = (size_t)(b * SSQ) * DD + h * DKK;

    if (nt > 0) {
        att_stage_load(sb, Kf, Vf, gKV0, tid);
        if (tid < 16) CP16(sbias_u32 + tid * 16, &cb[b * SSQ + tid * 4]);
        CPCOMMIT();
    }

    for (int t = 0; t < nt; ++t) {
        const int st = t & 1;
        if (t + 1 < nt) {
            att_stage_load(sb + (st ^ 1) * AT_STAGEB, Kf, Vf,
                           gKV0 + (size_t)(t + 1) * 64 * DD, tid);
            if (tid < 16)
                CP16(sbias_u32 + (st ^ 1) * 256 + tid * 16,
                     &cb[b * SSQ + (t + 1) * 64 + tid * 4]);
            CPCOMMIT();
            CPWAIT1();
        } else {
            CPWAIT0();
        }
        __syncthreads();

        const uint32_t bKf = sb + st * AT_STAGEB;
        const uint32_t bVf = bKf + AT_TILEB;

        float s[8][4];
#pragma unroll
        for (int nj = 0; nj < 8; nj++)
#pragma unroll
            for (int e = 0; e < 4; e++) s[nj][e] = 0.0f;

#pragma unroll
        for (int kb = 0; kb < 4; kb++) {
#pragma unroll
            for (int np = 0; np < 2; np++) {
                uint32_t kf0[4], kf1[4];
                uint32_t off0 = (((np * 2 + 0) * 16 + lrK) * AS + kb * 16 + lcK) * 2;
                uint32_t off1 = (((np * 2 + 1) * 16 + lrK) * AS + kb * 16 + lcK) * 2;
                ldsm4(kf0, bKf + off0);
                ldsm4(kf1, bKf + off1);
                mma16816h(s[np * 4 + 0], qf[kb], kf0[0], kf0[1]);
                mma16816h(s[np * 4 + 1], qf[kb], kf0[2], kf0[3]);
                mma16816h(s[np * 4 + 2], qf[kb], kf1[0], kf1[1]);
                mma16816h(s[np * 4 + 3], qf[kb], kf1[2], kf1[3]);
            }
        }

#pragma unroll
        for (int nj = 0; nj < 8; nj++) {
            float b0 = sBias[st][nj * 8 + c * 2];
            float b1 = sBias[st][nj * 8 + c * 2 + 1];
            s[nj][0] = fmaf(s[nj][0], scale2, b0);
            s[nj][1] = fmaf(s[nj][1], scale2, b1);
            s[nj][2] = fmaf(s[nj][2], scale2, b0);
            s[nj][3] = fmaf(s[nj][3], scale2, b1);
        }

        float mx0 = -INFINITY, mx1 = -INFINITY;
#pragma unroll
        for (int nj = 0; nj < 8; nj++) {
            mx0 = fmaxf(mx0, fmaxf(s[nj][0], s[nj][1]));
            mx1 = fmaxf(mx1, fmaxf(s[nj][2], s[nj][3]));
        }
        mx0 = fmaxf(mx0, __shfl_xor_sync(0xffffffffu, mx0, 1));
        mx0 = fmaxf(mx0, __shfl_xor_sync(0xffffffffu, mx0, 2));
        mx1 = fmaxf(mx1, __shfl_xor_sync(0xffffffffu, mx1, 1));
        mx1 = fmaxf(mx1, __shfl_xor_sync(0xffffffffu, mx1, 2));
        float mn0 = fmaxf(m0, mx0), mn1 = fmaxf(m1, mx1);
        float f0 = ex2f(m0 - mn0), f1 = ex2f(m1 - mn1);
        m0 = mn0; m1 = mn1;

        float sum0 = 0.0f, sum1 = 0.0f;
#pragma unroll
        for (int nj = 0; nj < 8; nj++) {
            s[nj][0] = ex2f(s[nj][0] - m0);
            s[nj][1] = ex2f(s[nj][1] - m0);
            s[nj][2] = ex2f(s[nj][2] - m1);
            s[nj][3] = ex2f(s[nj][3] - m1);
            sum0 += s[nj][0] + s[nj][1];
            sum1 += s[nj][2] + s[nj][3];
        }
        sum0 += __shfl_xor_sync(0xffffffffu, sum0, 1);
        sum0 += __shfl_xor_sync(0xffffffffu, sum0, 2);
        sum1 += __shfl_xor_sync(0xffffffffu, sum1, 1);
        sum1 += __shfl_xor_sync(0xffffffffu, sum1, 2);
        l0 = l0 * f0 + sum0;
        l1 = l1 * f1 + sum1;
#pragma unroll
        for (int on = 0; on < 8; on++) {
            acc[on][0] *= f0; acc[on][1] *= f0;
            acc[on][2] *= f1; acc[on][3] *= f1;
        }

#pragma unroll
        for (int kb2 = 0; kb2 < 4; kb2++) {
            uint32_t pa[4];
#pragma unroll
            for (int q2 = 0; q2 < 2; q2++) {
                float* sp = s[2 * kb2 + q2];
                pa[q2 * 2]     = bitsh(__float22half2_rn(make_float2(sp[0], sp[1])));
                pa[q2 * 2 + 1] = bitsh(__float22half2_rn(make_float2(sp[2], sp[3])));
            }
#pragma unroll
            for (int op = 0; op < 2; op++) {
                uint32_t vh0[4], vh1[4];
                uint32_t off0 = ((kb2 * 16 + lrV) * AS + (op * 2 + 0) * 16 + lcV) * 2;
                uint32_t off1 = ((kb2 * 16 + lrV) * AS + (op * 2 + 1) * 16 + lcV) * 2;
                ldsm4t(vh0, bVf + off0);
                ldsm4t(vh1, bVf + off1);
                mma16816h(acc[op * 4 + 0], pa, vh0[0], vh0[1]);
                mma16816h(acc[op * 4 + 1], pa, vh0[2], vh0[3]);
                mma16816h(acc[op * 4 + 2], pa, vh1[0], vh1[1]);
                mma16816h(acc[op * 4 + 3], pa, vh1[2], vh1[3]);
            }
        }
        __syncthreads();
    }

    float inv0 = l0 > 0.f ? 1.0f / l0 : 0.f;
    float inv1 = l1 > 0.f ? 1.0f / l1 : 0.f;
    int rowg = b * SSQ + q0 + w * 16 + g;
#pragma unroll
    for (int on = 0; on < 8; on++) {
        int col = h * DKK + on * 8 + c * 2;
        __half2 o01 = __float22half2_rn(
            make_float2(acc[on][0] * inv0, acc[on][1] * inv0));
        __half2 o23 = __float22half2_rn(
            make_float2(acc[on][2] * inv1, acc[on][3] * inv1));
        *(__half2*)&Of[(size_t)rowg * DD + col] = o01;
        *(__half2*)&Of[(size_t)(rowg + 8) * DD + col] = o23;
    }
}

// ---------------------------------------------------------------------------
// Launch. Index 3 (profiled) = flash_mma_k.
// ---------------------------------------------------------------------------
extern "C" void kernel_launch(void* const* d_in, const int* in_sizes, int n_in,
                              void* d_out, int out_size)
{
    const float* q    = (const float*)d_in[0];
    const float* k    = (const float*)d_in[1];
    const float* v    = (const float*)d_in[2];
    const int*   mask = (const int*)  d_in[3];
    const float* Wq   = (const float*)d_in[4];
    const float* bq   = (const float*)d_in[5];
    const float* Wk   = (const float*)d_in[6];
    const float* bk   = (const float*)d_in[7];
    const float* Wv   = (const float*)d_in[8];
    const float* bv   = (const float*)d_in[9];
    const float* Wo   = (const float*)d_in[10];
    const float* bo   = (const float*)d_in[11];
    float* out = (float*)d_out;

    __half *qAf, *kAf, *vAf;
    __half *WqF, *WkF, *WvF, *WoH, *WoL;
    __half *Qf, *Kf, *Vf, *Of;
    float *cb; int *idx, *nv;
    cudaGetSymbolAddress((void**)&qAf, g_qAf);
    cudaGetSymbolAddress((void**)&kAf, g_kAf);
    cudaGetSymbolAddress((void**)&vAf, g_vAf);
    cudaGetSymbolAddress((void**)&WqF, g_WqF);
    cudaGetSymbolAddress((void**)&WkF, g_WkF);
    cudaGetSymbolAddress((void**)&WvF, g_WvF);
    cudaGetSymbolAddress((void**)&WoH, g_WoH); cudaGetSymbolAddress((void**)&WoL, g_WoL);
    cudaGetSymbolAddress((void**)&Qf, g_Qf);
    cudaGetSymbolAddress((void**)&Kf, g_Kf);
    cudaGetSymbolAddress((void**)&Vf, g_Vf);
    cudaGetSymbolAddress((void**)&Of, g_Of);
    cudaGetSymbolAddress((void**)&cb, g_cbias);
    cudaGetSymbolAddress((void**)&idx, g_idx);
    cudaGetSymbolAddress((void**)&nv, g_nv);

    cudaFuncSetAttribute(gemm3_mma,
                         cudaFuncAttributeMaxDynamicSharedMemorySize, G1_SMEM);
    cudaFuncSetAttribute(gemm_out_mma,
                         cudaFuncAttributeMaxDynamicSharedMemorySize, GO_SMEM);
    cudaFuncSetAttribute(flash_mma_k,
                         cudaFuncAttributeMaxDynamicSharedMemorySize, AT_SMEM);

    // 0: mask scan/compaction
    scan_mask_k<<<BB, 512>>>(mask, idx, nv, cb);

    // 1: all splits fused
    SplitArgs sa;
    sa.q = q; sa.k = k; sa.v = v;
    sa.wq = Wq; sa.wk = Wk; sa.wv = Wv; sa.wo = Wo;
    sa.qf = qAf; sa.kf = kAf; sa.vf = vAf;
    sa.wqf = WqF; sa.wkf = WkF; sa.wvf = WvF;
    sa.woh = WoH; sa.wol = WoL;
    sa.idx = idx; sa.nv = nv;
    split_all_k<<<1024, 256>>>(sa);

    // 2: fused QKV projections (fp16 x1)
    G3Args p;
    p.Af[0] = qAf; p.Wf[0] = WqF; p.bias[0] = bq; p.Cf[0] = Qf;
    p.Af[1] = kAf; p.Wf[1] = WkF; p.bias[1] = bk; p.Cf[1] = Kf;
    p.Af[2] = vAf; p.Wf[2] = WvF; p.bias[2] = bv; p.Cf[2] = Vf;
    p.nv = nv;
    dim3 gg3(DD / 128, MTOT / 128, 3);
    gemm3_mma<<<gg3, 256, G1_SMEM>>>(p);

    // 3: attention over compacted keys (profiled), all-fp16 MMA
    dim3 ga(SSQ / 128, BB * HHD);
    flash_mma_k<<<ga, 256, AT_SMEM>>>(Qf, Kf, Vf, cb, nv, Of);

    // 4: output projection (fp16 x2, Wo hi/lo)
    dim3 gg(DD / 128, MTOT / 128);
    gemm_out_mma<<<gg, 256, GO_SMEM>>>(Of, WoH, WoL, bo, out);
}

// round 17
// speedup vs baseline: 1.9791x; 1.1053x over previous
#include <cuda_runtime.h>
#include <cuda_bf16.h>
#include <cuda_fp16.h>
#include <math.h>
#include <stdint.h>

// Problem dims
#define BB   2
#define SSQ  2048
#define DD   1024
#define HHD  16
#define DKK  64
#define MTOT (BB * SSQ)   // 4096

#define LOG2E 1.44269504f

// ---------------------------------------------------------------------------
// Scratch (__device__ globals; no allocation allowed)
// ---------------------------------------------------------------------------
__device__ __half g_qAf[MTOT * DD];                   // q input (fp16)
__device__ __half g_kAf[MTOT * DD];                   // compacted k input (fp16)
__device__ __half g_vAf[MTOT * DD];                   // compacted v input (fp16)
__device__ __half g_WqF[DD * DD];                     // Wq single fp16
__device__ __half g_WkF[DD * DD];                     // Wk single fp16
__device__ __half g_WvF[DD * DD];                     // Wv single fp16
__device__ __half g_WoF[DD * DD];                     // Wo single fp16
__device__ __half g_Qf[MTOT * DD];                    // projected Q (fp16)
__device__ __half g_Kf[MTOT * DD];                    // compacted projected K (fp16)
__device__ __half g_Vf[MTOT * DD];                    // compacted projected V (fp16)
__device__ __half g_Of[MTOT * DD];                    // attention output (fp16)
__device__ float g_cbias[MTOT];                       // compacted bias
__device__ int   g_idx[MTOT];                         // compaction permutation
__device__ int   g_nv[BB];                            // valid keys per batch

// ---------------------------------------------------------------------------
// PTX helpers
// ---------------------------------------------------------------------------
__device__ __forceinline__ uint32_t smem_u32(const void* p) {
    uint32_t a;
    asm("{ .reg .u64 t; cvta.to.shared.u64 t, %1; cvt.u32.u64 %0, t; }"
        : "=r"(a) : "l"(p));
    return a;
}
__device__ __forceinline__ void ldsm4(uint32_t r[4], uint32_t a) {
    asm volatile("ldmatrix.sync.aligned.m8n8.x4.shared.b16 {%0,%1,%2,%3}, [%4];"
                 : "=r"(r[0]), "=r"(r[1]), "=r"(r[2]), "=r"(r[3]) : "r"(a));
}
__device__ __forceinline__ void ldsm4t(uint32_t r[4], uint32_t a) {
    asm volatile("ldmatrix.sync.aligned.m8n8.x4.trans.shared.b16 {%0,%1,%2,%3}, [%4];"
                 : "=r"(r[0]), "=r"(r[1]), "=r"(r[2]), "=r"(r[3]) : "r"(a));
}
// fp16 MMA (f32 accumulate)
__device__ __forceinline__ void mma16816h(float* c, const uint32_t* a,
                                          uint32_t b0, uint32_t b1) {
    asm("mma.sync.aligned.m16n8k16.row.col.f32.f16.f16.f32 "
        "{%0,%1,%2,%3}, {%4,%5,%6,%7}, {%8,%9}, {%0,%1,%2,%3};"
        : "+f"(c[0]), "+f"(c[1]), "+f"(c[2]), "+f"(c[3])
        : "r"(a[0]), "r"(a[1]), "r"(a[2]), "r"(a[3]), "r"(b0), "r"(b1));
}
__device__ __forceinline__ uint32_t bitsh(__half2 h) {
    return *reinterpret_cast<uint32_t*>(&h);
}
__device__ __forceinline__ float ex2f(float x) {
    float y;
    asm("ex2.approx.ftz.f32 %0, %1;" : "=f"(y) : "f"(x));
    return y;
}
#define CP16(dst, src) \
    asm volatile("cp.async.cg.shared.global [%0], [%1], 16;" \
                 :: "r"(dst), "l"(src) : "memory")
#define CPCOMMIT() asm volatile("cp.async.commit_group;" ::: "memory")
#define CPWAIT1()  asm volatile("cp.async.wait_group 1;" ::: "memory")
#define CPWAIT0()  asm volatile("cp.async.wait_group 0;" ::: "memory")

__device__ __forceinline__ int clamp_nv(int x) {
    return x < 0 ? 0 : (x > SSQ ? SSQ : x);
}

// ---------------------------------------------------------------------------
// Mask compaction: deterministic (stable) prefix scan, one block per batch.
// ---------------------------------------------------------------------------
__global__ void scan_mask_k(const int* __restrict__ mask, int* __restrict__ idx,
                            int* __restrict__ nv, float* __restrict__ cbias)
{
    __shared__ int warp_sums[16];
    __shared__ int s_nv;
    const int b = blockIdx.x;
    const int tid = threadIdx.x;
    const int lane = tid & 31, wrp = tid >> 5;
    const int base = tid * 4;

    int m[4];
#pragma unroll
    for (int u = 0; u < 4; u++) m[u] = mask[b * SSQ + base + u] != 0;
    int local = m[0] + m[1] + m[2] + m[3];

    int pre = local;
#pragma unroll
    for (int d = 1; d < 32; d <<= 1) {
        int y = __shfl_up_sync(0xffffffffu, pre, d);
        if (lane >= d) pre += y;
    }
    if (lane == 31) warp_sums[wrp] = pre;
    __syncthreads();
    if (wrp == 0) {
        int ws = (lane < 16) ? warp_sums[lane] : 0;
#pragma unroll
        for (int d = 1; d < 16; d <<= 1) {
            int y = __shfl_up_sync(0xffffffffu, ws, d);
            if (lane >= d) ws += y;
        }
        if (lane < 16) warp_sums[lane] = ws;
        if (lane == 15) s_nv = ws;
    }
    __syncthreads();

    int offset = (pre - local) + (wrp > 0 ? warp_sums[wrp - 1] : 0);
#pragma unroll
    for (int u = 0; u < 4; u++) {
        if (m[u] && offset < SSQ) { idx[b * SSQ + offset] = base + u; offset++; }
    }
    const int total = s_nv;
    if (tid == 0) nv[b] = total;
#pragma unroll
    for (int u = 0; u < 4; u++) {
        int j = base + u;
        cbias[b * SSQ + j] = (j < total) ? 0.0f : -1e9f * LOG2E;
    }
}

// ---------------------------------------------------------------------------
// split helpers
// ---------------------------------------------------------------------------
__device__ __forceinline__ void store_h(float4 v, __half* __restrict__ o, int i)
{
    ((__half2*)o)[2 * i + 0] = __float22half2_rn(make_float2(v.x, v.y));
    ((__half2*)o)[2 * i + 1] = __float22half2_rn(make_float2(v.z, v.w));
}

// All splits in one kernel:
//   [0, 1M)   : q -> fp16 single
//   [1M, 3M)  : k,v gathered-compacted -> fp16 single (+ zero pad to rnd128)
//   [3M, 4M)  : Wq/Wk/Wv/Wo -> fp16 single
struct SplitArgs {
    const float *q, *k, *v;
    const float *wq, *wk, *wv, *wo;
    __half *qf, *kf, *vf;
    __half *wqf, *wkf, *wvf, *wof;
    const int *idx, *nv;
};

__global__ void split_all_k(SplitArgs a)
{
    const int n4q = MTOT * DD / 4;          // 1M
    const int n4kv = 2 * MTOT * DD / 4;     // 2M
    const int n4w = DD * DD / 4;            // 256K
    const int total = n4q + n4kv + 4 * n4w; // 4M
    int i = blockIdx.x * blockDim.x + threadIdx.x;
    int stride = gridDim.x * blockDim.x;
    for (; i < total; i += stride) {
        if (i < n4q) {
            store_h(((const float4*)a.q)[i], a.qf, i);
            continue;
        }
        if (i < n4q + n4kv) {
            int r = i - n4q;
            int tsel = r >> 20;             // 0=k, 1=v
            int rem = r & ((1 << 20) - 1);
            int b = rem >> 19;
            int loc = rem & ((1 << 19) - 1);
            int row = loc >> 8;
            int c4 = loc & 255;
            int nvb = clamp_nv(a.nv[b]);
            int rnd = (nvb + 127) & ~127;
            if (row >= rnd) continue;
            __half* o = tsel ? a.vf : a.kf;
            int dsti = (b * SSQ + row) * 256 + c4;
            if (row < nvb) {
                const float* src = tsel ? a.v : a.k;
                int srow = a.idx[b * SSQ + row] & (SSQ - 1);
                store_h(((const float4*)src)[(b * SSQ + srow) * 256 + c4], o, dsti);
            } else {
                store_h(make_float4(0.f, 0.f, 0.f, 0.f), o, dsti);
            }
            continue;
        }
        int r = i - n4q - n4kv;
        int wsel = r / n4w;
        int wi = r - wsel * n4w;
        if (wsel == 0)      store_h(((const float4*)a.wq)[wi], a.wqf, wi);
        else if (wsel == 1) store_h(((const float4*)a.wk)[wi], a.wkf, wi);
        else if (wsel == 2) store_h(((const float4*)a.wv)[wi], a.wvf, wi);
        else                store_h(((const float4*)a.wo)[wi], a.wof, wi);
    }
}

// ---------------------------------------------------------------------------
// fp16 x1 GEMM mainloop: 128x128 tile, BK=32, 8 warps, 2-tile stages.
// ---------------------------------------------------------------------------
#define GS 40
#define GH_TILEB  (128 * GS * 2)      // 10240 B
#define G1_STAGEB (2 * GH_TILEB)      // 20480 B
#define G1_SMEM   (2 * G1_STAGEB)     // 40960 B

__device__ __forceinline__ void gemm1_stage_load(
    uint32_t sbase, const __half* __restrict__ gA,
    const __half* __restrict__ gW, int k0, int tid)
{
#pragma unroll
    for (int i = tid; i < 512; i += 256) {
        int r = i >> 2, c4 = i & 3;
        size_t go = (size_t)r * DD + k0 + c4 * 8;
        uint32_t so = (uint32_t)(r * GS + c4 * 8) * 2;
        CP16(sbase + so,            gA + go);
        CP16(sbase + GH_TILEB + so, gW + go);
    }
}

__device__ __forceinline__ void gemm1_mainloop(
    uint32_t sb, const __half* gA, const __half* gW,
    int tid, int lane, int wm, int wn, float acc[2][8][4])
{
    const int lrA = wm * 32 + (lane & 15);
    const int lcA = (lane >> 4) * 8;
    const int lrB = wn * 64 + ((lane >> 4) & 1) * 8 + (lane & 7);
    const int lcB = ((lane >> 3) & 1) * 8;

    gemm1_stage_load(sb, gA, gW, 0, tid);
    CPCOMMIT();

    for (int t = 0; t < 32; ++t) {
        const int st = t & 1;
        if (t < 31) {
            gemm1_stage_load(sb + (st ^ 1) * G1_STAGEB, gA, gW, (t + 1) * 32, tid);
            CPCOMMIT();
            CPWAIT1();
        } else {
            CPWAIT0();
        }
        __syncthreads();

        const uint32_t bA = sb + st * G1_STAGEB;
        const uint32_t bW = bA + GH_TILEB;

#pragma unroll
        for (int kb = 0; kb < 2; kb++) {
            uint32_t av[2][4];
#pragma unroll
            for (int mi = 0; mi < 2; mi++) {
                uint32_t off = ((lrA + mi * 16) * GS + kb * 16 + lcA) * 2;
                ldsm4(av[mi], bA + off);
            }
#pragma unroll
            for (int njp = 0; njp < 4; njp++) {
                uint32_t off = ((lrB + njp * 16) * GS + kb * 16 + lcB) * 2;
                uint32_t bw[4];
                ldsm4(bw, bW + off);
                mma16816h(acc[0][njp * 2],     av[0], bw[0], bw[1]);
                mma16816h(acc[1][njp * 2],     av[1], bw[0], bw[1]);
                mma16816h(acc[0][njp * 2 + 1], av[0], bw[2], bw[3]);
                mma16816h(acc[1][njp * 2 + 1], av[1], bw[2], bw[3]);
            }
        }
        __syncthreads();
    }
}

// Fused QKV projections (fp16 x1); K/V (z>0) skip masked-out tiles.
struct G3Args {
    const __half *Af[3], *Wf[3];
    const float* bias[3];
    __half* Cf[3];
    const int* nv;
};

__global__ __launch_bounds__(256, 2) void gemm3_mma(G3Args p)
{
    extern __shared__ __align__(16) char dyn[];
    const uint32_t sb = smem_u32(dyn);
    const int z = blockIdx.z;
    const int bm = blockIdx.y * 128;
    const int bn = blockIdx.x * 128;

    if (z > 0) {
        int batch = bm >> 11;
        int local = bm & 2047;
        int rnd = (clamp_nv(p.nv[batch]) + 127) & ~127;
        if (local >= rnd) return;
    }

    const int tid  = threadIdx.x;
    const int lane = tid & 31;
    const int warp = tid >> 5;
    const int wm = warp & 3, wn = warp >> 2;

    float acc[2][8][4];
#pragma unroll
    for (int mi = 0; mi < 2; mi++)
#pragma unroll
        for (int nj = 0; nj < 8; nj++)
#pragma unroll
            for (int e = 0; e < 4; e++) acc[mi][nj][e] = 0.0f;

    gemm1_mainloop(sb,
                   p.Af[z] + (size_t)bm * DD, p.Wf[z] + (size_t)bn * DD,
                   tid, lane, wm, wn, acc);

    const float* bias = p.bias[z];
    __half* Cf = p.Cf[z];
    const int g = lane >> 2, c = lane & 3;
#pragma unroll
    for (int mi = 0; mi < 2; mi++) {
#pragma unroll
        for (int nj = 0; nj < 8; nj++) {
            int row = bm + wm * 32 + mi * 16 + g;
            int col = bn + wn * 64 + nj * 8 + c * 2;
            float b0 = bias[col], b1 = bias[col + 1];
            __half2 v01 = __float22half2_rn(
                make_float2(acc[mi][nj][0] + b0, acc[mi][nj][1] + b1));
            __half2 v23 = __float22half2_rn(
                make_float2(acc[mi][nj][2] + b0, acc[mi][nj][3] + b1));
            *(__half2*)&Cf[(size_t)row * DD + col] = v01;
            *(__half2*)&Cf[(size_t)(row + 8) * DD + col] = v23;
        }
    }
}

// Output projection (fp16 x1, fp32 out)
__global__ __launch_bounds__(256, 2) void gemm_out_mma(
    const __half* __restrict__ Af, const __half* __restrict__ Wf,
    const float* __restrict__ bias, float* __restrict__ Cf)
{
    extern __shared__ __align__(16) char dyn[];
    const uint32_t sb = smem_u32(dyn);
    const int tid  = threadIdx.x;
    const int lane = tid & 31;
    const int warp = tid >> 5;
    const int wm = warp & 3, wn = warp >> 2;
    const int bm = blockIdx.y * 128;
    const int bn = blockIdx.x * 128;

    float acc[2][8][4];
#pragma unroll
    for (int mi = 0; mi < 2; mi++)
#pragma unroll
        for (int nj = 0; nj < 8; nj++)
#pragma unroll
            for (int e = 0; e < 4; e++) acc[mi][nj][e] = 0.0f;

    gemm1_mainloop(sb,
                   Af + (size_t)bm * DD, Wf + (size_t)bn * DD,
                   tid, lane, wm, wn, acc);

    const int g = lane >> 2, c = lane & 3;
#pragma unroll
    for (int mi = 0; mi < 2; mi++) {
#pragma unroll
        for (int nj = 0; nj < 8; nj++) {
            int row = bm + wm * 32 + mi * 16 + g;
            int col = bn + wn * 64 + nj * 8 + c * 2;
            float b0 = bias[col], b1 = bias[col + 1];
            *(float2*)&Cf[(size_t)row * DD + col] =
                make_float2(acc[mi][nj][0] + b0, acc[mi][nj][1] + b1);
            *(float2*)&Cf[(size_t)(row + 8) * DD + col] =
                make_float2(acc[mi][nj][2] + b0, acc[mi][nj][3] + b1);
        }
    }
}

// ---------------------------------------------------------------------------
// Flash attention over COMPACTED keys (R14-16 geometry; bias only last tile).
// ---------------------------------------------------------------------------
#define AS 72
#define AT_TILEB  (64 * AS * 2)
#define AT_STAGEB (2 * AT_TILEB)
#define AT_SMEM   (2 * AT_STAGEB)

__device__ __forceinline__ void att_stage_load(
    uint32_t sbase, const __half* __restrict__ Kf,
    const __half* __restrict__ Vf, size_t gbase, int tid)
{
#pragma unroll
    for (int i = tid; i < 512; i += 256) {
        int r = i >> 3, c8 = i & 7;
        size_t go = gbase + (size_t)r * DD + c8 * 8;
        uint32_t so = (uint32_t)(r * AS + c8 * 8) * 2;
        CP16(sbase + so,            Kf + go);
        CP16(sbase + AT_TILEB + so, Vf + go);
    }
}

__global__ __launch_bounds__(256) void flash_mma_k(
    const __half* __restrict__ Qf,
    const __half* __restrict__ Kf, const __half* __restrict__ Vf,
    const float* __restrict__ cb, const int* __restrict__ nvp,
    __half* __restrict__ Of)
{
    extern __shared__ __align__(16) char dyn[];
    __shared__ __align__(16) float sBias[2][64];
    const uint32_t sb = smem_u32(dyn);
    const uint32_t sbias_u32 = smem_u32(&sBias[0][0]);

    const int tid  = threadIdx.x;
    const int lane = tid & 31;
    const int w    = tid >> 5;
    const int b  = blockIdx.y >> 4;
    const int h  = blockIdx.y & 15;
    const int q0 = blockIdx.x * 128;
    const int g = lane >> 2, c = lane & 3;
    const int nt = (clamp_nv(nvp[b]) + 63) >> 6;

    {
        __half* sQ = (__half*)dyn;
        const __half* gQ = Qf + (size_t)(b * SSQ + q0) * DD + h * DKK;
#pragma unroll
        for (int i = tid; i < 1024; i += 256) {
            int r = i >> 3, c8 = i & 7;
            *(uint4*)&sQ[r * AS + c8 * 8] =
                *(const uint4*)&gQ[(size_t)r * DD + c8 * 8];
        }
    }
    __syncthreads();

    uint32_t qf[4][4];
    {
        const int lrQ = w * 16 + (lane & 15);
        const int lcQ = (lane >> 4) * 8;
#pragma unroll
        for (int kb = 0; kb < 4; kb++) {
            uint32_t off = (lrQ * AS + kb * 16 + lcQ) * 2;
            ldsm4(qf[kb], sb + off);
        }
    }
    __syncthreads();

    float m0 = -INFINITY, m1 = -INFINITY, l0 = 0.0f, l1 = 0.0f;
    float acc[8][4];
#pragma unroll
    for (int on = 0; on < 8; on++)
#pragma unroll
        for (int e = 0; e < 4; e++) acc[on][e] = 0.0f;

    const int lrK = ((lane >> 4) & 1) * 8 + (lane & 7);
    const int lcK = ((lane >> 3) & 1) * 8;
    const int lrV = ((lane >> 3) & 1) * 8 + (lane & 7);
    const int lcV = (lane >> 4) * 8;
    const float scale2 = 0.125f * LOG2E;
    const size_t gKV0 = (size_t)(b * SSQ) * DD + h * DKK;

    if (nt > 0) {
        att_stage_load(sb, Kf, Vf, gKV0, tid);
        if (tid < 16) CP16(sbias_u32 + tid * 16, &cb[b * SSQ + tid * 4]);
        CPCOMMIT();
    }

    for (int t = 0; t < nt; ++t) {
        const int st = t & 1;
        if (t + 1 < nt) {
            att_stage_load(sb + (st ^ 1) * AT_STAGEB, Kf, Vf,
                           gKV0 + (size_t)(t + 1) * 64 * DD, tid);
            if (tid < 16)
                CP16(sbias_u32 + (st ^ 1) * 256 + tid * 16,
                     &cb[b * SSQ + (t + 1) * 64 + tid * 4]);
            CPCOMMIT();
            CPWAIT1();
        } else {
            CPWAIT0();
        }
        __syncthreads();

        const uint32_t bKf = sb + st * AT_STAGEB;
        const uint32_t bVf = bKf + AT_TILEB;

        float s[8][4];
#pragma unroll
        for (int nj = 0; nj < 8; nj++)
#pragma unroll
            for (int e = 0; e < 4; e++) s[nj][e] = 0.0f;

#pragma unroll
        for (int kb = 0; kb < 4; kb++) {
#pragma unroll
            for (int np = 0; np < 2; np++) {
                uint32_t kf0[4], kf1[4];
                uint32_t off0 = (((np * 2 + 0) * 16 + lrK) * AS + kb * 16 + lcK) * 2;
                uint32_t off1 = (((np * 2 + 1) * 16 + lrK) * AS + kb * 16 + lcK) * 2;
                ldsm4(kf0, bKf + off0);
                ldsm4(kf1, bKf + off1);
                mma16816h(s[np * 4 + 0], qf[kb], kf0[0], kf0[1]);
                mma16816h(s[np * 4 + 1], qf[kb], kf0[2], kf0[3]);
                mma16816h(s[np * 4 + 2], qf[kb], kf1[0], kf1[1]);
                mma16816h(s[np * 4 + 3], qf[kb], kf1[2], kf1[3]);
            }
        }

        // scale (+ bias only on the last tile, where pad slots live)
        if (t + 1 == nt) {
#pragma unroll
            for (int nj = 0; nj < 8; nj++) {
                float b0 = sBias[st][nj * 8 + c * 2];
                float b1 = sBias[st][nj * 8 + c * 2 + 1];
                s[nj][0] = fmaf(s[nj][0], scale2, b0);
                s[nj][1] = fmaf(s[nj][1], scale2, b1);
                s[nj][2] = fmaf(s[nj][2], scale2, b0);
                s[nj][3] = fmaf(s[nj][3], scale2, b1);
            }
        } else {
#pragma unroll
            for (int nj = 0; nj < 8; nj++) {
                s[nj][0] *= scale2;
                s[nj][1] *= scale2;
                s[nj][2] *= scale2;
                s[nj][3] *= scale2;
            }
        }

        float mx0 = -INFINITY, mx1 = -INFINITY;
#pragma unroll
        for (int nj = 0; nj < 8; nj++) {
            mx0 = fmaxf(mx0, fmaxf(s[nj][0], s[nj][1]));
            mx1 = fmaxf(mx1, fmaxf(s[nj][2], s[nj][3]));
        }
        mx0 = fmaxf(mx0, __shfl_xor_sync(0xffffffffu, mx0, 1));
        mx0 = fmaxf(mx0, __shfl_xor_sync(0xffffffffu, mx0, 2));
        mx1 = fmaxf(mx1, __shfl_xor_sync(0xffffffffu, mx1, 1));
        mx1 = fmaxf(mx1, __shfl_xor_sync(0xffffffffu, mx1, 2));
        float mn0 = fmaxf(m0, mx0), mn1 = fmaxf(m1, mx1);
        float f0 = ex2f(m0 - mn0), f1 = ex2f(m1 - mn1);
        m0 = mn0; m1 = mn1;

        float sum0 = 0.0f, sum1 = 0.0f;
#pragma unroll
        for (int nj = 0; nj < 8; nj++) {
            s[nj][0] = ex2f(s[nj][0] - m0);
            s[nj][1] = ex2f(s[nj][1] - m0);
            s[nj][2] = ex2f(s[nj][2] - m1);
            s[nj][3] = ex2f(s[nj][3] - m1);
            sum0 += s[nj][0] + s[nj][1];
            sum1 += s[nj][2] + s[nj][3];
        }
        sum0 += __shfl_xor_sync(0xffffffffu, sum0, 1);
        sum0 += __shfl_xor_sync(0xffffffffu, sum0, 2);
        sum1 += __shfl_xor_sync(0xffffffffu, sum1, 1);
        sum1 += __shfl_xor_sync(0xffffffffu, sum1, 2);
        l0 = l0 * f0 + sum0;
        l1 = l1 * f1 + sum1;
#pragma unroll
        for (int on = 0; on < 8; on++) {
            acc[on][0] *= f0; acc[on][1] *= f0;
            acc[on][2] *= f1; acc[on][3] *= f1;
        }

#pragma unroll
        for (int kb2 = 0; kb2 < 4; kb2++) {
            uint32_t pa[4];
#pragma unroll
            for (int q2 = 0; q2 < 2; q2++) {
                float* sp = s[2 * kb2 + q2];
                pa[q2 * 2]     = bitsh(__float22half2_rn(make_float2(sp[0], sp[1])));
                pa[q2 * 2 + 1] = bitsh(__float22half2_rn(make_float2(sp[2], sp[3])));
            }
#pragma unroll
            for (int op = 0; op < 2; op++) {
                uint32_t vh0[4], vh1[4];
                uint32_t off0 = ((kb2 * 16 + lrV) * AS + (op * 2 + 0) * 16 + lcV) * 2;
                uint32_t off1 = ((kb2 * 16 + lrV) * AS + (op * 2 + 1) * 16 + lcV) * 2;
                ldsm4t(vh0, bVf + off0);
                ldsm4t(vh1, bVf + off1);
                mma16816h(acc[op * 4 + 0], pa, vh0[0], vh0[1]);
                mma16816h(acc[op * 4 + 1], pa, vh0[2], vh0[3]);
                mma16816h(acc[op * 4 + 2], pa, vh1[0], vh1[1]);
                mma16816h(acc[op * 4 + 3], pa, vh1[2], vh1[3]);
            }
        }
        __syncthreads();
    }

    float inv0 = l0 > 0.f ? 1.0f / l0 : 0.f;
    float inv1 = l1 > 0.f ? 1.0f / l1 : 0.f;
    int rowg = b * SSQ + q0 + w * 16 + g;
#pragma unroll
    for (int on = 0; on < 8; on++) {
        int col = h * DKK + on * 8 + c * 2;
        __half2 o01 = __float22half2_rn(
            make_float2(acc[on][0] * inv0, acc[on][1] * inv0));
        __half2 o23 = __float22half2_rn(
            make_float2(acc[on][2] * inv1, acc[on][3] * inv1));
        *(__half2*)&Of[(size_t)rowg * DD + col] = o01;
        *(__half2*)&Of[(size_t)(rowg + 8) * DD + col] = o23;
    }
}

// ---------------------------------------------------------------------------
// Launch. Index 3 (profiled) = flash_mma_k.
// ---------------------------------------------------------------------------
extern "C" void kernel_launch(void* const* d_in, const int* in_sizes, int n_in,
                              void* d_out, int out_size)
{
    const float* q    = (const float*)d_in[0];
    const float* k    = (const float*)d_in[1];
    const float* v    = (const float*)d_in[2];
    const int*   mask = (const int*)  d_in[3];
    const float* Wq   = (const float*)d_in[4];
    const float* bq   = (const float*)d_in[5];
    const float* Wk   = (const float*)d_in[6];
    const float* bk   = (const float*)d_in[7];
    const float* Wv   = (const float*)d_in[8];
    const float* bv   = (const float*)d_in[9];
    const float* Wo   = (const float*)d_in[10];
    const float* bo   = (const float*)d_in[11];
    float* out = (float*)d_out;

    __half *qAf, *kAf, *vAf;
    __half *WqF, *WkF, *WvF, *WoF;
    __half *Qf, *Kf, *Vf, *Of;
    float *cb; int *idx, *nv;
    cudaGetSymbolAddress((void**)&qAf, g_qAf);
    cudaGetSymbolAddress((void**)&kAf, g_kAf);
    cudaGetSymbolAddress((void**)&vAf, g_vAf);
    cudaGetSymbolAddress((void**)&WqF, g_WqF);
    cudaGetSymbolAddress((void**)&WkF, g_WkF);
    cudaGetSymbolAddress((void**)&WvF, g_WvF);
    cudaGetSymbolAddress((void**)&WoF, g_WoF);
    cudaGetSymbolAddress((void**)&Qf, g_Qf);
    cudaGetSymbolAddress((void**)&Kf, g_Kf);
    cudaGetSymbolAddress((void**)&Vf, g_Vf);
    cudaGetSymbolAddress((void**)&Of, g_Of);
    cudaGetSymbolAddress((void**)&cb, g_cbias);
    cudaGetSymbolAddress((void**)&idx, g_idx);
    cudaGetSymbolAddress((void**)&nv, g_nv);

    cudaFuncSetAttribute(gemm3_mma,
                         cudaFuncAttributeMaxDynamicSharedMemorySize, G1_SMEM);
    cudaFuncSetAttribute(gemm_out_mma,
                         cudaFuncAttributeMaxDynamicSharedMemorySize, G1_SMEM);
    cudaFuncSetAttribute(flash_mma_k,
                         cudaFuncAttributeMaxDynamicSharedMemorySize, AT_SMEM);

    // 0: mask scan/compaction
    scan_mask_k<<<BB, 512>>>(mask, idx, nv, cb);

    // 1: all splits fused
    SplitArgs sa;
    sa.q = q; sa.k = k; sa.v = v;
    sa.wq = Wq; sa.wk = Wk; sa.wv = Wv; sa.wo = Wo;
    sa.qf = qAf; sa.kf = kAf; sa.vf = vAf;
    sa.wqf = WqF; sa.wkf = WkF; sa.wvf = WvF; sa.wof = WoF;
    sa.idx = idx; sa.nv = nv;
    split_all_k<<<1024, 256>>>(sa);

    // 2: fused QKV projections (fp16 x1)
    G3Args p;
    p.Af[0] = qAf; p.Wf[0] = WqF; p.bias[0] = bq; p.Cf[0] = Qf;
    p.Af[1] = kAf; p.Wf[1] = WkF; p.bias[1] = bk; p.Cf[1] = Kf;
    p.Af[2] = vAf; p.Wf[2] = WvF; p.bias[2] = bv; p.Cf[2] = Vf;
    p.nv = nv;
    dim3 gg3(DD / 128, MTOT / 128, 3);
    gemm3_mma<<<gg3, 256, G1_SMEM>>>(p);

    // 3: attention over compacted keys (profiled), all-fp16 MMA
    dim3 ga(SSQ / 128, BB * HHD);
    flash_mma_k<<<ga, 256, AT_SMEM>>>(Qf, Kf, Vf, cb, nv, Of);

    // 4: output projection (fp16 x1)
    dim3 gg(DD / 128, MTOT / 128);
    gemm_out_mma<<<gg, 256, G1_SMEM>>>(Of, WoF, bo, out);
}